// round 1
// baseline (speedup 1.0000x reference)
#include <cuda_runtime.h>
#include <math.h>

// ---------------------------------------------------------------------------
// Problem constants
// ---------------------------------------------------------------------------
#define S_LEN 4096
#define DIM   512
#define HEADS 8
#define DH    64
#define NPM   16
#define SEGLEN 512
#define KL    (S_LEN + NPM)        // 4112 keys after memory prepend
#define QKV_N (3 * HEADS * DH)     // 1536

// ---------------------------------------------------------------------------
// Scratch (device globals: no allocation allowed)
// ---------------------------------------------------------------------------
__device__ float g_inv_rms[S_LEN];
__device__ float g_Q[HEADS * S_LEN * DH];     // [h][s][d]
__device__ float g_K[HEADS * KL * DH];        // [h][t][d], t in [0,4112)
__device__ float g_V[HEADS * KL * DH];
__device__ float g_attn[S_LEN * DIM];         // [s][h*64+d] -> A of output GEMM
__device__ float g_cos[KL * 32];              // [pos][j]
__device__ float g_sin[KL * 32];

// ---------------------------------------------------------------------------
// 1) RMSNorm row scales: inv_rms[s] = rsqrt(mean(seq[s]^2) + eps)
// ---------------------------------------------------------------------------
__global__ void rms_kernel(const float* __restrict__ seq) {
    int s = blockIdx.x;
    int tid = threadIdx.x;                         // 128 threads, 4 floats each
    const float4* row = (const float4*)(seq + (size_t)s * DIM);
    float4 v = row[tid];
    float p = v.x * v.x + v.y * v.y + v.z * v.z + v.w * v.w;
    #pragma unroll
    for (int o = 16; o; o >>= 1) p += __shfl_xor_sync(0xffffffffu, p, o);
    __shared__ float ws[4];
    if ((tid & 31) == 0) ws[tid >> 5] = p;
    __syncthreads();
    if (tid == 0) {
        float tot = ws[0] + ws[1] + ws[2] + ws[3];
        g_inv_rms[s] = rsqrtf(tot * (1.0f / (float)DIM) + 1.1920928955078125e-07f);
    }
}

// ---------------------------------------------------------------------------
// 2) RoPE tables. Match the jax float32 reference: inv_freq rounded to f32,
//    angle = f32(pos) * f32(inv_freq) in f32, then accurate cos/sin of that
//    exact f32 angle (computed in double -> ~0.5 ulp, robust to fast-math).
// ---------------------------------------------------------------------------
__global__ void rope_table_kernel() {
    int idx = blockIdx.x * blockDim.x + threadIdx.x;
    if (idx >= KL * 32) return;
    int pos = idx >> 5, j = idx & 31;
    float rf  = (float)pow(10000.0, -(double)j / 32.0);
    float ang = (float)pos * rf;
    g_cos[idx] = (float)cos((double)ang);
    g_sin[idx] = (float)sin((double)ang);
}

// ---------------------------------------------------------------------------
// 3/6) Tiled fp32 SGEMM. BM=BN=128, BK=8, 256 threads, 8x8 microtile.
// SCALE: A[row][k] *= inv_rms[row] * colScale[k]  (fused RMSNorm for QKV)
// EPI==0: plain C[row*N+col] store.
// EPI==1: scatter into g_Q / g_K / g_V (K/V rows offset by NPM).
// ---------------------------------------------------------------------------
template <int EPI, bool SCALE>
__global__ __launch_bounds__(256) void sgemm128(
    const float* __restrict__ A, const float* __restrict__ B,
    float* __restrict__ C, int M, int N, int K,
    const float* __restrict__ colScale)
{
    const int BM = 128, BN = 128, BK = 8;
    __shared__ float As[BK][BM];
    __shared__ float Bs[BK][BN];

    int tid  = threadIdx.x;
    int row0 = blockIdx.y * BM, col0 = blockIdx.x * BN;
    int tr = tid >> 4, tc = tid & 15;

    int ar  = tid >> 1,  ac4 = (tid & 1) * 4;   // A tile: 128 rows x 8 cols
    int br  = tid >> 5,  bc4 = (tid & 31) * 4;  // B tile: 8 rows x 128 cols

    float rs = 1.0f;
    if (SCALE) rs = g_inv_rms[row0 + ar];

    float acc[8][8];
    #pragma unroll
    for (int i = 0; i < 8; i++)
        #pragma unroll
        for (int j = 0; j < 8; j++) acc[i][j] = 0.0f;

    for (int k0 = 0; k0 < K; k0 += BK) {
        float4 av = *(const float4*)(A + (size_t)(row0 + ar) * K + k0 + ac4);
        if (SCALE) {
            av.x *= rs * colScale[k0 + ac4 + 0];
            av.y *= rs * colScale[k0 + ac4 + 1];
            av.z *= rs * colScale[k0 + ac4 + 2];
            av.w *= rs * colScale[k0 + ac4 + 3];
        }
        As[ac4 + 0][ar] = av.x;
        As[ac4 + 1][ar] = av.y;
        As[ac4 + 2][ar] = av.z;
        As[ac4 + 3][ar] = av.w;

        float4 bv = *(const float4*)(B + (size_t)(k0 + br) * N + col0 + bc4);
        *(float4*)&Bs[br][bc4] = bv;

        __syncthreads();
        #pragma unroll
        for (int kk = 0; kk < BK; kk++) {
            float a[8], b[8];
            *(float4*)(a + 0) = *(const float4*)&As[kk][tr * 4];
            *(float4*)(a + 4) = *(const float4*)&As[kk][64 + tr * 4];
            *(float4*)(b + 0) = *(const float4*)&Bs[kk][tc * 4];
            *(float4*)(b + 4) = *(const float4*)&Bs[kk][64 + tc * 4];
            #pragma unroll
            for (int i = 0; i < 8; i++)
                #pragma unroll
                for (int j = 0; j < 8; j++)
                    acc[i][j] += a[i] * b[j];
        }
        __syncthreads();
    }

    #pragma unroll
    for (int i = 0; i < 8; i++) {
        int row = row0 + ((i < 4) ? (tr * 4 + i) : (64 + tr * 4 + i - 4));
        #pragma unroll
        for (int j = 0; j < 8; j++) {
            int col = col0 + ((j < 4) ? (tc * 4 + j) : (64 + tc * 4 + j - 4));
            float val = acc[i][j];
            if (EPI == 0) {
                C[(size_t)row * N + col] = val;
            } else {
                int region = col >> 9;          // 0:q 1:k 2:v  (tiles never straddle)
                int cr = col & 511;
                int hh = cr >> 6, dd = cr & 63;
                if (region == 0)      g_Q[((size_t)hh * S_LEN + row) * DH + dd] = val;
                else if (region == 1) g_K[((size_t)hh * KL + row + NPM) * DH + dd] = val;
                else                  g_V[((size_t)hh * KL + row + NPM) * DH + dd] = val;
            }
        }
    }
}

// ---------------------------------------------------------------------------
// 4) RoPE apply. One warp per row (lane = pair index j).
//    Rows [0, 8*4112): K rows (t<16 sourced from pm[0], also copies pm[1]->V).
//    Rows [8*4112, +8*4096): Q rows at position s+16.
// ---------------------------------------------------------------------------
__global__ void rope_apply_kernel(const float* __restrict__ pm) {
    int gwarp = (blockIdx.x * blockDim.x + threadIdx.x) >> 5;
    int j = threadIdx.x & 31;
    const int KROWS = HEADS * KL;
    const int TOT   = KROWS + HEADS * S_LEN;
    if (gwarp >= TOT) return;

    if (gwarp < KROWS) {
        int h = gwarp / KL, t = gwarp % KL;
        float* krow = g_K + ((size_t)h * KL + t) * DH;
        float x1, x2;
        if (t < NPM) {
            const float* pmk = pm + (((size_t)0 * HEADS + h) * NPM + t) * DH;
            const float* pmv = pm + (((size_t)1 * HEADS + h) * NPM + t) * DH;
            x1 = pmk[2 * j]; x2 = pmk[2 * j + 1];
            float* vrow = g_V + ((size_t)h * KL + t) * DH;
            vrow[2 * j]     = pmv[2 * j];
            vrow[2 * j + 1] = pmv[2 * j + 1];
        } else {
            x1 = krow[2 * j]; x2 = krow[2 * j + 1];
        }
        float c = g_cos[t * 32 + j], sn = g_sin[t * 32 + j];
        krow[2 * j]     = x1 * c - x2 * sn;
        krow[2 * j + 1] = x2 * c + x1 * sn;
    } else {
        int r = gwarp - KROWS;
        int h = r / S_LEN, s = r % S_LEN;
        int pos = s + NPM;
        float* qrow = g_Q + ((size_t)h * S_LEN + s) * DH;
        float x1 = qrow[2 * j], x2 = qrow[2 * j + 1];
        float c = g_cos[pos * 32 + j], sn = g_sin[pos * 32 + j];
        qrow[2 * j]     = x1 * c - x2 * sn;
        qrow[2 * j + 1] = x2 * c + x1 * sn;
    }
}

// ---------------------------------------------------------------------------
// 5) Attention. Grid (qchunk=4, seg=8, head=8); 128 threads = 1 query each.
//    q (64 regs) and o (64 regs) per thread; 32-key K/V tiles in smem;
//    scores staged in padded smem (dynamic index without spills);
//    online softmax. Memory tile (16 keys, always visible) processed first so
//    the running max is finite before any fully-masked tile.
// ---------------------------------------------------------------------------
__global__ __launch_bounds__(128) void attn_kernel() {
    const int qc = blockIdx.x, seg = blockIdx.y, h = blockIdx.z;
    const int q  = threadIdx.x;
    const int qseg = qc * 128 + q;          // segment-local query index
    const int s    = seg * SEGLEN + qseg;   // global sequence index

    float qreg[64];
    const float* qp = g_Q + ((size_t)h * S_LEN + s) * DH;
    #pragma unroll
    for (int d = 0; d < 64; d += 4) {
        float4 t4 = *(const float4*)(qp + d);
        qreg[d] = t4.x; qreg[d + 1] = t4.y; qreg[d + 2] = t4.z; qreg[d + 3] = t4.w;
    }
    float o[64];
    #pragma unroll
    for (int d = 0; d < 64; d++) o[d] = 0.0f;
    float m = -INFINITY, l = 0.0f;

    __shared__ float ks[32][64];
    __shared__ float vs[32][64];
    __shared__ float scs[128][33];

    const int ntiles = (qc + 1) * 4;        // 32-key tiles covering [0, (qc+1)*128)
    for (int t = -1; t < ntiles; t++) {
        const int cnt   = (t < 0) ? NPM : 32;
        const int krow0 = (t < 0) ? 0 : (NPM + seg * SEGLEN + t * 32);
        const float4* kb = (const float4*)(g_K + ((size_t)h * KL + krow0) * DH);
        const float4* vb = (const float4*)(g_V + ((size_t)h * KL + krow0) * DH);

        __syncthreads();
        const int n4 = cnt * (DH / 4);
        for (int i = q; i < n4; i += 128) {
            ((float4*)ks)[i] = kb[i];
            ((float4*)vs)[i] = vb[i];
        }
        __syncthreads();

        float tmax = -INFINITY;
        for (int kk = 0; kk < cnt; kk++) {
            float acc = 0.0f;
            #pragma unroll
            for (int d = 0; d < 64; d += 4) {
                float4 kv = *(const float4*)&ks[kk][d];
                acc += qreg[d] * kv.x + qreg[d + 1] * kv.y
                     + qreg[d + 2] * kv.z + qreg[d + 3] * kv.w;
            }
            acc *= 0.125f;                                   // 1/sqrt(64)
            if (t >= 0 && (t * 32 + kk) > qseg) acc = -INFINITY;  // causal in-segment
            scs[q][kk] = acc;
            tmax = fmaxf(tmax, acc);
        }

        float mnew = fmaxf(m, tmax);
        float corr = __expf(m - mnew);       // 0 on first tile (m=-inf), else rescale
        l *= corr;
        #pragma unroll
        for (int d = 0; d < 64; d++) o[d] *= corr;

        for (int kk = 0; kk < cnt; kk++) {
            float p = __expf(scs[q][kk] - mnew);
            l += p;
            #pragma unroll
            for (int d = 0; d < 64; d += 4) {
                float4 vv = *(const float4*)&vs[kk][d];
                o[d]     += p * vv.x; o[d + 1] += p * vv.y;
                o[d + 2] += p * vv.z; o[d + 3] += p * vv.w;
            }
        }
        m = mnew;
    }

    float invl = 1.0f / l;
    float* op = g_attn + (size_t)s * DIM + h * DH;
    #pragma unroll
    for (int d = 0; d < 64; d += 4) {
        float4 t4 = make_float4(o[d] * invl, o[d + 1] * invl,
                                o[d + 2] * invl, o[d + 3] * invl);
        *(float4*)(op + d) = t4;
    }
}

// ---------------------------------------------------------------------------
// Launch
// ---------------------------------------------------------------------------
extern "C" void kernel_launch(void* const* d_in, const int* in_sizes, int n_in,
                              void* d_out, int out_size) {
    const float* seq    = (const float*)d_in[0];
    const float* norm_w = (const float*)d_in[1];
    const float* w_qkv  = (const float*)d_in[2];
    const float* w_out  = (const float*)d_in[3];
    const float* pm     = (const float*)d_in[4];

    float* attn_ptr = nullptr;
    cudaGetSymbolAddress((void**)&attn_ptr, g_attn);   // host query, capture-safe

    rms_kernel<<<S_LEN, 128>>>(seq);
    rope_table_kernel<<<(KL * 32 + 127) / 128, 128>>>();

    sgemm128<1, true><<<dim3(QKV_N / 128, S_LEN / 128), 256>>>(
        seq, w_qkv, nullptr, S_LEN, QKV_N, DIM, norm_w);

    {
        const int TOTW = HEADS * KL + HEADS * S_LEN;   // 65664 warps
        int threads = TOTW * 32;
        rope_apply_kernel<<<(threads + 127) / 128, 128>>>(pm);
    }

    attn_kernel<<<dim3(4, 8, 8), 128>>>();

    sgemm128<0, false><<<dim3(DIM / 128, S_LEN / 128), 256>>>(
        attn_ptr, w_out, (float*)d_out, S_LEN, DIM, DIM, nullptr);
}

// round 4
// speedup vs baseline: 1.1874x; 1.1874x over previous
#include <cuda_runtime.h>
#include <cuda_bf16.h>
#include <cstdint>
#include <math.h>

// ---------------------------------------------------------------------------
// Problem constants
// ---------------------------------------------------------------------------
#define S_LEN 4096
#define DIM   512
#define HEADS 8
#define DH    64
#define NPM   16
#define SEGLEN 512
#define KL    (S_LEN + NPM)        // 4112 keys after memory prepend
#define QKV_N (3 * HEADS * DH)     // 1536

// ---------------------------------------------------------------------------
// Scratch (device globals: no allocation allowed)
// ---------------------------------------------------------------------------
__device__ float g_inv_rms[S_LEN];
__device__ float g_Q[HEADS * S_LEN * DH];     // [h][s][d]
__device__ float g_K[HEADS * KL * DH];        // [h][t][d]
__device__ float g_V[HEADS * KL * DH];
__device__ float g_attn[S_LEN * DIM];         // [s][h*64+d]
__device__ float g_cos[KL * 32];
__device__ float g_sin[KL * 32];

// ---------------------------------------------------------------------------
// 1) RMSNorm row scales
// ---------------------------------------------------------------------------
__global__ void rms_kernel(const float* __restrict__ seq) {
    int s = blockIdx.x;
    int tid = threadIdx.x;                         // 128 threads, 4 floats each
    const float4* row = (const float4*)(seq + (size_t)s * DIM);
    float4 v = row[tid];
    float p = v.x * v.x + v.y * v.y + v.z * v.z + v.w * v.w;
    #pragma unroll
    for (int o = 16; o; o >>= 1) p += __shfl_xor_sync(0xffffffffu, p, o);
    __shared__ float ws[4];
    if ((tid & 31) == 0) ws[tid >> 5] = p;
    __syncthreads();
    if (tid == 0) {
        float tot = ws[0] + ws[1] + ws[2] + ws[3];
        g_inv_rms[s] = rsqrtf(tot * (1.0f / (float)DIM) + 1.1920928955078125e-07f);
    }
}

// ---------------------------------------------------------------------------
// 2) RoPE tables (double-precision trig to track the f32 reference)
// ---------------------------------------------------------------------------
__global__ void rope_table_kernel() {
    int idx = blockIdx.x * blockDim.x + threadIdx.x;
    if (idx >= KL * 32) return;
    int pos = idx >> 5, j = idx & 31;
    float rf  = (float)pow(10000.0, -(double)j / 32.0);
    float ang = (float)pos * rf;
    g_cos[idx] = (float)cos((double)ang);
    g_sin[idx] = (float)sin((double)ang);
}

// ---------------------------------------------------------------------------
// Tensor-core GEMM: bf16 3-term split (a_hi*b_hi + a_hi*b_lo + a_lo*b_hi),
// fp32 accumulate via mma.sync.m16n8k16. BM=BN=128, BK=32, 256 threads,
// warp grid 2(m) x 4(n), 64x32 per warp. No templates, no lambdas.
// colScale != nullptr: A[row][k] *= g_inv_rms[row] * colScale[k]
// epi == 0: plain store to C. epi == 1: scatter to g_Q/g_K/g_V.
// ---------------------------------------------------------------------------
__device__ __forceinline__ uint32_t bf2_hi(float a0, float a1) {
    unsigned short u0 = __bfloat16_as_ushort(__float2bfloat16(a0));
    unsigned short u1 = __bfloat16_as_ushort(__float2bfloat16(a1));
    return (uint32_t)u0 | ((uint32_t)u1 << 16);
}
__device__ __forceinline__ uint32_t bf2_lo(float a0, float a1) {
    float r0 = a0 - __bfloat162float(__float2bfloat16(a0));
    float r1 = a1 - __bfloat162float(__float2bfloat16(a1));
    unsigned short u0 = __bfloat16_as_ushort(__float2bfloat16(r0));
    unsigned short u1 = __bfloat16_as_ushort(__float2bfloat16(r1));
    return (uint32_t)u0 | ((uint32_t)u1 << 16);
}

__device__ __forceinline__ void ldsm_x4(uint32_t& r0, uint32_t& r1,
                                        uint32_t& r2, uint32_t& r3, uint32_t addr) {
    asm volatile("ldmatrix.sync.aligned.m8n8.x4.shared.b16 {%0,%1,%2,%3}, [%4];"
                 : "=r"(r0), "=r"(r1), "=r"(r2), "=r"(r3) : "r"(addr));
}

__device__ __forceinline__ void mma16816(float* c, const uint32_t* a,
                                         uint32_t b0, uint32_t b1) {
    asm volatile(
        "mma.sync.aligned.m16n8k16.row.col.f32.bf16.bf16.f32 "
        "{%0,%1,%2,%3}, {%4,%5,%6,%7}, {%8,%9}, {%0,%1,%2,%3};"
        : "+f"(c[0]), "+f"(c[1]), "+f"(c[2]), "+f"(c[3])
        : "r"(a[0]), "r"(a[1]), "r"(a[2]), "r"(a[3]), "r"(b0), "r"(b1));
}

#define LDK 20   // uint32 per smem row (= 40 bf16 = 80 bytes, conflict-free)

// Load next-stage fp32 fragments into areg/breg registers.
#define LOAD_STAGE(K0) do {                                                   \
    int _k0 = (K0);                                                           \
    float4 _v0 = *(const float4*)(Arow + _k0 + 0);                            \
    float4 _v1 = *(const float4*)(Arow + _k0 + 4);                            \
    float4 _v2 = *(const float4*)(Arow + _k0 + 8);                            \
    float4 _v3 = *(const float4*)(Arow + _k0 + 12);                           \
    areg[0]=_v0.x; areg[1]=_v0.y; areg[2]=_v0.z; areg[3]=_v0.w;               \
    areg[4]=_v1.x; areg[5]=_v1.y; areg[6]=_v1.z; areg[7]=_v1.w;               \
    areg[8]=_v2.x; areg[9]=_v2.y; areg[10]=_v2.z; areg[11]=_v2.w;             \
    areg[12]=_v3.x; areg[13]=_v3.y; areg[14]=_v3.z; areg[15]=_v3.w;           \
    if (colScale) {                                                           \
        _Pragma("unroll")                                                     \
        for (int _j = 0; _j < 16; _j++)                                       \
            areg[_j] *= rs * colScale[_k0 + kg16 + _j];                       \
    }                                                                         \
    _Pragma("unroll")                                                         \
    for (int _j = 0; _j < 16; _j++)                                           \
        breg[_j] = Bcol[(size_t)(_k0 + _j) * N];                              \
} while (0)

// Convert areg/breg to hi/lo bf16x2 and store to the 4 smem tiles.
#define STORE_STAGE() do {                                                    \
    uint32_t _wh[8], _wl[8], _xh[8], _xl[8];                                  \
    _Pragma("unroll")                                                         \
    for (int _i = 0; _i < 8; _i++) {                                          \
        _wh[_i] = bf2_hi(areg[2*_i], areg[2*_i+1]);                           \
        _wl[_i] = bf2_lo(areg[2*_i], areg[2*_i+1]);                           \
        _xh[_i] = bf2_hi(breg[2*_i], breg[2*_i+1]);                           \
        _xl[_i] = bf2_lo(breg[2*_i], breg[2*_i+1]);                           \
    }                                                                         \
    int _o = srow * LDK + kg8;                                                \
    *(uint4*)&sAh[_o]     = make_uint4(_wh[0], _wh[1], _wh[2], _wh[3]);       \
    *(uint4*)&sAh[_o + 4] = make_uint4(_wh[4], _wh[5], _wh[6], _wh[7]);       \
    *(uint4*)&sAl[_o]     = make_uint4(_wl[0], _wl[1], _wl[2], _wl[3]);       \
    *(uint4*)&sAl[_o + 4] = make_uint4(_wl[4], _wl[5], _wl[6], _wl[7]);       \
    *(uint4*)&sBh[_o]     = make_uint4(_xh[0], _xh[1], _xh[2], _xh[3]);       \
    *(uint4*)&sBh[_o + 4] = make_uint4(_xh[4], _xh[5], _xh[6], _xh[7]);       \
    *(uint4*)&sBl[_o]     = make_uint4(_xl[0], _xl[1], _xl[2], _xl[3]);       \
    *(uint4*)&sBl[_o + 4] = make_uint4(_xl[4], _xl[5], _xl[6], _xl[7]);       \
} while (0)

__global__ __launch_bounds__(256) void mm_kernel(
    const float* __restrict__ A, const float* __restrict__ B,
    float* __restrict__ C, int N, int K,
    const float* __restrict__ colScale, int epi)
{
    __shared__ uint32_t sAh[128 * LDK];
    __shared__ uint32_t sAl[128 * LDK];
    __shared__ uint32_t sBh[128 * LDK];
    __shared__ uint32_t sBl[128 * LDK];

    const int tid  = threadIdx.x;
    const int lane = tid & 31, warp = tid >> 5;
    const int wm = warp & 1, wn = warp >> 1;          // 2 x 4 warp grid
    const int row0 = blockIdx.y * 128, col0 = blockIdx.x * 128;

    // staging mapping: 256 threads = 128 rows x 2 k-halves (16 k each)
    const int srow = tid & 127;
    const int kg16 = (tid >> 7) * 16;                 // 0 or 16
    const int kg8  = (tid >> 7) * 8;

    const uint32_t bAh = (uint32_t)__cvta_generic_to_shared(sAh);
    const uint32_t bAl = (uint32_t)__cvta_generic_to_shared(sAl);
    const uint32_t bBh = (uint32_t)__cvta_generic_to_shared(sBh);
    const uint32_t bBl = (uint32_t)__cvta_generic_to_shared(sBl);

    float rs = 1.0f;
    if (colScale) rs = g_inv_rms[row0 + srow];

    const float* Arow = A + (size_t)(row0 + srow) * K + kg16;
    const float* Bcol = B + (size_t)kg16 * N + col0 + srow;

    float areg[16], breg[16];
    const int NST = K / 32;

    float acc[4][4][4];
    #pragma unroll
    for (int i = 0; i < 4; i++)
        #pragma unroll
        for (int j = 0; j < 4; j++)
            #pragma unroll
            for (int r = 0; r < 4; r++) acc[i][j][r] = 0.0f;

    LOAD_STAGE(0);
    STORE_STAGE();
    __syncthreads();

    const int mbase = wm * 64, nbase = wn * 32;
    const int lr = lane & 15, lh = (lane >> 4) * 16;   // lh: byte offset of k-half

    for (int s = 0; s < NST; s++) {
        if (s + 1 < NST) LOAD_STAGE((s + 1) * 32);

        #pragma unroll
        for (int kk = 0; kk < 2; kk++) {               // two k16 steps per stage
            const uint32_t kb = (uint32_t)(kk * 32 + lh);  // byte offset in row
            uint32_t ah[4][4], al[4][4], bh[2][4], bl[2][4];
            #pragma unroll
            for (int mf = 0; mf < 4; mf++) {
                uint32_t ro = (uint32_t)(mbase + mf * 16 + lr) * 80 + kb;
                ldsm_x4(ah[mf][0], ah[mf][1], ah[mf][2], ah[mf][3], bAh + ro);
                ldsm_x4(al[mf][0], al[mf][1], al[mf][2], al[mf][3], bAl + ro);
            }
            #pragma unroll
            for (int np = 0; np < 2; np++) {
                uint32_t ro = (uint32_t)(nbase + np * 16 + lr) * 80 + kb;
                ldsm_x4(bh[np][0], bh[np][1], bh[np][2], bh[np][3], bBh + ro);
                ldsm_x4(bl[np][0], bl[np][1], bl[np][2], bl[np][3], bBl + ro);
            }
            #pragma unroll
            for (int mf = 0; mf < 4; mf++) {
                #pragma unroll
                for (int nf = 0; nf < 4; nf++) {
                    const int np = nf >> 1, half = nf & 1;
                    uint32_t b0h = bh[np][half], b1h = bh[np][2 + half];
                    uint32_t b0l = bl[np][half], b1l = bl[np][2 + half];
                    mma16816(acc[mf][nf], ah[mf], b0h, b1h);
                    mma16816(acc[mf][nf], ah[mf], b0l, b1l);
                    mma16816(acc[mf][nf], al[mf], b0h, b1h);
                }
            }
        }
        __syncthreads();
        if (s + 1 < NST) { STORE_STAGE(); }
        __syncthreads();
    }

    // Epilogue: acc[mf][nf] covers rows (wm*64+mf*16 + lane/4 [+8]),
    // cols (wn*32+nf*8 + (lane%4)*2 [+1]).
    #pragma unroll
    for (int mf = 0; mf < 4; mf++) {
        #pragma unroll
        for (int nf = 0; nf < 4; nf++) {
            int r = row0 + mbase + mf * 16 + (lane >> 2);
            int c = col0 + nbase + nf * 8 + (lane & 3) * 2;
            #pragma unroll
            for (int rr = 0; rr < 4; rr++) {
                int row = r + ((rr >= 2) ? 8 : 0);
                int col = c + (rr & 1);
                float val = acc[mf][nf][rr];
                if (epi == 0) {
                    C[(size_t)row * N + col] = val;
                } else {
                    int region = col >> 9;            // 0:q 1:k 2:v
                    int cr = col & 511;
                    int hh = cr >> 6, dd = cr & 63;
                    if (region == 0)      g_Q[((size_t)hh * S_LEN + row) * DH + dd] = val;
                    else if (region == 1) g_K[((size_t)hh * KL + row + NPM) * DH + dd] = val;
                    else                  g_V[((size_t)hh * KL + row + NPM) * DH + dd] = val;
                }
            }
        }
    }
}

// ---------------------------------------------------------------------------
// 4) RoPE apply (one warp per row; memory slots from pm)
// ---------------------------------------------------------------------------
__global__ void rope_apply_kernel(const float* __restrict__ pm) {
    int gwarp = (blockIdx.x * blockDim.x + threadIdx.x) >> 5;
    int j = threadIdx.x & 31;
    const int KROWS = HEADS * KL;
    const int TOT   = KROWS + HEADS * S_LEN;
    if (gwarp >= TOT) return;

    if (gwarp < KROWS) {
        int h = gwarp / KL, t = gwarp % KL;
        float* krow = g_K + ((size_t)h * KL + t) * DH;
        float x1, x2;
        if (t < NPM) {
            const float* pmk = pm + (((size_t)0 * HEADS + h) * NPM + t) * DH;
            const float* pmv = pm + (((size_t)1 * HEADS + h) * NPM + t) * DH;
            x1 = pmk[2 * j]; x2 = pmk[2 * j + 1];
            float* vrow = g_V + ((size_t)h * KL + t) * DH;
            vrow[2 * j]     = pmv[2 * j];
            vrow[2 * j + 1] = pmv[2 * j + 1];
        } else {
            x1 = krow[2 * j]; x2 = krow[2 * j + 1];
        }
        float c = g_cos[t * 32 + j], sn = g_sin[t * 32 + j];
        krow[2 * j]     = x1 * c - x2 * sn;
        krow[2 * j + 1] = x2 * c + x1 * sn;
    } else {
        int r = gwarp - KROWS;
        int h = r / S_LEN, s = r % S_LEN;
        int pos = s + NPM;
        float* qrow = g_Q + ((size_t)h * S_LEN + s) * DH;
        float x1 = qrow[2 * j], x2 = qrow[2 * j + 1];
        float c = g_cos[pos * 32 + j], sn = g_sin[pos * 32 + j];
        qrow[2 * j]     = x1 * c - x2 * sn;
        qrow[2 * j + 1] = x2 * c + x1 * sn;
    }
}

// ---------------------------------------------------------------------------
// 5) Attention (unchanged from round 1)
// ---------------------------------------------------------------------------
__global__ __launch_bounds__(128) void attn_kernel() {
    const int qc = blockIdx.x, seg = blockIdx.y, h = blockIdx.z;
    const int q  = threadIdx.x;
    const int qseg = qc * 128 + q;
    const int s    = seg * SEGLEN + qseg;

    float qreg[64];
    const float* qp = g_Q + ((size_t)h * S_LEN + s) * DH;
    #pragma unroll
    for (int d = 0; d < 64; d += 4) {
        float4 t4 = *(const float4*)(qp + d);
        qreg[d] = t4.x; qreg[d + 1] = t4.y; qreg[d + 2] = t4.z; qreg[d + 3] = t4.w;
    }
    float o[64];
    #pragma unroll
    for (int d = 0; d < 64; d++) o[d] = 0.0f;
    float m = -INFINITY, l = 0.0f;

    __shared__ float ks[32][64];
    __shared__ float vs[32][64];
    __shared__ float scs[128][33];

    const int ntiles = (qc + 1) * 4;
    for (int t = -1; t < ntiles; t++) {
        const int cnt   = (t < 0) ? NPM : 32;
        const int krow0 = (t < 0) ? 0 : (NPM + seg * SEGLEN + t * 32);
        const float4* kb = (const float4*)(g_K + ((size_t)h * KL + krow0) * DH);
        const float4* vb = (const float4*)(g_V + ((size_t)h * KL + krow0) * DH);

        __syncthreads();
        const int n4 = cnt * (DH / 4);
        for (int i = q; i < n4; i += 128) {
            ((float4*)ks)[i] = kb[i];
            ((float4*)vs)[i] = vb[i];
        }
        __syncthreads();

        float tmax = -INFINITY;
        for (int kk = 0; kk < cnt; kk++) {
            float acc = 0.0f;
            #pragma unroll
            for (int d = 0; d < 64; d += 4) {
                float4 kv = *(const float4*)&ks[kk][d];
                acc += qreg[d] * kv.x + qreg[d + 1] * kv.y
                     + qreg[d + 2] * kv.z + qreg[d + 3] * kv.w;
            }
            acc *= 0.125f;
            if (t >= 0 && (t * 32 + kk) > qseg) acc = -INFINITY;
            scs[q][kk] = acc;
            tmax = fmaxf(tmax, acc);
        }

        float mnew = fmaxf(m, tmax);
        float corr = __expf(m - mnew);
        l *= corr;
        #pragma unroll
        for (int d = 0; d < 64; d++) o[d] *= corr;

        for (int kk = 0; kk < cnt; kk++) {
            float p = __expf(scs[q][kk] - mnew);
            l += p;
            #pragma unroll
            for (int d = 0; d < 64; d += 4) {
                float4 vv = *(const float4*)&vs[kk][d];
                o[d]     += p * vv.x; o[d + 1] += p * vv.y;
                o[d + 2] += p * vv.z; o[d + 3] += p * vv.w;
            }
        }
        m = mnew;
    }

    float invl = 1.0f / l;
    float* op = g_attn + (size_t)s * DIM + h * DH;
    #pragma unroll
    for (int d = 0; d < 64; d += 4) {
        float4 t4 = make_float4(o[d] * invl, o[d + 1] * invl,
                                o[d + 2] * invl, o[d + 3] * invl);
        *(float4*)(op + d) = t4;
    }
}

// ---------------------------------------------------------------------------
// Launch
// ---------------------------------------------------------------------------
extern "C" void kernel_launch(void* const* d_in, const int* in_sizes, int n_in,
                              void* d_out, int out_size) {
    const float* seq    = (const float*)d_in[0];
    const float* norm_w = (const float*)d_in[1];
    const float* w_qkv  = (const float*)d_in[2];
    const float* w_out  = (const float*)d_in[3];
    const float* pm     = (const float*)d_in[4];

    float* attn_ptr = nullptr;
    cudaGetSymbolAddress((void**)&attn_ptr, g_attn);

    rms_kernel<<<S_LEN, 128>>>(seq);
    rope_table_kernel<<<(KL * 32 + 127) / 128, 128>>>();

    mm_kernel<<<dim3(QKV_N / 128, S_LEN / 128), 256>>>(
        seq, w_qkv, nullptr, QKV_N, DIM, norm_w, 1);

    {
        const int TOTW = HEADS * KL + HEADS * S_LEN;
        int threads = TOTW * 32;
        rope_apply_kernel<<<(threads + 127) / 128, 128>>>(pm);
    }

    attn_kernel<<<dim3(4, 8, 8), 128>>>();

    mm_kernel<<<dim3(DIM / 128, S_LEN / 128), 256>>>(
        attn_ptr, w_out, (float*)d_out, DIM, DIM, nullptr, 0);
}

// round 5
// speedup vs baseline: 1.7093x; 1.4396x over previous
#include <cuda_runtime.h>
#include <cuda_bf16.h>
#include <cstdint>
#include <math.h>

// ---------------------------------------------------------------------------
// Problem constants
// ---------------------------------------------------------------------------
#define S_LEN 4096
#define DIM   512
#define HEADS 8
#define DH    64
#define NPM   16
#define SEGLEN 512
#define KL    (S_LEN + NPM)        // 4112 keys after memory prepend
#define QKV_N (3 * HEADS * DH)     // 1536

// ---------------------------------------------------------------------------
// Scratch (device globals: no allocation allowed)
// ---------------------------------------------------------------------------
__device__ float g_inv_rms[S_LEN];
__device__ float g_Q[HEADS * S_LEN * DH];     // fp32 [h][s][d] (pre-rope)
__device__ float g_K[HEADS * KL * DH];        // fp32 [h][t][d] (pre-rope, t>=16)
__device__ float g_V[HEADS * KL * DH];        // fp32 [h][t][d]
__device__ float g_attn[S_LEN * DIM];         // [s][h*64+d]
__device__ float g_cos[KL * 32];
__device__ float g_sin[KL * 32];
// bf16 hi/lo operand copies for tensor-core attention
__device__ __align__(16) __nv_bfloat16 g_Qh[HEADS * S_LEN * DH];
__device__ __align__(16) __nv_bfloat16 g_Ql[HEADS * S_LEN * DH];
__device__ __align__(16) __nv_bfloat16 g_Kh[HEADS * KL * DH];
__device__ __align__(16) __nv_bfloat16 g_Kl[HEADS * KL * DH];
__device__ __align__(16) __nv_bfloat16 g_Vth[HEADS * DH * KL];  // [h][d][t]
__device__ __align__(16) __nv_bfloat16 g_Vtl[HEADS * DH * KL];

// ---------------------------------------------------------------------------
// helpers
// ---------------------------------------------------------------------------
__device__ __forceinline__ uint32_t bf2_hi(float a0, float a1) {
    unsigned short u0 = __bfloat16_as_ushort(__float2bfloat16(a0));
    unsigned short u1 = __bfloat16_as_ushort(__float2bfloat16(a1));
    return (uint32_t)u0 | ((uint32_t)u1 << 16);
}
__device__ __forceinline__ uint32_t bf2_lo(float a0, float a1) {
    float r0 = a0 - __bfloat162float(__float2bfloat16(a0));
    float r1 = a1 - __bfloat162float(__float2bfloat16(a1));
    unsigned short u0 = __bfloat16_as_ushort(__float2bfloat16(r0));
    unsigned short u1 = __bfloat16_as_ushort(__float2bfloat16(r1));
    return (uint32_t)u0 | ((uint32_t)u1 << 16);
}

__device__ __forceinline__ void ldsm_x4(uint32_t& r0, uint32_t& r1,
                                        uint32_t& r2, uint32_t& r3, uint32_t addr) {
    asm volatile("ldmatrix.sync.aligned.m8n8.x4.shared.b16 {%0,%1,%2,%3}, [%4];"
                 : "=r"(r0), "=r"(r1), "=r"(r2), "=r"(r3) : "r"(addr));
}

__device__ __forceinline__ void mma16816(float* c, const uint32_t* a,
                                         uint32_t b0, uint32_t b1) {
    asm volatile(
        "mma.sync.aligned.m16n8k16.row.col.f32.bf16.bf16.f32 "
        "{%0,%1,%2,%3}, {%4,%5,%6,%7}, {%8,%9}, {%0,%1,%2,%3};"
        : "+f"(c[0]), "+f"(c[1]), "+f"(c[2]), "+f"(c[3])
        : "r"(a[0]), "r"(a[1]), "r"(a[2]), "r"(a[3]), "r"(b0), "r"(b1));
}

// ---------------------------------------------------------------------------
// 1) RMSNorm row scales
// ---------------------------------------------------------------------------
__global__ void rms_kernel(const float* __restrict__ seq) {
    int s = blockIdx.x;
    int tid = threadIdx.x;
    const float4* row = (const float4*)(seq + (size_t)s * DIM);
    float4 v = row[tid];
    float p = v.x * v.x + v.y * v.y + v.z * v.z + v.w * v.w;
    #pragma unroll
    for (int o = 16; o; o >>= 1) p += __shfl_xor_sync(0xffffffffu, p, o);
    __shared__ float ws[4];
    if ((tid & 31) == 0) ws[tid >> 5] = p;
    __syncthreads();
    if (tid == 0) {
        float tot = ws[0] + ws[1] + ws[2] + ws[3];
        g_inv_rms[s] = rsqrtf(tot * (1.0f / (float)DIM) + 1.1920928955078125e-07f);
    }
}

// ---------------------------------------------------------------------------
// 2) RoPE tables (double-precision trig to track the f32 reference)
// ---------------------------------------------------------------------------
__global__ void rope_table_kernel() {
    int idx = blockIdx.x * blockDim.x + threadIdx.x;
    if (idx >= KL * 32) return;
    int pos = idx >> 5, j = idx & 31;
    float rf  = (float)pow(10000.0, -(double)j / 32.0);
    float ang = (float)pos * rf;
    g_cos[idx] = (float)cos((double)ang);
    g_sin[idx] = (float)sin((double)ang);
}

// ---------------------------------------------------------------------------
// Tensor-core GEMM: bf16 3-term split (verified round 4). Unchanged.
// ---------------------------------------------------------------------------
#define LDK 20

#define LOAD_STAGE(K0) do {                                                   \
    int _k0 = (K0);                                                           \
    float4 _v0 = *(const float4*)(Arow + _k0 + 0);                            \
    float4 _v1 = *(const float4*)(Arow + _k0 + 4);                            \
    float4 _v2 = *(const float4*)(Arow + _k0 + 8);                            \
    float4 _v3 = *(const float4*)(Arow + _k0 + 12);                           \
    areg[0]=_v0.x; areg[1]=_v0.y; areg[2]=_v0.z; areg[3]=_v0.w;               \
    areg[4]=_v1.x; areg[5]=_v1.y; areg[6]=_v1.z; areg[7]=_v1.w;               \
    areg[8]=_v2.x; areg[9]=_v2.y; areg[10]=_v2.z; areg[11]=_v2.w;             \
    areg[12]=_v3.x; areg[13]=_v3.y; areg[14]=_v3.z; areg[15]=_v3.w;           \
    if (colScale) {                                                           \
        _Pragma("unroll")                                                     \
        for (int _j = 0; _j < 16; _j++)                                       \
            areg[_j] *= rs * colScale[_k0 + kg16 + _j];                       \
    }                                                                         \
    _Pragma("unroll")                                                         \
    for (int _j = 0; _j < 16; _j++)                                           \
        breg[_j] = Bcol[(size_t)(_k0 + _j) * N];                              \
} while (0)

#define STORE_STAGE() do {                                                    \
    uint32_t _wh[8], _wl[8], _xh[8], _xl[8];                                  \
    _Pragma("unroll")                                                         \
    for (int _i = 0; _i < 8; _i++) {                                          \
        _wh[_i] = bf2_hi(areg[2*_i], areg[2*_i+1]);                           \
        _wl[_i] = bf2_lo(areg[2*_i], areg[2*_i+1]);                           \
        _xh[_i] = bf2_hi(breg[2*_i], breg[2*_i+1]);                           \
        _xl[_i] = bf2_lo(breg[2*_i], breg[2*_i+1]);                           \
    }                                                                         \
    int _o = srow * LDK + kg8;                                                \
    *(uint4*)&sAh[_o]     = make_uint4(_wh[0], _wh[1], _wh[2], _wh[3]);       \
    *(uint4*)&sAh[_o + 4] = make_uint4(_wh[4], _wh[5], _wh[6], _wh[7]);       \
    *(uint4*)&sAl[_o]     = make_uint4(_wl[0], _wl[1], _wl[2], _wl[3]);       \
    *(uint4*)&sAl[_o + 4] = make_uint4(_wl[4], _wl[5], _wl[6], _wl[7]);       \
    *(uint4*)&sBh[_o]     = make_uint4(_xh[0], _xh[1], _xh[2], _xh[3]);       \
    *(uint4*)&sBh[_o + 4] = make_uint4(_xh[4], _xh[5], _xh[6], _xh[7]);       \
    *(uint4*)&sBl[_o]     = make_uint4(_xl[0], _xl[1], _xl[2], _xl[3]);       \
    *(uint4*)&sBl[_o + 4] = make_uint4(_xl[4], _xl[5], _xl[6], _xl[7]);       \
} while (0)

__global__ __launch_bounds__(256) void mm_kernel(
    const float* __restrict__ A, const float* __restrict__ B,
    float* __restrict__ C, int N, int K,
    const float* __restrict__ colScale, int epi)
{
    __shared__ uint32_t sAh[128 * LDK];
    __shared__ uint32_t sAl[128 * LDK];
    __shared__ uint32_t sBh[128 * LDK];
    __shared__ uint32_t sBl[128 * LDK];

    const int tid  = threadIdx.x;
    const int lane = tid & 31, warp = tid >> 5;
    const int wm = warp & 1, wn = warp >> 1;
    const int row0 = blockIdx.y * 128, col0 = blockIdx.x * 128;

    const int srow = tid & 127;
    const int kg16 = (tid >> 7) * 16;
    const int kg8  = (tid >> 7) * 8;

    const uint32_t bAh = (uint32_t)__cvta_generic_to_shared(sAh);
    const uint32_t bAl = (uint32_t)__cvta_generic_to_shared(sAl);
    const uint32_t bBh = (uint32_t)__cvta_generic_to_shared(sBh);
    const uint32_t bBl = (uint32_t)__cvta_generic_to_shared(sBl);

    float rs = 1.0f;
    if (colScale) rs = g_inv_rms[row0 + srow];

    const float* Arow = A + (size_t)(row0 + srow) * K + kg16;
    const float* Bcol = B + (size_t)kg16 * N + col0 + srow;

    float areg[16], breg[16];
    const int NST = K / 32;

    float acc[4][4][4];
    #pragma unroll
    for (int i = 0; i < 4; i++)
        #pragma unroll
        for (int j = 0; j < 4; j++)
            #pragma unroll
            for (int r = 0; r < 4; r++) acc[i][j][r] = 0.0f;

    LOAD_STAGE(0);
    STORE_STAGE();
    __syncthreads();

    const int mbase = wm * 64, nbase = wn * 32;
    const int lr = lane & 15, lh = (lane >> 4) * 16;

    for (int s = 0; s < NST; s++) {
        if (s + 1 < NST) LOAD_STAGE((s + 1) * 32);

        #pragma unroll
        for (int kk = 0; kk < 2; kk++) {
            const uint32_t kb = (uint32_t)(kk * 32 + lh);
            uint32_t ah[4][4], al[4][4], bh[2][4], bl[2][4];
            #pragma unroll
            for (int mf = 0; mf < 4; mf++) {
                uint32_t ro = (uint32_t)(mbase + mf * 16 + lr) * 80 + kb;
                ldsm_x4(ah[mf][0], ah[mf][1], ah[mf][2], ah[mf][3], bAh + ro);
                ldsm_x4(al[mf][0], al[mf][1], al[mf][2], al[mf][3], bAl + ro);
            }
            #pragma unroll
            for (int np = 0; np < 2; np++) {
                uint32_t ro = (uint32_t)(nbase + np * 16 + lr) * 80 + kb;
                ldsm_x4(bh[np][0], bh[np][1], bh[np][2], bh[np][3], bBh + ro);
                ldsm_x4(bl[np][0], bl[np][1], bl[np][2], bl[np][3], bBl + ro);
            }
            #pragma unroll
            for (int mf = 0; mf < 4; mf++) {
                #pragma unroll
                for (int nf = 0; nf < 4; nf++) {
                    const int np = nf >> 1, half = nf & 1;
                    uint32_t b0h = bh[np][half], b1h = bh[np][2 + half];
                    uint32_t b0l = bl[np][half], b1l = bl[np][2 + half];
                    mma16816(acc[mf][nf], ah[mf], b0h, b1h);
                    mma16816(acc[mf][nf], ah[mf], b0l, b1l);
                    mma16816(acc[mf][nf], al[mf], b0h, b1h);
                }
            }
        }
        __syncthreads();
        if (s + 1 < NST) { STORE_STAGE(); }
        __syncthreads();
    }

    #pragma unroll
    for (int mf = 0; mf < 4; mf++) {
        #pragma unroll
        for (int nf = 0; nf < 4; nf++) {
            int r = row0 + mbase + mf * 16 + (lane >> 2);
            int c = col0 + nbase + nf * 8 + (lane & 3) * 2;
            #pragma unroll
            for (int rr = 0; rr < 4; rr++) {
                int row = r + ((rr >= 2) ? 8 : 0);
                int col = c + (rr & 1);
                float val = acc[mf][nf][rr];
                if (epi == 0) {
                    C[(size_t)row * N + col] = val;
                } else {
                    int region = col >> 9;
                    int cr = col & 511;
                    int hh = cr >> 6, dd = cr & 63;
                    if (region == 0)      g_Q[((size_t)hh * S_LEN + row) * DH + dd] = val;
                    else if (region == 1) g_K[((size_t)hh * KL + row + NPM) * DH + dd] = val;
                    else                  g_V[((size_t)hh * KL + row + NPM) * DH + dd] = val;
                }
            }
        }
    }
}

// ---------------------------------------------------------------------------
// 4) RoPE apply + bf16 hi/lo emission for Q and K. One warp per row.
// ---------------------------------------------------------------------------
__global__ void rope_apply_kernel(const float* __restrict__ pm) {
    int gwarp = (blockIdx.x * blockDim.x + threadIdx.x) >> 5;
    int j = threadIdx.x & 31;
    const int KROWS = HEADS * KL;
    const int TOT   = KROWS + HEADS * S_LEN;
    if (gwarp >= TOT) return;

    if (gwarp < KROWS) {
        int h = gwarp / KL, t = gwarp % KL;
        const size_t base = ((size_t)h * KL + t) * DH + 2 * j;
        float x1, x2;
        if (t < NPM) {
            const float* pmk = pm + (((size_t)0 * HEADS + h) * NPM + t) * DH;
            const float* pmv = pm + (((size_t)1 * HEADS + h) * NPM + t) * DH;
            x1 = pmk[2 * j]; x2 = pmk[2 * j + 1];
            g_V[base]     = pmv[2 * j];
            g_V[base + 1] = pmv[2 * j + 1];
        } else {
            x1 = g_K[base]; x2 = g_K[base + 1];
        }
        float c = g_cos[t * 32 + j], sn = g_sin[t * 32 + j];
        float r1 = x1 * c - x2 * sn;
        float r2 = x2 * c + x1 * sn;
        *(uint32_t*)(g_Kh + base) = bf2_hi(r1, r2);
        *(uint32_t*)(g_Kl + base) = bf2_lo(r1, r2);
    } else {
        int r = gwarp - KROWS;
        int h = r / S_LEN, s = r % S_LEN;
        int pos = s + NPM;
        const size_t base = ((size_t)h * S_LEN + s) * DH + 2 * j;
        float x1 = g_Q[base], x2 = g_Q[base + 1];
        float c = g_cos[pos * 32 + j], sn = g_sin[pos * 32 + j];
        float r1 = x1 * c - x2 * sn;
        float r2 = x2 * c + x1 * sn;
        *(uint32_t*)(g_Qh + base) = bf2_hi(r1, r2);
        *(uint32_t*)(g_Ql + base) = bf2_lo(r1, r2);
    }
}

// ---------------------------------------------------------------------------
// 4b) V transpose + bf16 split: g_V [h][t][d] -> g_Vth/g_Vtl [h][d][t]
// ---------------------------------------------------------------------------
__global__ void vtrans_kernel() {
    __shared__ float tile[32][33];
    int h  = blockIdx.z;
    int d0 = blockIdx.y * 32;
    int t0 = blockIdx.x * 32;
    for (int r = threadIdx.y; r < 32; r += 8) {
        int t = t0 + r;
        if (t < KL)
            tile[r][threadIdx.x] = g_V[((size_t)h * KL + t) * DH + d0 + threadIdx.x];
    }
    __syncthreads();
    for (int r = threadIdx.y; r < 32; r += 8) {
        int d = d0 + r;
        int t = t0 + threadIdx.x;
        if (t < KL) {
            float v = tile[threadIdx.x][r];
            __nv_bfloat16 hi = __float2bfloat16(v);
            g_Vth[((size_t)(h * DH + d)) * KL + t] = hi;
            g_Vtl[((size_t)(h * DH + d)) * KL + t] =
                __float2bfloat16(v - __bfloat162float(hi));
        }
    }
}

// ---------------------------------------------------------------------------
// 5) Tensor-core flash attention.
// Grid (qt=8, seg=8, h=8), 128 threads (4 warps x 16 q-rows).
// Tiles: mem tile (16 keys) first, then kt = 0..qt (64 keys each).
// S = Q*K^T via 3-split bf16 mma; online softmax (exp2 domain) on C frags;
// P split hi/lo, O += P*V^T via 3-split. All smem 128B rows, XOR-swizzled.
// ---------------------------------------------------------------------------
#define SWADDR(base, row, ch) ((base) + (uint32_t)(row) * 128u + \
                               ((uint32_t)((ch) ^ ((row) & 7)) << 4))

__global__ __launch_bounds__(128) void attn_mma_kernel() {
    __shared__ uint4 sQh[512], sQl[512];   // [qrow][chunk of 8 bf16]
    __shared__ uint4 sKh[512], sKl[512];   // [key ][d-chunk]
    __shared__ uint4 sVh[512], sVl[512];   // [d   ][key-chunk]  (V^T)

    const int qt = blockIdx.x, seg = blockIdx.y, h = blockIdx.z;
    const int tid = threadIdx.x;
    const int lane = tid & 31, w = tid >> 5;

    const uint32_t bQh = (uint32_t)__cvta_generic_to_shared(sQh);
    const uint32_t bQl = (uint32_t)__cvta_generic_to_shared(sQl);
    const uint32_t bKh = (uint32_t)__cvta_generic_to_shared(sKh);
    const uint32_t bKl = (uint32_t)__cvta_generic_to_shared(sKl);
    const uint32_t bVh = (uint32_t)__cvta_generic_to_shared(sVh);
    const uint32_t bVl = (uint32_t)__cvta_generic_to_shared(sVl);

    const int s0 = seg * SEGLEN + qt * 64;      // first query of block

    // ---- stage Q (64 rows x 64 d) ----
    for (int i = tid; i < 512; i += 128) {
        int row = i >> 3, ch = i & 7;
        const uint4* srch = (const uint4*)(g_Qh + ((size_t)h * S_LEN + s0 + row) * DH) + ch;
        const uint4* srcl = (const uint4*)(g_Ql + ((size_t)h * S_LEN + s0 + row) * DH) + ch;
        int d = row * 8 + (ch ^ (row & 7));
        sQh[d] = *srch;
        sQl[d] = *srcl;
    }
    __syncthreads();

    // ---- Q fragments (resident) ----
    uint32_t qh[4][4], ql[4][4];
    {
        int row = w * 16 + (lane & 15);
        #pragma unroll
        for (int j = 0; j < 4; j++) {
            int ch = 2 * j + (lane >> 4);
            ldsm_x4(qh[j][0], qh[j][1], qh[j][2], qh[j][3], SWADDR(bQh, row, ch));
            ldsm_x4(ql[j][0], ql[j][1], ql[j][2], ql[j][3], SWADDR(bQl, row, ch));
        }
    }

    float oacc[8][4];
    #pragma unroll
    for (int nf = 0; nf < 8; nf++)
        #pragma unroll
        for (int r = 0; r < 4; r++) oacc[nf][r] = 0.0f;
    float mrun[2] = {-INFINITY, -INFINITY};
    float lrun[2] = {0.0f, 0.0f};

    const float SC = 0.125f * 1.44269504088896341f;   // scale * log2(e)
    const int r1 = lane >> 2;                          // warp-local row (also +8)
    const int cbase = (lane & 3) * 2;

    const int ntiles = qt + 2;                         // mem + (qt+1)
    for (int tt = 0; tt < ntiles; tt++) {
        const bool ismem = (tt == 0);
        const int cntK = ismem ? 16 : 64;
        const int t0 = ismem ? 0 : (NPM + seg * SEGLEN + (tt - 1) * 64);
        const bool diag = (!ismem) && ((tt - 1) == qt);

        // ---- stage K (keys x d) and V^T (d x keys) ----
        __syncthreads();
        for (int i = tid; i < 512; i += 128) {
            int row = i >> 3, ch = i & 7;
            int d = row * 8 + (ch ^ (row & 7));
            if (row < cntK) {
                sKh[d] = *((const uint4*)(g_Kh + ((size_t)h * KL + t0 + row) * DH) + ch);
                sKl[d] = *((const uint4*)(g_Kl + ((size_t)h * KL + t0 + row) * DH) + ch);
            }
            if (ch * 8 < cntK) {
                sVh[d] = *((const uint4*)(g_Vth + ((size_t)(h * DH + row)) * KL + t0) + ch);
                sVl[d] = *((const uint4*)(g_Vtl + ((size_t)(h * DH + row)) * KL + t0) + ch);
            }
        }
        __syncthreads();

        // ---- S = Q K^T (3-split) ----
        float sacc[8][4];
        #pragma unroll
        for (int nf = 0; nf < 8; nf++)
            #pragma unroll
            for (int r = 0; r < 4; r++) sacc[nf][r] = 0.0f;

        #pragma unroll
        for (int j = 0; j < 4; j++) {                  // d contraction
            uint32_t kh[4][4], kl[4][4];
            int ch = 2 * j + (lane >> 4);
            #pragma unroll
            for (int ng = 0; ng < 4; ng++) {
                if (ismem && ng > 0) break;
                int row = ng * 16 + (lane & 15);
                ldsm_x4(kh[ng][0], kh[ng][1], kh[ng][2], kh[ng][3], SWADDR(bKh, row, ch));
                ldsm_x4(kl[ng][0], kl[ng][1], kl[ng][2], kl[ng][3], SWADDR(bKl, row, ch));
            }
            #pragma unroll
            for (int nf = 0; nf < 8; nf++) {
                if (ismem && nf >= 2) continue;
                const int ng = nf >> 1, sel = nf & 1;
                uint32_t b0h = kh[ng][sel], b1h = kh[ng][2 + sel];
                uint32_t b0l = kl[ng][sel], b1l = kl[ng][2 + sel];
                mma16816(sacc[nf], qh[j], b0h, b1h);
                mma16816(sacc[nf], qh[j], b0l, b1l);
                mma16816(sacc[nf], ql[j], b0h, b1h);
            }
        }

        // ---- scale + mask (exp2 domain) ----
        #pragma unroll
        for (int nf = 0; nf < 8; nf++) {
            #pragma unroll
            for (int r = 0; r < 4; r++) {
                int col = nf * 8 + cbase + (r & 1);
                int qrow = w * 16 + r1 + ((r >= 2) ? 8 : 0);
                float v = sacc[nf][r] * SC;
                bool bad = (ismem && col >= 16) || (diag && col > qrow);
                sacc[nf][r] = bad ? -INFINITY : v;
            }
        }

        // ---- row max ----
        float ml[2] = {-INFINITY, -INFINITY};
        #pragma unroll
        for (int nf = 0; nf < 8; nf++) {
            ml[0] = fmaxf(ml[0], fmaxf(sacc[nf][0], sacc[nf][1]));
            ml[1] = fmaxf(ml[1], fmaxf(sacc[nf][2], sacc[nf][3]));
        }
        #pragma unroll
        for (int o = 1; o <= 2; o <<= 1) {
            ml[0] = fmaxf(ml[0], __shfl_xor_sync(0xffffffffu, ml[0], o));
            ml[1] = fmaxf(ml[1], __shfl_xor_sync(0xffffffffu, ml[1], o));
        }
        float mnew0 = fmaxf(mrun[0], ml[0]);
        float mnew1 = fmaxf(mrun[1], ml[1]);
        float corr0 = exp2f(mrun[0] - mnew0);          // 0 when mrun=-inf
        float corr1 = exp2f(mrun[1] - mnew1);
        mrun[0] = mnew0; mrun[1] = mnew1;

        // ---- p = exp2(s - m), row sums ----
        float ls[2] = {0.0f, 0.0f};
        #pragma unroll
        for (int nf = 0; nf < 8; nf++) {
            float p0 = exp2f(sacc[nf][0] - mnew0);
            float p1 = exp2f(sacc[nf][1] - mnew0);
            float p2 = exp2f(sacc[nf][2] - mnew1);
            float p3 = exp2f(sacc[nf][3] - mnew1);
            sacc[nf][0] = p0; sacc[nf][1] = p1; sacc[nf][2] = p2; sacc[nf][3] = p3;
            ls[0] += p0 + p1; ls[1] += p2 + p3;
        }
        #pragma unroll
        for (int o = 1; o <= 2; o <<= 1) {
            ls[0] += __shfl_xor_sync(0xffffffffu, ls[0], o);
            ls[1] += __shfl_xor_sync(0xffffffffu, ls[1], o);
        }
        lrun[0] = lrun[0] * corr0 + ls[0];
        lrun[1] = lrun[1] * corr1 + ls[1];

        #pragma unroll
        for (int nf = 0; nf < 8; nf++) {
            oacc[nf][0] *= corr0; oacc[nf][1] *= corr0;
            oacc[nf][2] *= corr1; oacc[nf][3] *= corr1;
        }

        // ---- O += P V^T (3-split) ----
        #pragma unroll
        for (int j = 0; j < 4; j++) {                  // key contraction
            if (ismem && j > 0) break;
            uint32_t pa_h[4], pa_l[4];
            pa_h[0] = bf2_hi(sacc[2*j][0],   sacc[2*j][1]);
            pa_h[1] = bf2_hi(sacc[2*j][2],   sacc[2*j][3]);
            pa_h[2] = bf2_hi(sacc[2*j+1][0], sacc[2*j+1][1]);
            pa_h[3] = bf2_hi(sacc[2*j+1][2], sacc[2*j+1][3]);
            pa_l[0] = bf2_lo(sacc[2*j][0],   sacc[2*j][1]);
            pa_l[1] = bf2_lo(sacc[2*j][2],   sacc[2*j][3]);
            pa_l[2] = bf2_lo(sacc[2*j+1][0], sacc[2*j+1][1]);
            pa_l[3] = bf2_lo(sacc[2*j+1][2], sacc[2*j+1][3]);

            uint32_t vh[4][4], vl[4][4];
            int ch = 2 * j + (lane >> 4);
            #pragma unroll
            for (int dg = 0; dg < 4; dg++) {
                int row = dg * 16 + (lane & 15);
                ldsm_x4(vh[dg][0], vh[dg][1], vh[dg][2], vh[dg][3], SWADDR(bVh, row, ch));
                ldsm_x4(vl[dg][0], vl[dg][1], vl[dg][2], vl[dg][3], SWADDR(bVl, row, ch));
            }
            #pragma unroll
            for (int nf = 0; nf < 8; nf++) {
                const int dg = nf >> 1, sel = nf & 1;
                uint32_t b0h = vh[dg][sel], b1h = vh[dg][2 + sel];
                uint32_t b0l = vl[dg][sel], b1l = vl[dg][2 + sel];
                mma16816(oacc[nf], pa_h, b0h, b1h);
                mma16816(oacc[nf], pa_h, b0l, b1l);
                mma16816(oacc[nf], pa_l, b0h, b1h);
            }
        }
    }

    // ---- write out ----
    float inv0 = 1.0f / lrun[0];
    float inv1 = 1.0f / lrun[1];
    int qrow = s0 + w * 16 + r1;
    #pragma unroll
    for (int nf = 0; nf < 8; nf++) {
        int col = h * DH + nf * 8 + cbase;
        g_attn[(size_t)qrow * DIM + col]           = oacc[nf][0] * inv0;
        g_attn[(size_t)qrow * DIM + col + 1]       = oacc[nf][1] * inv0;
        g_attn[(size_t)(qrow + 8) * DIM + col]     = oacc[nf][2] * inv1;
        g_attn[(size_t)(qrow + 8) * DIM + col + 1] = oacc[nf][3] * inv1;
    }
}

// ---------------------------------------------------------------------------
// Launch
// ---------------------------------------------------------------------------
extern "C" void kernel_launch(void* const* d_in, const int* in_sizes, int n_in,
                              void* d_out, int out_size) {
    const float* seq    = (const float*)d_in[0];
    const float* norm_w = (const float*)d_in[1];
    const float* w_qkv  = (const float*)d_in[2];
    const float* w_out  = (const float*)d_in[3];
    const float* pm     = (const float*)d_in[4];

    float* attn_ptr = nullptr;
    cudaGetSymbolAddress((void**)&attn_ptr, g_attn);

    rms_kernel<<<S_LEN, 128>>>(seq);
    rope_table_kernel<<<(KL * 32 + 127) / 128, 128>>>();

    mm_kernel<<<dim3(QKV_N / 128, S_LEN / 128), 256>>>(
        seq, w_qkv, nullptr, QKV_N, DIM, norm_w, 1);

    {
        const int TOTW = HEADS * KL + HEADS * S_LEN;
        int threads = TOTW * 32;
        rope_apply_kernel<<<(threads + 127) / 128, 128>>>(pm);
    }

    vtrans_kernel<<<dim3((KL + 31) / 32, DH / 32, HEADS), dim3(32, 8)>>>();

    attn_mma_kernel<<<dim3(8, 8, 8), 128>>>();

    mm_kernel<<<dim3(DIM / 128, S_LEN / 128), 256>>>(
        attn_ptr, w_out, (float*)d_out, DIM, DIM, nullptr, 0);
}

// round 7
// speedup vs baseline: 2.1709x; 1.2701x over previous
#include <cuda_runtime.h>
#include <cuda_bf16.h>
#include <cstdint>
#include <math.h>

// ---------------------------------------------------------------------------
// Problem constants
// ---------------------------------------------------------------------------
#define S_LEN 4096
#define DIM   512
#define HEADS 8
#define DH    64
#define NPM   16
#define SEGLEN 512
#define KL    (S_LEN + NPM)        // 4112 keys after memory prepend
#define QKV_N (3 * HEADS * DH)     // 1536

// ---------------------------------------------------------------------------
// Scratch (device globals: no allocation allowed)
// ---------------------------------------------------------------------------
__device__ float g_inv_rms[S_LEN];
__device__ float g_Q[HEADS * S_LEN * DH];     // fp32 [h][s][d] (pre-rope)
__device__ float g_K[HEADS * KL * DH];        // fp32 [h][t][d] (pre-rope, t>=16)
__device__ float g_V[HEADS * KL * DH];        // fp32 [h][t][d]
__device__ float g_cos[KL * 32];
__device__ float g_sin[KL * 32];
// pre-split bf16 operands
__device__ __align__(16) __nv_bfloat16 g_Xh[S_LEN * DIM];      // normed input
__device__ __align__(16) __nv_bfloat16 g_Xl[S_LEN * DIM];
__device__ __align__(16) __nv_bfloat16 g_WqkvTh[QKV_N * DIM];  // [n][k]
__device__ __align__(16) __nv_bfloat16 g_WqkvTl[QKV_N * DIM];
__device__ __align__(16) __nv_bfloat16 g_WoutTh[DIM * DIM];    // [n][k]
__device__ __align__(16) __nv_bfloat16 g_WoutTl[DIM * DIM];
__device__ __align__(16) __nv_bfloat16 g_Ah[S_LEN * DIM];      // attention out
__device__ __align__(16) __nv_bfloat16 g_Al[S_LEN * DIM];
// attention operands
__device__ __align__(16) __nv_bfloat16 g_Qh[HEADS * S_LEN * DH];
__device__ __align__(16) __nv_bfloat16 g_Ql[HEADS * S_LEN * DH];
__device__ __align__(16) __nv_bfloat16 g_Kh[HEADS * KL * DH];
__device__ __align__(16) __nv_bfloat16 g_Kl[HEADS * KL * DH];
__device__ __align__(16) __nv_bfloat16 g_Vth[HEADS * DH * KL]; // [h][d][t]
__device__ __align__(16) __nv_bfloat16 g_Vtl[HEADS * DH * KL];

// ---------------------------------------------------------------------------
// helpers
// ---------------------------------------------------------------------------
__device__ __forceinline__ uint32_t bf2_hi(float a0, float a1) {
    unsigned short u0 = __bfloat16_as_ushort(__float2bfloat16(a0));
    unsigned short u1 = __bfloat16_as_ushort(__float2bfloat16(a1));
    return (uint32_t)u0 | ((uint32_t)u1 << 16);
}
__device__ __forceinline__ uint32_t bf2_lo(float a0, float a1) {
    float r0 = a0 - __bfloat162float(__float2bfloat16(a0));
    float r1 = a1 - __bfloat162float(__float2bfloat16(a1));
    unsigned short u0 = __bfloat16_as_ushort(__float2bfloat16(r0));
    unsigned short u1 = __bfloat16_as_ushort(__float2bfloat16(r1));
    return (uint32_t)u0 | ((uint32_t)u1 << 16);
}

__device__ __forceinline__ void ldsm_x4(uint32_t& r0, uint32_t& r1,
                                        uint32_t& r2, uint32_t& r3, uint32_t addr) {
    asm volatile("ldmatrix.sync.aligned.m8n8.x4.shared.b16 {%0,%1,%2,%3}, [%4];"
                 : "=r"(r0), "=r"(r1), "=r"(r2), "=r"(r3) : "r"(addr));
}

__device__ __forceinline__ void mma16816(float* c, const uint32_t* a,
                                         uint32_t b0, uint32_t b1) {
    asm volatile(
        "mma.sync.aligned.m16n8k16.row.col.f32.bf16.bf16.f32 "
        "{%0,%1,%2,%3}, {%4,%5,%6,%7}, {%8,%9}, {%0,%1,%2,%3};"
        : "+f"(c[0]), "+f"(c[1]), "+f"(c[2]), "+f"(c[3])
        : "r"(a[0]), "r"(a[1]), "r"(a[2]), "r"(a[3]), "r"(b0), "r"(b1));
}

#define CPA16(dst, src) \
    asm volatile("cp.async.cg.shared.global [%0], [%1], 16;" \
                 :: "r"(dst), "l"(src))

// ---------------------------------------------------------------------------
// 1) RMSNorm row scales
// ---------------------------------------------------------------------------
__global__ void rms_kernel(const float* __restrict__ seq) {
    int s = blockIdx.x;
    int tid = threadIdx.x;
    const float4* row = (const float4*)(seq + (size_t)s * DIM);
    float4 v = row[tid];
    float p = v.x * v.x + v.y * v.y + v.z * v.z + v.w * v.w;
    #pragma unroll
    for (int o = 16; o; o >>= 1) p += __shfl_xor_sync(0xffffffffu, p, o);
    __shared__ float ws[4];
    if ((tid & 31) == 0) ws[tid >> 5] = p;
    __syncthreads();
    if (tid == 0) {
        float tot = ws[0] + ws[1] + ws[2] + ws[3];
        g_inv_rms[s] = rsqrtf(tot * (1.0f / (float)DIM) + 1.1920928955078125e-07f);
    }
}

// ---------------------------------------------------------------------------
// 2) RoPE tables
// ---------------------------------------------------------------------------
__global__ void rope_table_kernel() {
    int idx = blockIdx.x * blockDim.x + threadIdx.x;
    if (idx >= KL * 32) return;
    int pos = idx >> 5, j = idx & 31;
    float rf  = (float)pow(10000.0, -(double)j / 32.0);
    float ang = (float)pos * rf;
    g_cos[idx] = (float)cos((double)ang);
    g_sin[idx] = (float)sin((double)ang);
}

// ---------------------------------------------------------------------------
// 2b) Convert normed X to bf16 hi/lo (rms * norm_w fused). One-time.
// ---------------------------------------------------------------------------
__global__ void convert_x_kernel(const float* __restrict__ seq,
                                 const float* __restrict__ norm_w) {
    int s = blockIdx.x;
    int tid = threadIdx.x;                       // 128
    float rs = g_inv_rms[s];
    float4 v = ((const float4*)(seq + (size_t)s * DIM))[tid];
    float4 w = ((const float4*)norm_w)[tid];
    v.x *= rs * w.x; v.y *= rs * w.y; v.z *= rs * w.z; v.w *= rs * w.w;
    ((uint2*)(g_Xh + (size_t)s * DIM))[tid] = make_uint2(bf2_hi(v.x, v.y), bf2_hi(v.z, v.w));
    ((uint2*)(g_Xl + (size_t)s * DIM))[tid] = make_uint2(bf2_lo(v.x, v.y), bf2_lo(v.z, v.w));
}

// ---------------------------------------------------------------------------
// 2c) Transpose+split weights: src [K][N] fp32 -> dstT hi/lo [N][K] bf16.
// ---------------------------------------------------------------------------
__global__ void wtrans_kernel(const float* __restrict__ src,
                              __nv_bfloat16* __restrict__ dh,
                              __nv_bfloat16* __restrict__ dl, int K, int N) {
    __shared__ float tile[32][33];
    int n0 = blockIdx.x * 32, k0 = blockIdx.y * 32;
    for (int r = threadIdx.y; r < 32; r += 8)
        tile[r][threadIdx.x] = src[(size_t)(k0 + r) * N + n0 + threadIdx.x];
    __syncthreads();
    for (int r = threadIdx.y; r < 32; r += 8) {
        int n = n0 + r, k = k0 + threadIdx.x;
        float v = tile[threadIdx.x][r];
        __nv_bfloat16 hi = __float2bfloat16(v);
        dh[(size_t)n * K + k] = hi;
        dl[(size_t)n * K + k] = __float2bfloat16(v - __bfloat162float(hi));
    }
}

// ---------------------------------------------------------------------------
// 3) bf16 split GEMM, pre-converted inputs, cp.async double-buffered.
// A hi/lo [M][K], B hi/lo [N][K] (pre-transposed). BM=BN=128, BK=32.
// 256 threads, 2x4 warps, 64x32 per warp. 3-term split MMA.
// Dynamic smem: 2 stages x (Ah,Al,Bh,Bl) x 128 rows x 80 B = 81920 B.
// epi 0: C store. epi 1: scatter Q/K/V fp32.
// ---------------------------------------------------------------------------
#define STG_A_H 0
#define STG_A_L 10240
#define STG_B_H 20480
#define STG_B_L 30720
#define STG_SZ  40960

#define PREFETCH(S) do {                                                      \
    int _k0 = (S) * 32;                                                       \
    uint32_t _b = sbase + ((S) & 1) * STG_SZ + r * 80 + cg * 16;              \
    const __nv_bfloat16* _ag = Ah + (size_t)(row0 + r) * K + _k0 + cg * 8;    \
    const __nv_bfloat16* _al = Al + (size_t)(row0 + r) * K + _k0 + cg * 8;    \
    const __nv_bfloat16* _bg = Bh + (size_t)(col0 + r) * K + _k0 + cg * 8;    \
    const __nv_bfloat16* _bl = Bl + (size_t)(col0 + r) * K + _k0 + cg * 8;    \
    CPA16(_b + STG_A_H,      _ag);                                            \
    CPA16(_b + STG_A_H + 16, _ag + 8);                                        \
    CPA16(_b + STG_A_L,      _al);                                            \
    CPA16(_b + STG_A_L + 16, _al + 8);                                        \
    CPA16(_b + STG_B_H,      _bg);                                            \
    CPA16(_b + STG_B_H + 16, _bg + 8);                                        \
    CPA16(_b + STG_B_L,      _bl);                                            \
    CPA16(_b + STG_B_L + 16, _bl + 8);                                        \
    asm volatile("cp.async.commit_group;");                                   \
} while (0)

__global__ __launch_bounds__(256) void mm2_kernel(
    const __nv_bfloat16* __restrict__ Ah, const __nv_bfloat16* __restrict__ Al,
    const __nv_bfloat16* __restrict__ Bh, const __nv_bfloat16* __restrict__ Bl,
    float* __restrict__ C, int N, int K, int epi)
{
    extern __shared__ __align__(16) uint8_t smem[];
    const uint32_t sbase = (uint32_t)__cvta_generic_to_shared(smem);

    const int tid  = threadIdx.x;
    const int lane = tid & 31, warp = tid >> 5;
    const int wm = warp & 1, wn = warp >> 1;
    const int row0 = blockIdx.y * 128, col0 = blockIdx.x * 128;

    const int r  = tid >> 1;            // staging row 0..127
    const int cg = (tid & 1) * 2;       // chunk group 0 or 2

    const int NST = K / 32;             // 16

    float acc[4][4][4];
    #pragma unroll
    for (int i = 0; i < 4; i++)
        #pragma unroll
        for (int j = 0; j < 4; j++)
            #pragma unroll
            for (int q = 0; q < 4; q++) acc[i][j][q] = 0.0f;

    PREFETCH(0);
    PREFETCH(1);

    const int mbase = wm * 64, nbase = wn * 32;
    const int lr = lane & 15, lh = (lane >> 4) * 16;

    for (int s = 0; s < NST; s++) {
        if (s + 1 < NST) asm volatile("cp.async.wait_group 1;");
        else             asm volatile("cp.async.wait_group 0;");
        __syncthreads();

        const uint32_t bAh = sbase + (s & 1) * STG_SZ + STG_A_H;
        const uint32_t bAl = sbase + (s & 1) * STG_SZ + STG_A_L;
        const uint32_t bBh = sbase + (s & 1) * STG_SZ + STG_B_H;
        const uint32_t bBl = sbase + (s & 1) * STG_SZ + STG_B_L;

        #pragma unroll
        for (int kk = 0; kk < 2; kk++) {
            const uint32_t kb = (uint32_t)(kk * 32 + lh);
            uint32_t ah[4][4], al[4][4], bh[2][4], bl[2][4];
            #pragma unroll
            for (int mf = 0; mf < 4; mf++) {
                uint32_t ro = (uint32_t)(mbase + mf * 16 + lr) * 80 + kb;
                ldsm_x4(ah[mf][0], ah[mf][1], ah[mf][2], ah[mf][3], bAh + ro);
                ldsm_x4(al[mf][0], al[mf][1], al[mf][2], al[mf][3], bAl + ro);
            }
            #pragma unroll
            for (int np = 0; np < 2; np++) {
                uint32_t ro = (uint32_t)(nbase + np * 16 + lr) * 80 + kb;
                ldsm_x4(bh[np][0], bh[np][1], bh[np][2], bh[np][3], bBh + ro);
                ldsm_x4(bl[np][0], bl[np][1], bl[np][2], bl[np][3], bBl + ro);
            }
            #pragma unroll
            for (int mf = 0; mf < 4; mf++) {
                #pragma unroll
                for (int nf = 0; nf < 4; nf++) {
                    const int np = nf >> 1, half = nf & 1;
                    uint32_t b0h = bh[np][half], b1h = bh[np][2 + half];
                    uint32_t b0l = bl[np][half], b1l = bl[np][2 + half];
                    mma16816(acc[mf][nf], ah[mf], b0h, b1h);
                    mma16816(acc[mf][nf], ah[mf], b0l, b1l);
                    mma16816(acc[mf][nf], al[mf], b0h, b1h);
                }
            }
        }
        __syncthreads();
        if (s + 2 < NST) PREFETCH(s + 2);
    }

    #pragma unroll
    for (int mf = 0; mf < 4; mf++) {
        #pragma unroll
        for (int nf = 0; nf < 4; nf++) {
            int rr0 = row0 + mbase + mf * 16 + (lane >> 2);
            int cc0 = col0 + nbase + nf * 8 + (lane & 3) * 2;
            #pragma unroll
            for (int q = 0; q < 4; q++) {
                int row = rr0 + ((q >= 2) ? 8 : 0);
                int col = cc0 + (q & 1);
                float val = acc[mf][nf][q];
                if (epi == 0) {
                    C[(size_t)row * N + col] = val;
                } else {
                    int region = col >> 9;
                    int cr = col & 511;
                    int hh = cr >> 6, dd = cr & 63;
                    if (region == 0)      g_Q[((size_t)hh * S_LEN + row) * DH + dd] = val;
                    else if (region == 1) g_K[((size_t)hh * KL + row + NPM) * DH + dd] = val;
                    else                  g_V[((size_t)hh * KL + row + NPM) * DH + dd] = val;
                }
            }
        }
    }
}

// ---------------------------------------------------------------------------
// 4) RoPE apply + bf16 hi/lo emission for Q and K. One warp per row.
// ---------------------------------------------------------------------------
__global__ void rope_apply_kernel(const float* __restrict__ pm) {
    int gwarp = (blockIdx.x * blockDim.x + threadIdx.x) >> 5;
    int j = threadIdx.x & 31;
    const int KROWS = HEADS * KL;
    const int TOT   = KROWS + HEADS * S_LEN;
    if (gwarp >= TOT) return;

    if (gwarp < KROWS) {
        int h = gwarp / KL, t = gwarp % KL;
        const size_t base = ((size_t)h * KL + t) * DH + 2 * j;
        float x1, x2;
        if (t < NPM) {
            const float* pmk = pm + (((size_t)0 * HEADS + h) * NPM + t) * DH;
            const float* pmv = pm + (((size_t)1 * HEADS + h) * NPM + t) * DH;
            x1 = pmk[2 * j]; x2 = pmk[2 * j + 1];
            g_V[base]     = pmv[2 * j];
            g_V[base + 1] = pmv[2 * j + 1];
        } else {
            x1 = g_K[base]; x2 = g_K[base + 1];
        }
        float c = g_cos[t * 32 + j], sn = g_sin[t * 32 + j];
        float r1 = x1 * c - x2 * sn;
        float r2 = x2 * c + x1 * sn;
        *(uint32_t*)(g_Kh + base) = bf2_hi(r1, r2);
        *(uint32_t*)(g_Kl + base) = bf2_lo(r1, r2);
    } else {
        int rr = gwarp - KROWS;
        int h = rr / S_LEN, s = rr % S_LEN;
        int pos = s + NPM;
        const size_t base = ((size_t)h * S_LEN + s) * DH + 2 * j;
        float x1 = g_Q[base], x2 = g_Q[base + 1];
        float c = g_cos[pos * 32 + j], sn = g_sin[pos * 32 + j];
        float r1 = x1 * c - x2 * sn;
        float r2 = x2 * c + x1 * sn;
        *(uint32_t*)(g_Qh + base) = bf2_hi(r1, r2);
        *(uint32_t*)(g_Ql + base) = bf2_lo(r1, r2);
    }
}

// ---------------------------------------------------------------------------
// 4b) V transpose + split: g_V [h][t][d] -> g_Vth/g_Vtl [h][d][t]
// ---------------------------------------------------------------------------
__global__ void vtrans_kernel() {
    __shared__ float tile[32][33];
    int h  = blockIdx.z;
    int d0 = blockIdx.y * 32;
    int t0 = blockIdx.x * 32;
    for (int r = threadIdx.y; r < 32; r += 8) {
        int t = t0 + r;
        if (t < KL)
            tile[r][threadIdx.x] = g_V[((size_t)h * KL + t) * DH + d0 + threadIdx.x];
    }
    __syncthreads();
    for (int r = threadIdx.y; r < 32; r += 8) {
        int d = d0 + r;
        int t = t0 + threadIdx.x;
        if (t < KL) {
            float v = tile[threadIdx.x][r];
            __nv_bfloat16 hi = __float2bfloat16(v);
            g_Vth[((size_t)(h * DH + d)) * KL + t] = hi;
            g_Vtl[((size_t)(h * DH + d)) * KL + t] =
                __float2bfloat16(v - __bfloat162float(hi));
        }
    }
}

// ---------------------------------------------------------------------------
// 5) Tensor-core flash attention (verified round 5). Epilogue emits
//    bf16 hi/lo (g_Ah/g_Al) for the out-projection GEMM.
// ---------------------------------------------------------------------------
#define SWADDR(base, row, ch) ((base) + (uint32_t)(row) * 128u + \
                               ((uint32_t)((ch) ^ ((row) & 7)) << 4))

__global__ __launch_bounds__(128) void attn_mma_kernel() {
    __shared__ uint4 sQh[512], sQl[512];
    __shared__ uint4 sKh[512], sKl[512];
    __shared__ uint4 sVh[512], sVl[512];

    const int qt = blockIdx.x, seg = blockIdx.y, h = blockIdx.z;
    const int tid = threadIdx.x;
    const int lane = tid & 31, w = tid >> 5;

    const uint32_t bQh = (uint32_t)__cvta_generic_to_shared(sQh);
    const uint32_t bQl = (uint32_t)__cvta_generic_to_shared(sQl);
    const uint32_t bKh = (uint32_t)__cvta_generic_to_shared(sKh);
    const uint32_t bKl = (uint32_t)__cvta_generic_to_shared(sKl);
    const uint32_t bVh = (uint32_t)__cvta_generic_to_shared(sVh);
    const uint32_t bVl = (uint32_t)__cvta_generic_to_shared(sVl);

    const int s0 = seg * SEGLEN + qt * 64;

    for (int i = tid; i < 512; i += 128) {
        int row = i >> 3, ch = i & 7;
        const uint4* srch = (const uint4*)(g_Qh + ((size_t)h * S_LEN + s0 + row) * DH) + ch;
        const uint4* srcl = (const uint4*)(g_Ql + ((size_t)h * S_LEN + s0 + row) * DH) + ch;
        int d = row * 8 + (ch ^ (row & 7));
        sQh[d] = *srch;
        sQl[d] = *srcl;
    }
    __syncthreads();

    uint32_t qh[4][4], ql[4][4];
    {
        int row = w * 16 + (lane & 15);
        #pragma unroll
        for (int j = 0; j < 4; j++) {
            int ch = 2 * j + (lane >> 4);
            ldsm_x4(qh[j][0], qh[j][1], qh[j][2], qh[j][3], SWADDR(bQh, row, ch));
            ldsm_x4(ql[j][0], ql[j][1], ql[j][2], ql[j][3], SWADDR(bQl, row, ch));
        }
    }

    float oacc[8][4];
    #pragma unroll
    for (int nf = 0; nf < 8; nf++)
        #pragma unroll
        for (int q = 0; q < 4; q++) oacc[nf][q] = 0.0f;
    float mrun[2] = {-INFINITY, -INFINITY};
    float lrun[2] = {0.0f, 0.0f};

    const float SC = 0.125f * 1.44269504088896341f;
    const int r1 = lane >> 2;
    const int cbase = (lane & 3) * 2;

    const int ntiles = qt + 2;
    for (int tt = 0; tt < ntiles; tt++) {
        const bool ismem = (tt == 0);
        const int cntK = ismem ? 16 : 64;
        const int t0 = ismem ? 0 : (NPM + seg * SEGLEN + (tt - 1) * 64);
        const bool diag = (!ismem) && ((tt - 1) == qt);

        __syncthreads();
        for (int i = tid; i < 512; i += 128) {
            int row = i >> 3, ch = i & 7;
            int d = row * 8 + (ch ^ (row & 7));
            if (row < cntK) {
                sKh[d] = *((const uint4*)(g_Kh + ((size_t)h * KL + t0 + row) * DH) + ch);
                sKl[d] = *((const uint4*)(g_Kl + ((size_t)h * KL + t0 + row) * DH) + ch);
            }
            if (ch * 8 < cntK) {
                sVh[d] = *((const uint4*)(g_Vth + ((size_t)(h * DH + row)) * KL + t0) + ch);
                sVl[d] = *((const uint4*)(g_Vtl + ((size_t)(h * DH + row)) * KL + t0) + ch);
            }
        }
        __syncthreads();

        float sacc[8][4];
        #pragma unroll
        for (int nf = 0; nf < 8; nf++)
            #pragma unroll
            for (int q = 0; q < 4; q++) sacc[nf][q] = 0.0f;

        #pragma unroll
        for (int j = 0; j < 4; j++) {
            uint32_t kh[4][4], kl[4][4];
            int ch = 2 * j + (lane >> 4);
            #pragma unroll
            for (int ng = 0; ng < 4; ng++) {
                if (ismem && ng > 0) break;
                int row = ng * 16 + (lane & 15);
                ldsm_x4(kh[ng][0], kh[ng][1], kh[ng][2], kh[ng][3], SWADDR(bKh, row, ch));
                ldsm_x4(kl[ng][0], kl[ng][1], kl[ng][2], kl[ng][3], SWADDR(bKl, row, ch));
            }
            #pragma unroll
            for (int nf = 0; nf < 8; nf++) {
                if (ismem && nf >= 2) continue;
                const int ng = nf >> 1, sel = nf & 1;
                uint32_t b0h = kh[ng][sel], b1h = kh[ng][2 + sel];
                uint32_t b0l = kl[ng][sel], b1l = kl[ng][2 + sel];
                mma16816(sacc[nf], qh[j], b0h, b1h);
                mma16816(sacc[nf], qh[j], b0l, b1l);
                mma16816(sacc[nf], ql[j], b0h, b1h);
            }
        }

        #pragma unroll
        for (int nf = 0; nf < 8; nf++) {
            #pragma unroll
            for (int q = 0; q < 4; q++) {
                int col = nf * 8 + cbase + (q & 1);
                int qrow = w * 16 + r1 + ((q >= 2) ? 8 : 0);
                float v = sacc[nf][q] * SC;
                bool bad = (ismem && col >= 16) || (diag && col > qrow);
                sacc[nf][q] = bad ? -INFINITY : v;
            }
        }

        float ml[2] = {-INFINITY, -INFINITY};
        #pragma unroll
        for (int nf = 0; nf < 8; nf++) {
            ml[0] = fmaxf(ml[0], fmaxf(sacc[nf][0], sacc[nf][1]));
            ml[1] = fmaxf(ml[1], fmaxf(sacc[nf][2], sacc[nf][3]));
        }
        #pragma unroll
        for (int o = 1; o <= 2; o <<= 1) {
            ml[0] = fmaxf(ml[0], __shfl_xor_sync(0xffffffffu, ml[0], o));
            ml[1] = fmaxf(ml[1], __shfl_xor_sync(0xffffffffu, ml[1], o));
        }
        float mnew0 = fmaxf(mrun[0], ml[0]);
        float mnew1 = fmaxf(mrun[1], ml[1]);
        float corr0 = exp2f(mrun[0] - mnew0);
        float corr1 = exp2f(mrun[1] - mnew1);
        mrun[0] = mnew0; mrun[1] = mnew1;

        float ls[2] = {0.0f, 0.0f};
        #pragma unroll
        for (int nf = 0; nf < 8; nf++) {
            float p0 = exp2f(sacc[nf][0] - mnew0);
            float p1 = exp2f(sacc[nf][1] - mnew0);
            float p2 = exp2f(sacc[nf][2] - mnew1);
            float p3 = exp2f(sacc[nf][3] - mnew1);
            sacc[nf][0] = p0; sacc[nf][1] = p1; sacc[nf][2] = p2; sacc[nf][3] = p3;
            ls[0] += p0 + p1; ls[1] += p2 + p3;
        }
        #pragma unroll
        for (int o = 1; o <= 2; o <<= 1) {
            ls[0] += __shfl_xor_sync(0xffffffffu, ls[0], o);
            ls[1] += __shfl_xor_sync(0xffffffffu, ls[1], o);
        }
        lrun[0] = lrun[0] * corr0 + ls[0];
        lrun[1] = lrun[1] * corr1 + ls[1];

        #pragma unroll
        for (int nf = 0; nf < 8; nf++) {
            oacc[nf][0] *= corr0; oacc[nf][1] *= corr0;
            oacc[nf][2] *= corr1; oacc[nf][3] *= corr1;
        }

        #pragma unroll
        for (int j = 0; j < 4; j++) {
            if (ismem && j > 0) break;
            uint32_t pa_h[4], pa_l[4];
            pa_h[0] = bf2_hi(sacc[2*j][0],   sacc[2*j][1]);
            pa_h[1] = bf2_hi(sacc[2*j][2],   sacc[2*j][3]);
            pa_h[2] = bf2_hi(sacc[2*j+1][0], sacc[2*j+1][1]);
            pa_h[3] = bf2_hi(sacc[2*j+1][2], sacc[2*j+1][3]);
            pa_l[0] = bf2_lo(sacc[2*j][0],   sacc[2*j][1]);
            pa_l[1] = bf2_lo(sacc[2*j][2],   sacc[2*j][3]);
            pa_l[2] = bf2_lo(sacc[2*j+1][0], sacc[2*j+1][1]);
            pa_l[3] = bf2_lo(sacc[2*j+1][2], sacc[2*j+1][3]);

            uint32_t vh[4][4], vl[4][4];
            int ch = 2 * j + (lane >> 4);
            #pragma unroll
            for (int dg = 0; dg < 4; dg++) {
                int row = dg * 16 + (lane & 15);
                ldsm_x4(vh[dg][0], vh[dg][1], vh[dg][2], vh[dg][3], SWADDR(bVh, row, ch));
                ldsm_x4(vl[dg][0], vl[dg][1], vl[dg][2], vl[dg][3], SWADDR(bVl, row, ch));
            }
            #pragma unroll
            for (int nf = 0; nf < 8; nf++) {
                const int dg = nf >> 1, sel = nf & 1;
                uint32_t b0h = vh[dg][sel], b1h = vh[dg][2 + sel];
                uint32_t b0l = vl[dg][sel], b1l = vl[dg][2 + sel];
                mma16816(oacc[nf], pa_h, b0h, b1h);
                mma16816(oacc[nf], pa_h, b0l, b1l);
                mma16816(oacc[nf], pa_l, b0h, b1h);
            }
        }
    }

    float inv0 = 1.0f / lrun[0];
    float inv1 = 1.0f / lrun[1];
    int qrow = s0 + w * 16 + r1;
    #pragma unroll
    for (int nf = 0; nf < 8; nf++) {
        int col = h * DH + nf * 8 + cbase;
        float o0 = oacc[nf][0] * inv0, o1 = oacc[nf][1] * inv0;
        float o2 = oacc[nf][2] * inv1, o3 = oacc[nf][3] * inv1;
        *(uint32_t*)(g_Ah + (size_t)qrow * DIM + col)       = bf2_hi(o0, o1);
        *(uint32_t*)(g_Al + (size_t)qrow * DIM + col)       = bf2_lo(o0, o1);
        *(uint32_t*)(g_Ah + (size_t)(qrow + 8) * DIM + col) = bf2_hi(o2, o3);
        *(uint32_t*)(g_Al + (size_t)(qrow + 8) * DIM + col) = bf2_lo(o2, o3);
    }
}

// ---------------------------------------------------------------------------
// Launch
// ---------------------------------------------------------------------------
extern "C" void kernel_launch(void* const* d_in, const int* in_sizes, int n_in,
                              void* d_out, int out_size) {
    const float* seq    = (const float*)d_in[0];
    const float* norm_w = (const float*)d_in[1];
    const float* w_qkv  = (const float*)d_in[2];
    const float* w_out  = (const float*)d_in[3];
    const float* pm     = (const float*)d_in[4];

    __nv_bfloat16 *xh, *xl, *wqh, *wql, *woh, *wol, *ah, *al;
    cudaGetSymbolAddress((void**)&xh,  g_Xh);
    cudaGetSymbolAddress((void**)&xl,  g_Xl);
    cudaGetSymbolAddress((void**)&wqh, g_WqkvTh);
    cudaGetSymbolAddress((void**)&wql, g_WqkvTl);
    cudaGetSymbolAddress((void**)&woh, g_WoutTh);
    cudaGetSymbolAddress((void**)&wol, g_WoutTl);
    cudaGetSymbolAddress((void**)&ah,  g_Ah);
    cudaGetSymbolAddress((void**)&al,  g_Al);

    cudaFuncSetAttribute(mm2_kernel,
                         cudaFuncAttributeMaxDynamicSharedMemorySize, 81920);

    rms_kernel<<<S_LEN, 128>>>(seq);
    rope_table_kernel<<<(KL * 32 + 127) / 128, 128>>>();
    convert_x_kernel<<<S_LEN, 128>>>(seq, norm_w);
    wtrans_kernel<<<dim3(QKV_N / 32, DIM / 32), dim3(32, 8)>>>(w_qkv, wqh, wql, DIM, QKV_N);
    wtrans_kernel<<<dim3(DIM / 32, DIM / 32), dim3(32, 8)>>>(w_out, woh, wol, DIM, DIM);

    mm2_kernel<<<dim3(QKV_N / 128, S_LEN / 128), 256, 81920>>>(
        xh, xl, wqh, wql, nullptr, QKV_N, DIM, 1);

    {
        const int TOTW = HEADS * KL + HEADS * S_LEN;
        int threads = TOTW * 32;
        rope_apply_kernel<<<(threads + 127) / 128, 128>>>(pm);
    }

    vtrans_kernel<<<dim3((KL + 31) / 32, DH / 32, HEADS), dim3(32, 8)>>>();

    attn_mma_kernel<<<dim3(8, 8, 8), 128>>>();

    mm2_kernel<<<dim3(DIM / 128, S_LEN / 128), 256, 81920>>>(
        ah, al, woh, wol, (float*)d_out, DIM, DIM, 0);
}

// round 9
// speedup vs baseline: 2.3022x; 1.0605x over previous
#include <cuda_runtime.h>
#include <cuda_bf16.h>
#include <cstdint>
#include <math.h>

// ---------------------------------------------------------------------------
// Problem constants
// ---------------------------------------------------------------------------
#define S_LEN 4096
#define DIM   512
#define HEADS 8
#define DH    64
#define NPM   16
#define SEGLEN 512
#define KL    (S_LEN + NPM)        // 4112 keys after memory prepend
#define QKV_N (3 * HEADS * DH)     // 1536

// ---------------------------------------------------------------------------
// Scratch (device globals: no allocation allowed)
// ---------------------------------------------------------------------------
__device__ float g_Q[HEADS * S_LEN * DH];     // fp32 [h][s][d] (pre-rope)
__device__ float g_K[HEADS * KL * DH];        // fp32 [h][t][d] (pre-rope, t>=16)
__device__ float g_V[HEADS * KL * DH];        // fp32 [h][t][d]
__device__ float g_cos[KL * 32];
__device__ float g_sin[KL * 32];
// pre-split bf16 operands
__device__ __align__(16) __nv_bfloat16 g_Xh[S_LEN * DIM];      // normed input
__device__ __align__(16) __nv_bfloat16 g_Xl[S_LEN * DIM];
__device__ __align__(16) __nv_bfloat16 g_WqkvTh[QKV_N * DIM];  // [n][k]
__device__ __align__(16) __nv_bfloat16 g_WqkvTl[QKV_N * DIM];
__device__ __align__(16) __nv_bfloat16 g_WoutTh[DIM * DIM];    // [n][k]
__device__ __align__(16) __nv_bfloat16 g_WoutTl[DIM * DIM];
__device__ __align__(16) __nv_bfloat16 g_Ah[S_LEN * DIM];      // attention out
__device__ __align__(16) __nv_bfloat16 g_Al[S_LEN * DIM];
// attention operands
__device__ __align__(16) __nv_bfloat16 g_Qh[HEADS * S_LEN * DH];
__device__ __align__(16) __nv_bfloat16 g_Ql[HEADS * S_LEN * DH];
__device__ __align__(16) __nv_bfloat16 g_Kh[HEADS * KL * DH];
__device__ __align__(16) __nv_bfloat16 g_Kl[HEADS * KL * DH];
__device__ __align__(16) __nv_bfloat16 g_Vth[HEADS * DH * KL]; // [h][d][t]
__device__ __align__(16) __nv_bfloat16 g_Vtl[HEADS * DH * KL];

// ---------------------------------------------------------------------------
// helpers
// ---------------------------------------------------------------------------
// Truncation split of a float pair into bf16x2 hi (top 16 bits) and lo
// (residual, round-to-nearest). hi: 1 PRMT; lo: 2 AND + 2 SUB + 1 CVT.
__device__ __forceinline__ void split2(float a0, float a1,
                                       uint32_t& hi, uint32_t& lo) {
    uint32_t u0 = __float_as_uint(a0), u1 = __float_as_uint(a1);
    asm("prmt.b32 %0, %1, %2, 0x7632;" : "=r"(hi) : "r"(u0), "r"(u1));
    float r0 = a0 - __uint_as_float(u0 & 0xFFFF0000u);
    float r1 = a1 - __uint_as_float(u1 & 0xFFFF0000u);
    asm("cvt.rn.bf16x2.f32 %0, %1, %2;" : "=r"(lo) : "f"(r1), "f"(r0));
}

__device__ __forceinline__ float ex2(float x) {
    float r; asm("ex2.approx.f32 %0, %1;" : "=f"(r) : "f"(x)); return r;
}

__device__ __forceinline__ void ldsm_x4(uint32_t& r0, uint32_t& r1,
                                        uint32_t& r2, uint32_t& r3, uint32_t addr) {
    asm volatile("ldmatrix.sync.aligned.m8n8.x4.shared.b16 {%0,%1,%2,%3}, [%4];"
                 : "=r"(r0), "=r"(r1), "=r"(r2), "=r"(r3) : "r"(addr));
}

__device__ __forceinline__ void mma16816(float* c, const uint32_t* a,
                                         uint32_t b0, uint32_t b1) {
    asm volatile(
        "mma.sync.aligned.m16n8k16.row.col.f32.bf16.bf16.f32 "
        "{%0,%1,%2,%3}, {%4,%5,%6,%7}, {%8,%9}, {%0,%1,%2,%3};"
        : "+f"(c[0]), "+f"(c[1]), "+f"(c[2]), "+f"(c[3])
        : "r"(a[0]), "r"(a[1]), "r"(a[2]), "r"(a[3]), "r"(b0), "r"(b1));
}

#define CPA16(dst, src) \
    asm volatile("cp.async.cg.shared.global [%0], [%1], 16;" \
                 :: "r"(dst), "l"(src))

// ---------------------------------------------------------------------------
// 1) RoPE tables
// ---------------------------------------------------------------------------
__global__ void rope_table_kernel() {
    int idx = blockIdx.x * blockDim.x + threadIdx.x;
    if (idx >= KL * 32) return;
    int pos = idx >> 5, j = idx & 31;
    float rf  = (float)pow(10000.0, -(double)j / 32.0);
    float ang = (float)pos * rf;
    g_cos[idx] = (float)cos((double)ang);
    g_sin[idx] = (float)sin((double)ang);
}

// ---------------------------------------------------------------------------
// 2) RMSNorm + convert X to bf16 hi/lo in one pass.
// ---------------------------------------------------------------------------
__global__ void convert_x_kernel(const float* __restrict__ seq,
                                 const float* __restrict__ norm_w) {
    int s = blockIdx.x;
    int tid = threadIdx.x;                       // 128
    float4 v = ((const float4*)(seq + (size_t)s * DIM))[tid];
    float p = v.x * v.x + v.y * v.y + v.z * v.z + v.w * v.w;
    #pragma unroll
    for (int o = 16; o; o >>= 1) p += __shfl_xor_sync(0xffffffffu, p, o);
    __shared__ float ws[4];
    if ((tid & 31) == 0) ws[tid >> 5] = p;
    __syncthreads();
    float rs = rsqrtf((ws[0] + ws[1] + ws[2] + ws[3]) * (1.0f / (float)DIM)
                      + 1.1920928955078125e-07f);
    float4 w = ((const float4*)norm_w)[tid];
    v.x *= rs * w.x; v.y *= rs * w.y; v.z *= rs * w.z; v.w *= rs * w.w;
    uint32_t h0, l0, h1, l1;
    split2(v.x, v.y, h0, l0);
    split2(v.z, v.w, h1, l1);
    ((uint2*)(g_Xh + (size_t)s * DIM))[tid] = make_uint2(h0, h1);
    ((uint2*)(g_Xl + (size_t)s * DIM))[tid] = make_uint2(l0, l1);
}

// ---------------------------------------------------------------------------
// 2c) Transpose+split weights: src [K][N] fp32 -> dstT hi/lo [N][K] bf16.
// ---------------------------------------------------------------------------
__global__ void wtrans_kernel(const float* __restrict__ src,
                              __nv_bfloat16* __restrict__ dh,
                              __nv_bfloat16* __restrict__ dl, int K, int N) {
    __shared__ float tile[32][33];
    int n0 = blockIdx.x * 32, k0 = blockIdx.y * 32;
    for (int r = threadIdx.y; r < 32; r += 8)
        tile[r][threadIdx.x] = src[(size_t)(k0 + r) * N + n0 + threadIdx.x];
    __syncthreads();
    for (int r = threadIdx.y; r < 32; r += 8) {
        int n = n0 + r, k = k0 + threadIdx.x;
        float v = tile[threadIdx.x][r];
        uint32_t uv = __float_as_uint(v) & 0xFFFF0000u;
        dh[(size_t)n * K + k] = __ushort_as_bfloat16((unsigned short)(uv >> 16));
        dl[(size_t)n * K + k] = __float2bfloat16(v - __uint_as_float(uv));
    }
}

// ---------------------------------------------------------------------------
// 3) bf16 split GEMM, pre-converted inputs, cp.async double-buffered.
//    (verified round 7, unchanged)
// ---------------------------------------------------------------------------
#define STG_A_H 0
#define STG_A_L 10240
#define STG_B_H 20480
#define STG_B_L 30720
#define STG_SZ  40960

#define PREFETCH(S) do {                                                      \
    int _k0 = (S) * 32;                                                       \
    uint32_t _b = sbase + ((S) & 1) * STG_SZ + r * 80 + cg * 16;              \
    const __nv_bfloat16* _ag = Ah + (size_t)(row0 + r) * K + _k0 + cg * 8;    \
    const __nv_bfloat16* _al = Al + (size_t)(row0 + r) * K + _k0 + cg * 8;    \
    const __nv_bfloat16* _bg = Bh + (size_t)(col0 + r) * K + _k0 + cg * 8;    \
    const __nv_bfloat16* _bl = Bl + (size_t)(col0 + r) * K + _k0 + cg * 8;    \
    CPA16(_b + STG_A_H,      _ag);                                            \
    CPA16(_b + STG_A_H + 16, _ag + 8);                                        \
    CPA16(_b + STG_A_L,      _al);                                            \
    CPA16(_b + STG_A_L + 16, _al + 8);                                        \
    CPA16(_b + STG_B_H,      _bg);                                            \
    CPA16(_b + STG_B_H + 16, _bg + 8);                                        \
    CPA16(_b + STG_B_L,      _bl);                                            \
    CPA16(_b + STG_B_L + 16, _bl + 8);                                        \
    asm volatile("cp.async.commit_group;");                                   \
} while (0)

__global__ __launch_bounds__(256) void mm2_kernel(
    const __nv_bfloat16* __restrict__ Ah, const __nv_bfloat16* __restrict__ Al,
    const __nv_bfloat16* __restrict__ Bh, const __nv_bfloat16* __restrict__ Bl,
    float* __restrict__ C, int N, int K, int epi)
{
    extern __shared__ __align__(16) uint8_t smem[];
    const uint32_t sbase = (uint32_t)__cvta_generic_to_shared(smem);

    const int tid  = threadIdx.x;
    const int lane = tid & 31, warp = tid >> 5;
    const int wm = warp & 1, wn = warp >> 1;
    const int row0 = blockIdx.y * 128, col0 = blockIdx.x * 128;

    const int r  = tid >> 1;
    const int cg = (tid & 1) * 2;

    const int NST = K / 32;

    float acc[4][4][4];
    #pragma unroll
    for (int i = 0; i < 4; i++)
        #pragma unroll
        for (int j = 0; j < 4; j++)
            #pragma unroll
            for (int q = 0; q < 4; q++) acc[i][j][q] = 0.0f;

    PREFETCH(0);
    PREFETCH(1);

    const int mbase = wm * 64, nbase = wn * 32;
    const int lr = lane & 15, lh = (lane >> 4) * 16;

    for (int s = 0; s < NST; s++) {
        if (s + 1 < NST) asm volatile("cp.async.wait_group 1;");
        else             asm volatile("cp.async.wait_group 0;");
        __syncthreads();

        const uint32_t bAh = sbase + (s & 1) * STG_SZ + STG_A_H;
        const uint32_t bAl = sbase + (s & 1) * STG_SZ + STG_A_L;
        const uint32_t bBh = sbase + (s & 1) * STG_SZ + STG_B_H;
        const uint32_t bBl = sbase + (s & 1) * STG_SZ + STG_B_L;

        #pragma unroll
        for (int kk = 0; kk < 2; kk++) {
            const uint32_t kb = (uint32_t)(kk * 32 + lh);
            uint32_t ah[4][4], al[4][4], bh[2][4], bl[2][4];
            #pragma unroll
            for (int mf = 0; mf < 4; mf++) {
                uint32_t ro = (uint32_t)(mbase + mf * 16 + lr) * 80 + kb;
                ldsm_x4(ah[mf][0], ah[mf][1], ah[mf][2], ah[mf][3], bAh + ro);
                ldsm_x4(al[mf][0], al[mf][1], al[mf][2], al[mf][3], bAl + ro);
            }
            #pragma unroll
            for (int np = 0; np < 2; np++) {
                uint32_t ro = (uint32_t)(nbase + np * 16 + lr) * 80 + kb;
                ldsm_x4(bh[np][0], bh[np][1], bh[np][2], bh[np][3], bBh + ro);
                ldsm_x4(bl[np][0], bl[np][1], bl[np][2], bl[np][3], bBl + ro);
            }
            #pragma unroll
            for (int mf = 0; mf < 4; mf++) {
                #pragma unroll
                for (int nf = 0; nf < 4; nf++) {
                    const int np = nf >> 1, half = nf & 1;
                    uint32_t b0h = bh[np][half], b1h = bh[np][2 + half];
                    uint32_t b0l = bl[np][half], b1l = bl[np][2 + half];
                    mma16816(acc[mf][nf], ah[mf], b0h, b1h);
                    mma16816(acc[mf][nf], ah[mf], b0l, b1l);
                    mma16816(acc[mf][nf], al[mf], b0h, b1h);
                }
            }
        }
        __syncthreads();
        if (s + 2 < NST) PREFETCH(s + 2);
    }

    #pragma unroll
    for (int mf = 0; mf < 4; mf++) {
        #pragma unroll
        for (int nf = 0; nf < 4; nf++) {
            int rr0 = row0 + mbase + mf * 16 + (lane >> 2);
            int cc0 = col0 + nbase + nf * 8 + (lane & 3) * 2;
            #pragma unroll
            for (int q = 0; q < 4; q++) {
                int row = rr0 + ((q >= 2) ? 8 : 0);
                int col = cc0 + (q & 1);
                float val = acc[mf][nf][q];
                if (epi == 0) {
                    C[(size_t)row * N + col] = val;
                } else {
                    int region = col >> 9;
                    int cr = col & 511;
                    int hh = cr >> 6, dd = cr & 63;
                    if (region == 0)      g_Q[((size_t)hh * S_LEN + row) * DH + dd] = val;
                    else if (region == 1) g_K[((size_t)hh * KL + row + NPM) * DH + dd] = val;
                    else                  g_V[((size_t)hh * KL + row + NPM) * DH + dd] = val;
                }
            }
        }
    }
}

// ---------------------------------------------------------------------------
// 4) RoPE apply + bf16 hi/lo emission for Q and K. One warp per row.
// ---------------------------------------------------------------------------
__global__ void rope_apply_kernel(const float* __restrict__ pm) {
    int gwarp = (blockIdx.x * blockDim.x + threadIdx.x) >> 5;
    int j = threadIdx.x & 31;
    const int KROWS = HEADS * KL;
    const int TOT   = KROWS + HEADS * S_LEN;
    if (gwarp >= TOT) return;

    if (gwarp < KROWS) {
        int h = gwarp / KL, t = gwarp % KL;
        const size_t base = ((size_t)h * KL + t) * DH + 2 * j;
        float x1, x2;
        if (t < NPM) {
            const float* pmk = pm + (((size_t)0 * HEADS + h) * NPM + t) * DH;
            const float* pmv = pm + (((size_t)1 * HEADS + h) * NPM + t) * DH;
            x1 = pmk[2 * j]; x2 = pmk[2 * j + 1];
            g_V[base]     = pmv[2 * j];
            g_V[base + 1] = pmv[2 * j + 1];
        } else {
            x1 = g_K[base]; x2 = g_K[base + 1];
        }
        float c = g_cos[t * 32 + j], sn = g_sin[t * 32 + j];
        float r1 = x1 * c - x2 * sn;
        float r2 = x2 * c + x1 * sn;
        uint32_t hi, lo;
        split2(r1, r2, hi, lo);
        *(uint32_t*)(g_Kh + base) = hi;
        *(uint32_t*)(g_Kl + base) = lo;
    } else {
        int rr = gwarp - KROWS;
        int h = rr / S_LEN, s = rr % S_LEN;
        int pos = s + NPM;
        const size_t base = ((size_t)h * S_LEN + s) * DH + 2 * j;
        float x1 = g_Q[base], x2 = g_Q[base + 1];
        float c = g_cos[pos * 32 + j], sn = g_sin[pos * 32 + j];
        float r1 = x1 * c - x2 * sn;
        float r2 = x2 * c + x1 * sn;
        uint32_t hi, lo;
        split2(r1, r2, hi, lo);
        *(uint32_t*)(g_Qh + base) = hi;
        *(uint32_t*)(g_Ql + base) = lo;
    }
}

// ---------------------------------------------------------------------------
// 4b) V transpose + split: g_V [h][t][d] -> g_Vth/g_Vtl [h][d][t]
// ---------------------------------------------------------------------------
__global__ void vtrans_kernel() {
    __shared__ float tile[32][33];
    int h  = blockIdx.z;
    int d0 = blockIdx.y * 32;
    int t0 = blockIdx.x * 32;
    for (int r = threadIdx.y; r < 32; r += 8) {
        int t = t0 + r;
        if (t < KL)
            tile[r][threadIdx.x] = g_V[((size_t)h * KL + t) * DH + d0 + threadIdx.x];
    }
    __syncthreads();
    for (int r = threadIdx.y; r < 32; r += 8) {
        int d = d0 + r;
        int t = t0 + threadIdx.x;
        if (t < KL) {
            float v = tile[threadIdx.x][r];
            uint32_t uv = __float_as_uint(v) & 0xFFFF0000u;
            g_Vth[((size_t)(h * DH + d)) * KL + t] =
                __ushort_as_bfloat16((unsigned short)(uv >> 16));
            g_Vtl[((size_t)(h * DH + d)) * KL + t] =
                __float2bfloat16(v - __uint_as_float(uv));
        }
    }
}

// ---------------------------------------------------------------------------
// 5) Tensor-core flash attention, cp.async double-buffered K/V tiles.
// Dynamic smem: Q hi/lo 16 KB + 2 stages x (Kh,Kl,Vh,Vl) x 8 KB = 81920 B.
// ---------------------------------------------------------------------------
#define SWADDR(base, row, ch) ((base) + (uint32_t)(row) * 128u + \
                               ((uint32_t)((ch) ^ ((row) & 7)) << 4))

// Prefetch K/V tile TT (64 keys, unconditionally; mem tile over-fetches
// harmlessly - extra keys are masked / multiplied by p=0).
#define ATT_KVPF(TT) do {                                                     \
    int _t0 = ((TT) == 0) ? 0 : (NPM + seg * SEGLEN + ((TT) - 1) * 64);       \
    uint32_t _buf = kvbase + (((TT) & 1) ? 32768u : 0u);                      \
    _Pragma("unroll")                                                         \
    for (int _k = 0; _k < 4; _k++) {                                          \
        int _i = tid + _k * 128;                                              \
        int _row = _i >> 3, _ch = _i & 7;                                     \
        uint32_t _d16 = (uint32_t)(_row * 8 + (_ch ^ (_row & 7))) * 16u;      \
        const __nv_bfloat16* _kh = g_Kh + ((size_t)h * KL + _t0 + _row) * DH + _ch * 8; \
        const __nv_bfloat16* _kl = g_Kl + ((size_t)h * KL + _t0 + _row) * DH + _ch * 8; \
        const __nv_bfloat16* _vh = g_Vth + ((size_t)(h * DH + _row)) * KL + _t0 + _ch * 8; \
        const __nv_bfloat16* _vl = g_Vtl + ((size_t)(h * DH + _row)) * KL + _t0 + _ch * 8; \
        CPA16(_buf + _d16,          _kh);                                     \
        CPA16(_buf + 8192u + _d16,  _kl);                                     \
        CPA16(_buf + 16384u + _d16, _vh);                                     \
        CPA16(_buf + 24576u + _d16, _vl);                                     \
    }                                                                         \
    asm volatile("cp.async.commit_group;");                                   \
} while (0)

__global__ __launch_bounds__(128) void attn_mma_kernel() {
    extern __shared__ __align__(16) uint8_t asmem[];
    const uint32_t sbase  = (uint32_t)__cvta_generic_to_shared(asmem);
    const uint32_t qb     = sbase;             // Qh [0,8K), Ql [8K,16K)
    const uint32_t kvbase = sbase + 16384u;

    const int qt = blockIdx.x, seg = blockIdx.y, h = blockIdx.z;
    const int tid = threadIdx.x;
    const int lane = tid & 31, w = tid >> 5;
    const int s0 = seg * SEGLEN + qt * 64;
    const int ntiles = qt + 2;                 // mem + (qt+1), >= 2

    ATT_KVPF(0);
    ATT_KVPF(1);

    // stage Q (overlapped with K/V prefetch)
    for (int i = tid; i < 512; i += 128) {
        int row = i >> 3, ch = i & 7;
        int d = row * 8 + (ch ^ (row & 7));
        ((uint4*)asmem)[d] =
            *((const uint4*)(g_Qh + ((size_t)h * S_LEN + s0 + row) * DH) + ch);
        ((uint4*)(asmem + 8192))[d] =
            *((const uint4*)(g_Ql + ((size_t)h * S_LEN + s0 + row) * DH) + ch);
    }
    __syncthreads();

    uint32_t qh[4][4], ql[4][4];
    {
        int row = w * 16 + (lane & 15);
        #pragma unroll
        for (int j = 0; j < 4; j++) {
            int ch = 2 * j + (lane >> 4);
            ldsm_x4(qh[j][0], qh[j][1], qh[j][2], qh[j][3], SWADDR(qb, row, ch));
            ldsm_x4(ql[j][0], ql[j][1], ql[j][2], ql[j][3], SWADDR(qb + 8192u, row, ch));
        }
    }

    float oacc[8][4];
    #pragma unroll
    for (int nf = 0; nf < 8; nf++)
        #pragma unroll
        for (int q = 0; q < 4; q++) oacc[nf][q] = 0.0f;
    float mrun[2] = {-INFINITY, -INFINITY};
    float lrun[2] = {0.0f, 0.0f};

    const float SC = 0.125f * 1.44269504088896341f;
    const int r1 = lane >> 2;
    const int cbase = (lane & 3) * 2;

    for (int tt = 0; tt < ntiles; tt++) {
        const bool ismem = (tt == 0);
        const bool diag = (!ismem) && ((tt - 1) == qt);

        if (tt + 1 < ntiles) asm volatile("cp.async.wait_group 1;");
        else                 asm volatile("cp.async.wait_group 0;");
        __syncthreads();

        const uint32_t kb0 = kvbase + ((tt & 1) ? 32768u : 0u);
        const uint32_t bKh = kb0, bKl = kb0 + 8192u;
        const uint32_t bVh = kb0 + 16384u, bVl = kb0 + 24576u;

        // ---- S = Q K^T (3-split) ----
        float sacc[8][4];
        #pragma unroll
        for (int nf = 0; nf < 8; nf++)
            #pragma unroll
            for (int q = 0; q < 4; q++) sacc[nf][q] = 0.0f;

        #pragma unroll
        for (int j = 0; j < 4; j++) {
            uint32_t kh[4][4], kl[4][4];
            int ch = 2 * j + (lane >> 4);
            #pragma unroll
            for (int ng = 0; ng < 4; ng++) {
                if (ismem && ng > 0) break;
                int row = ng * 16 + (lane & 15);
                ldsm_x4(kh[ng][0], kh[ng][1], kh[ng][2], kh[ng][3], SWADDR(bKh, row, ch));
                ldsm_x4(kl[ng][0], kl[ng][1], kl[ng][2], kl[ng][3], SWADDR(bKl, row, ch));
            }
            #pragma unroll
            for (int nf = 0; nf < 8; nf++) {
                if (ismem && nf >= 2) continue;
                const int ng = nf >> 1, sel = nf & 1;
                uint32_t b0h = kh[ng][sel], b1h = kh[ng][2 + sel];
                uint32_t b0l = kl[ng][sel], b1l = kl[ng][2 + sel];
                mma16816(sacc[nf], qh[j], b0h, b1h);
                mma16816(sacc[nf], qh[j], b0l, b1l);
                mma16816(sacc[nf], ql[j], b0h, b1h);
            }
        }

        // ---- scale + mask (exp2 domain) ----
        #pragma unroll
        for (int nf = 0; nf < 8; nf++) {
            #pragma unroll
            for (int q = 0; q < 4; q++) {
                int col = nf * 8 + cbase + (q & 1);
                int qrow = w * 16 + r1 + ((q >= 2) ? 8 : 0);
                float v = sacc[nf][q] * SC;
                bool bad = (ismem && col >= 16) || (diag && col > qrow);
                sacc[nf][q] = bad ? -INFINITY : v;
            }
        }

        // ---- row max ----
        float ml[2] = {-INFINITY, -INFINITY};
        #pragma unroll
        for (int nf = 0; nf < 8; nf++) {
            ml[0] = fmaxf(ml[0], fmaxf(sacc[nf][0], sacc[nf][1]));
            ml[1] = fmaxf(ml[1], fmaxf(sacc[nf][2], sacc[nf][3]));
        }
        #pragma unroll
        for (int o = 1; o <= 2; o <<= 1) {
            ml[0] = fmaxf(ml[0], __shfl_xor_sync(0xffffffffu, ml[0], o));
            ml[1] = fmaxf(ml[1], __shfl_xor_sync(0xffffffffu, ml[1], o));
        }
        float mnew0 = fmaxf(mrun[0], ml[0]);
        float mnew1 = fmaxf(mrun[1], ml[1]);
        float corr0 = ex2(mrun[0] - mnew0);     // mnew finite after mem tile
        float corr1 = ex2(mrun[1] - mnew1);
        mrun[0] = mnew0; mrun[1] = mnew1;

        // ---- p = exp2(s - m), row sums ----
        float ls[2] = {0.0f, 0.0f};
        #pragma unroll
        for (int nf = 0; nf < 8; nf++) {
            float p0 = ex2(sacc[nf][0] - mnew0);
            float p1 = ex2(sacc[nf][1] - mnew0);
            float p2 = ex2(sacc[nf][2] - mnew1);
            float p3 = ex2(sacc[nf][3] - mnew1);
            sacc[nf][0] = p0; sacc[nf][1] = p1; sacc[nf][2] = p2; sacc[nf][3] = p3;
            ls[0] += p0 + p1; ls[1] += p2 + p3;
        }
        #pragma unroll
        for (int o = 1; o <= 2; o <<= 1) {
            ls[0] += __shfl_xor_sync(0xffffffffu, ls[0], o);
            ls[1] += __shfl_xor_sync(0xffffffffu, ls[1], o);
        }
        lrun[0] = lrun[0] * corr0 + ls[0];
        lrun[1] = lrun[1] * corr1 + ls[1];

        #pragma unroll
        for (int nf = 0; nf < 8; nf++) {
            oacc[nf][0] *= corr0; oacc[nf][1] *= corr0;
            oacc[nf][2] *= corr1; oacc[nf][3] *= corr1;
        }

        // ---- O += P V^T (3-split) ----
        #pragma unroll
        for (int j = 0; j < 4; j++) {
            if (ismem && j > 0) break;
            uint32_t pa_h[4], pa_l[4];
            split2(sacc[2*j][0],   sacc[2*j][1],   pa_h[0], pa_l[0]);
            split2(sacc[2*j][2],   sacc[2*j][3],   pa_h[1], pa_l[1]);
            split2(sacc[2*j+1][0], sacc[2*j+1][1], pa_h[2], pa_l[2]);
            split2(sacc[2*j+1][2], sacc[2*j+1][3], pa_h[3], pa_l[3]);

            uint32_t vh[4][4], vl[4][4];
            int ch = 2 * j + (lane >> 4);
            #pragma unroll
            for (int dg = 0; dg < 4; dg++) {
                int row = dg * 16 + (lane & 15);
                ldsm_x4(vh[dg][0], vh[dg][1], vh[dg][2], vh[dg][3], SWADDR(bVh, row, ch));
                ldsm_x4(vl[dg][0], vl[dg][1], vl[dg][2], vl[dg][3], SWADDR(bVl, row, ch));
            }
            #pragma unroll
            for (int nf = 0; nf < 8; nf++) {
                const int dg = nf >> 1, sel = nf & 1;
                uint32_t b0h = vh[dg][sel], b1h = vh[dg][2 + sel];
                uint32_t b0l = vl[dg][sel], b1l = vl[dg][2 + sel];
                mma16816(oacc[nf], pa_h, b0h, b1h);
                mma16816(oacc[nf], pa_h, b0l, b1l);
                mma16816(oacc[nf], pa_l, b0h, b1h);
            }
        }

        __syncthreads();
        if (tt + 2 < ntiles) ATT_KVPF(tt + 2);
    }

    float inv0 = 1.0f / lrun[0];
    float inv1 = 1.0f / lrun[1];
    int qrow = s0 + w * 16 + r1;
    #pragma unroll
    for (int nf = 0; nf < 8; nf++) {
        int col = h * DH + nf * 8 + cbase;
        uint32_t h0, l0, h1, l1;
        split2(oacc[nf][0] * inv0, oacc[nf][1] * inv0, h0, l0);
        split2(oacc[nf][2] * inv1, oacc[nf][3] * inv1, h1, l1);
        *(uint32_t*)(g_Ah + (size_t)qrow * DIM + col)       = h0;
        *(uint32_t*)(g_Al + (size_t)qrow * DIM + col)       = l0;
        *(uint32_t*)(g_Ah + (size_t)(qrow + 8) * DIM + col) = h1;
        *(uint32_t*)(g_Al + (size_t)(qrow + 8) * DIM + col) = l1;
    }
}

// ---------------------------------------------------------------------------
// Launch
// ---------------------------------------------------------------------------
extern "C" void kernel_launch(void* const* d_in, const int* in_sizes, int n_in,
                              void* d_out, int out_size) {
    const float* seq    = (const float*)d_in[0];
    const float* norm_w = (const float*)d_in[1];
    const float* w_qkv  = (const float*)d_in[2];
    const float* w_out  = (const float*)d_in[3];
    const float* pm     = (const float*)d_in[4];

    __nv_bfloat16 *xh, *xl, *wqh, *wql, *woh, *wol, *ah, *al;
    cudaGetSymbolAddress((void**)&xh,  g_Xh);
    cudaGetSymbolAddress((void**)&xl,  g_Xl);
    cudaGetSymbolAddress((void**)&wqh, g_WqkvTh);
    cudaGetSymbolAddress((void**)&wql, g_WqkvTl);
    cudaGetSymbolAddress((void**)&woh, g_WoutTh);
    cudaGetSymbolAddress((void**)&wol, g_WoutTl);
    cudaGetSymbolAddress((void**)&ah,  g_Ah);
    cudaGetSymbolAddress((void**)&al,  g_Al);

    cudaFuncSetAttribute(mm2_kernel,
                         cudaFuncAttributeMaxDynamicSharedMemorySize, 81920);
    cudaFuncSetAttribute(attn_mma_kernel,
                         cudaFuncAttributeMaxDynamicSharedMemorySize, 81920);

    rope_table_kernel<<<(KL * 32 + 127) / 128, 128>>>();
    convert_x_kernel<<<S_LEN, 128>>>(seq, norm_w);
    wtrans_kernel<<<dim3(QKV_N / 32, DIM / 32), dim3(32, 8)>>>(w_qkv, wqh, wql, DIM, QKV_N);
    wtrans_kernel<<<dim3(DIM / 32, DIM / 32), dim3(32, 8)>>>(w_out, woh, wol, DIM, DIM);

    mm2_kernel<<<dim3(QKV_N / 128, S_LEN / 128), 256, 81920>>>(
        xh, xl, wqh, wql, nullptr, QKV_N, DIM, 1);

    {
        const int TOTW = HEADS * KL + HEADS * S_LEN;
        int threads = TOTW * 32;
        rope_apply_kernel<<<(threads + 127) / 128, 128>>>(pm);
    }

    vtrans_kernel<<<dim3((KL + 31) / 32, DH / 32, HEADS), dim3(32, 8)>>>();

    attn_mma_kernel<<<dim3(8, 8, 8), 128, 81920>>>();

    mm2_kernel<<<dim3(DIM / 128, S_LEN / 128), 256, 81920>>>(
        ah, al, woh, wol, (float*)d_out, DIM, DIM, 0);
}

// round 10
// speedup vs baseline: 2.4390x; 1.0594x over previous
#include <cuda_runtime.h>
#include <cuda_bf16.h>
#include <cstdint>
#include <math.h>

// ---------------------------------------------------------------------------
// Problem constants
// ---------------------------------------------------------------------------
#define S_LEN 4096
#define DIM   512
#define HEADS 8
#define DH    64
#define NPM   16
#define SEGLEN 512
#define KL    (S_LEN + NPM)        // 4112 keys after memory prepend
#define QKV_N (3 * HEADS * DH)     // 1536

// ---------------------------------------------------------------------------
// Scratch (device globals: no allocation allowed)
// ---------------------------------------------------------------------------
__device__ float g_Q[HEADS * S_LEN * DH];     // fp32 [h][s][d] (pre-rope)
__device__ float g_K[HEADS * KL * DH];        // fp32 [h][t][d] (pre-rope, t>=16)
__device__ float g_V[HEADS * KL * DH];        // fp32 [h][t][d]
__device__ float g_cos[KL * 32];
__device__ float g_sin[KL * 32];
// pre-split bf16 operands
__device__ __align__(16) __nv_bfloat16 g_Xh[S_LEN * DIM];      // normed input
__device__ __align__(16) __nv_bfloat16 g_Xl[S_LEN * DIM];
__device__ __align__(16) __nv_bfloat16 g_WqkvTh[QKV_N * DIM];  // [n][k]
__device__ __align__(16) __nv_bfloat16 g_WqkvTl[QKV_N * DIM];
__device__ __align__(16) __nv_bfloat16 g_WoutTh[DIM * DIM];    // [n][k]
__device__ __align__(16) __nv_bfloat16 g_WoutTl[DIM * DIM];
__device__ __align__(16) __nv_bfloat16 g_Ah[S_LEN * DIM];      // attention out
__device__ __align__(16) __nv_bfloat16 g_Al[S_LEN * DIM];
// attention operands
__device__ __align__(16) __nv_bfloat16 g_Qh[HEADS * S_LEN * DH];
__device__ __align__(16) __nv_bfloat16 g_Ql[HEADS * S_LEN * DH];
__device__ __align__(16) __nv_bfloat16 g_Kh[HEADS * KL * DH];
__device__ __align__(16) __nv_bfloat16 g_Kl[HEADS * KL * DH];
__device__ __align__(16) __nv_bfloat16 g_Vth[HEADS * DH * KL]; // [h][d][t]
__device__ __align__(16) __nv_bfloat16 g_Vtl[HEADS * DH * KL];

// ---------------------------------------------------------------------------
// helpers
// ---------------------------------------------------------------------------
// Truncation split of a float pair into bf16x2 hi (top 16 bits) and lo
// (residual, round-to-nearest).
__device__ __forceinline__ void split2(float a0, float a1,
                                       uint32_t& hi, uint32_t& lo) {
    uint32_t u0 = __float_as_uint(a0), u1 = __float_as_uint(a1);
    asm("prmt.b32 %0, %1, %2, 0x7632;" : "=r"(hi) : "r"(u0), "r"(u1));
    float r0 = a0 - __uint_as_float(u0 & 0xFFFF0000u);
    float r1 = a1 - __uint_as_float(u1 & 0xFFFF0000u);
    asm("cvt.rn.bf16x2.f32 %0, %1, %2;" : "=r"(lo) : "f"(r1), "f"(r0));
}

__device__ __forceinline__ float ex2(float x) {
    float r; asm("ex2.approx.f32 %0, %1;" : "=f"(r) : "f"(x)); return r;
}

__device__ __forceinline__ void ldsm_x4(uint32_t& r0, uint32_t& r1,
                                        uint32_t& r2, uint32_t& r3, uint32_t addr) {
    asm volatile("ldmatrix.sync.aligned.m8n8.x4.shared.b16 {%0,%1,%2,%3}, [%4];"
                 : "=r"(r0), "=r"(r1), "=r"(r2), "=r"(r3) : "r"(addr));
}

__device__ __forceinline__ void mma16816(float* c, const uint32_t* a,
                                         uint32_t b0, uint32_t b1) {
    asm volatile(
        "mma.sync.aligned.m16n8k16.row.col.f32.bf16.bf16.f32 "
        "{%0,%1,%2,%3}, {%4,%5,%6,%7}, {%8,%9}, {%0,%1,%2,%3};"
        : "+f"(c[0]), "+f"(c[1]), "+f"(c[2]), "+f"(c[3])
        : "r"(a[0]), "r"(a[1]), "r"(a[2]), "r"(a[3]), "r"(b0), "r"(b1));
}

#define CPA16(dst, src) \
    asm volatile("cp.async.cg.shared.global [%0], [%1], 16;" \
                 :: "r"(dst), "l"(src))

// ---------------------------------------------------------------------------
// 1) RoPE tables
// ---------------------------------------------------------------------------
__global__ void rope_table_kernel() {
    int idx = blockIdx.x * blockDim.x + threadIdx.x;
    if (idx >= KL * 32) return;
    int pos = idx >> 5, j = idx & 31;
    float rf  = (float)pow(10000.0, -(double)j / 32.0);
    float ang = (float)pos * rf;
    g_cos[idx] = (float)cos((double)ang);
    g_sin[idx] = (float)sin((double)ang);
}

// ---------------------------------------------------------------------------
// 2) RMSNorm + convert X to bf16 hi/lo in one pass.
// ---------------------------------------------------------------------------
__global__ void convert_x_kernel(const float* __restrict__ seq,
                                 const float* __restrict__ norm_w) {
    int s = blockIdx.x;
    int tid = threadIdx.x;                       // 128
    float4 v = ((const float4*)(seq + (size_t)s * DIM))[tid];
    float p = v.x * v.x + v.y * v.y + v.z * v.z + v.w * v.w;
    #pragma unroll
    for (int o = 16; o; o >>= 1) p += __shfl_xor_sync(0xffffffffu, p, o);
    __shared__ float ws[4];
    if ((tid & 31) == 0) ws[tid >> 5] = p;
    __syncthreads();
    float rs = rsqrtf((ws[0] + ws[1] + ws[2] + ws[3]) * (1.0f / (float)DIM)
                      + 1.1920928955078125e-07f);
    float4 w = ((const float4*)norm_w)[tid];
    v.x *= rs * w.x; v.y *= rs * w.y; v.z *= rs * w.z; v.w *= rs * w.w;
    uint32_t h0, l0, h1, l1;
    split2(v.x, v.y, h0, l0);
    split2(v.z, v.w, h1, l1);
    ((uint2*)(g_Xh + (size_t)s * DIM))[tid] = make_uint2(h0, h1);
    ((uint2*)(g_Xl + (size_t)s * DIM))[tid] = make_uint2(l0, l1);
}

// ---------------------------------------------------------------------------
// 2c) Transpose+split weights: src [K][N] fp32 -> dstT hi/lo [N][K] bf16.
// ---------------------------------------------------------------------------
__global__ void wtrans_kernel(const float* __restrict__ src,
                              __nv_bfloat16* __restrict__ dh,
                              __nv_bfloat16* __restrict__ dl, int K, int N) {
    __shared__ float tile[32][33];
    int n0 = blockIdx.x * 32, k0 = blockIdx.y * 32;
    for (int r = threadIdx.y; r < 32; r += 8)
        tile[r][threadIdx.x] = src[(size_t)(k0 + r) * N + n0 + threadIdx.x];
    __syncthreads();
    for (int r = threadIdx.y; r < 32; r += 8) {
        int n = n0 + r, k = k0 + threadIdx.x;
        float v = tile[threadIdx.x][r];
        uint32_t uv = __float_as_uint(v) & 0xFFFF0000u;
        dh[(size_t)n * K + k] = __ushort_as_bfloat16((unsigned short)(uv >> 16));
        dl[(size_t)n * K + k] = __float2bfloat16(v - __uint_as_float(uv));
    }
}

// ---------------------------------------------------------------------------
// 3) bf16 split GEMM, pre-converted inputs, cp.async double-buffered.
//    (verified round 9, unchanged)
// ---------------------------------------------------------------------------
#define STG_A_H 0
#define STG_A_L 10240
#define STG_B_H 20480
#define STG_B_L 30720
#define STG_SZ  40960

#define PREFETCH(S) do {                                                      \
    int _k0 = (S) * 32;                                                       \
    uint32_t _b = sbase + ((S) & 1) * STG_SZ + r * 80 + cg * 16;              \
    const __nv_bfloat16* _ag = Ah + (size_t)(row0 + r) * K + _k0 + cg * 8;    \
    const __nv_bfloat16* _al = Al + (size_t)(row0 + r) * K + _k0 + cg * 8;    \
    const __nv_bfloat16* _bg = Bh + (size_t)(col0 + r) * K + _k0 + cg * 8;    \
    const __nv_bfloat16* _bl = Bl + (size_t)(col0 + r) * K + _k0 + cg * 8;    \
    CPA16(_b + STG_A_H,      _ag);                                            \
    CPA16(_b + STG_A_H + 16, _ag + 8);                                        \
    CPA16(_b + STG_A_L,      _al);                                            \
    CPA16(_b + STG_A_L + 16, _al + 8);                                        \
    CPA16(_b + STG_B_H,      _bg);                                            \
    CPA16(_b + STG_B_H + 16, _bg + 8);                                        \
    CPA16(_b + STG_B_L,      _bl);                                            \
    CPA16(_b + STG_B_L + 16, _bl + 8);                                        \
    asm volatile("cp.async.commit_group;");                                   \
} while (0)

__global__ __launch_bounds__(256) void mm2_kernel(
    const __nv_bfloat16* __restrict__ Ah, const __nv_bfloat16* __restrict__ Al,
    const __nv_bfloat16* __restrict__ Bh, const __nv_bfloat16* __restrict__ Bl,
    float* __restrict__ C, int N, int K, int epi)
{
    extern __shared__ __align__(16) uint8_t smem[];
    const uint32_t sbase = (uint32_t)__cvta_generic_to_shared(smem);

    const int tid  = threadIdx.x;
    const int lane = tid & 31, warp = tid >> 5;
    const int wm = warp & 1, wn = warp >> 1;
    const int row0 = blockIdx.y * 128, col0 = blockIdx.x * 128;

    const int r  = tid >> 1;
    const int cg = (tid & 1) * 2;

    const int NST = K / 32;

    float acc[4][4][4];
    #pragma unroll
    for (int i = 0; i < 4; i++)
        #pragma unroll
        for (int j = 0; j < 4; j++)
            #pragma unroll
            for (int q = 0; q < 4; q++) acc[i][j][q] = 0.0f;

    PREFETCH(0);
    PREFETCH(1);

    const int mbase = wm * 64, nbase = wn * 32;
    const int lr = lane & 15, lh = (lane >> 4) * 16;

    for (int s = 0; s < NST; s++) {
        if (s + 1 < NST) asm volatile("cp.async.wait_group 1;");
        else             asm volatile("cp.async.wait_group 0;");
        __syncthreads();

        const uint32_t bAh = sbase + (s & 1) * STG_SZ + STG_A_H;
        const uint32_t bAl = sbase + (s & 1) * STG_SZ + STG_A_L;
        const uint32_t bBh = sbase + (s & 1) * STG_SZ + STG_B_H;
        const uint32_t bBl = sbase + (s & 1) * STG_SZ + STG_B_L;

        #pragma unroll
        for (int kk = 0; kk < 2; kk++) {
            const uint32_t kb = (uint32_t)(kk * 32 + lh);
            uint32_t ah[4][4], al[4][4], bh[2][4], bl[2][4];
            #pragma unroll
            for (int mf = 0; mf < 4; mf++) {
                uint32_t ro = (uint32_t)(mbase + mf * 16 + lr) * 80 + kb;
                ldsm_x4(ah[mf][0], ah[mf][1], ah[mf][2], ah[mf][3], bAh + ro);
                ldsm_x4(al[mf][0], al[mf][1], al[mf][2], al[mf][3], bAl + ro);
            }
            #pragma unroll
            for (int np = 0; np < 2; np++) {
                uint32_t ro = (uint32_t)(nbase + np * 16 + lr) * 80 + kb;
                ldsm_x4(bh[np][0], bh[np][1], bh[np][2], bh[np][3], bBh + ro);
                ldsm_x4(bl[np][0], bl[np][1], bl[np][2], bl[np][3], bBl + ro);
            }
            #pragma unroll
            for (int mf = 0; mf < 4; mf++) {
                #pragma unroll
                for (int nf = 0; nf < 4; nf++) {
                    const int np = nf >> 1, half = nf & 1;
                    uint32_t b0h = bh[np][half], b1h = bh[np][2 + half];
                    uint32_t b0l = bl[np][half], b1l = bl[np][2 + half];
                    mma16816(acc[mf][nf], ah[mf], b0h, b1h);
                    mma16816(acc[mf][nf], ah[mf], b0l, b1l);
                    mma16816(acc[mf][nf], al[mf], b0h, b1h);
                }
            }
        }
        __syncthreads();
        if (s + 2 < NST) PREFETCH(s + 2);
    }

    #pragma unroll
    for (int mf = 0; mf < 4; mf++) {
        #pragma unroll
        for (int nf = 0; nf < 4; nf++) {
            int rr0 = row0 + mbase + mf * 16 + (lane >> 2);
            int cc0 = col0 + nbase + nf * 8 + (lane & 3) * 2;
            #pragma unroll
            for (int q = 0; q < 4; q++) {
                int row = rr0 + ((q >= 2) ? 8 : 0);
                int col = cc0 + (q & 1);
                float val = acc[mf][nf][q];
                if (epi == 0) {
                    C[(size_t)row * N + col] = val;
                } else {
                    int region = col >> 9;
                    int cr = col & 511;
                    int hh = cr >> 6, dd = cr & 63;
                    if (region == 0)      g_Q[((size_t)hh * S_LEN + row) * DH + dd] = val;
                    else if (region == 1) g_K[((size_t)hh * KL + row + NPM) * DH + dd] = val;
                    else                  g_V[((size_t)hh * KL + row + NPM) * DH + dd] = val;
                }
            }
        }
    }
}

// ---------------------------------------------------------------------------
// 4) RoPE apply + bf16 hi/lo emission. 16 threads per row (float4 / uint2).
// ---------------------------------------------------------------------------
__global__ void rope_apply_kernel(const float* __restrict__ pm) {
    int gid = blockIdx.x * blockDim.x + threadIdx.x;
    int row = gid >> 4;                 // 16 threads per 64-elem row
    int u   = gid & 15;                 // covers elements 4u..4u+3 (pairs 2u,2u+1)
    const int KROWS = HEADS * KL;
    const int TOT   = KROWS + HEADS * S_LEN;
    if (row >= TOT) return;

    float4 x;
    size_t base;
    int pos;
    __nv_bfloat16 *dsth, *dstl;

    if (row < KROWS) {
        int h = row / KL, t = row % KL;
        pos = t;
        base = ((size_t)h * KL + t) * DH + 4 * u;
        if (t < NPM) {
            x = *(const float4*)(pm + (((size_t)0 * HEADS + h) * NPM + t) * DH + 4 * u);
            float4 vv = *(const float4*)(pm + (((size_t)1 * HEADS + h) * NPM + t) * DH + 4 * u);
            *(float4*)(g_V + base) = vv;
        } else {
            x = *(const float4*)(g_K + base);
        }
        dsth = g_Kh; dstl = g_Kl;
    } else {
        int rr = row - KROWS;
        int h = rr / S_LEN, s = rr % S_LEN;
        pos = s + NPM;
        base = ((size_t)h * S_LEN + s) * DH + 4 * u;
        x = *(const float4*)(g_Q + base);
        dsth = g_Qh; dstl = g_Ql;
    }

    float c0 = g_cos[pos * 32 + 2 * u],     s0 = g_sin[pos * 32 + 2 * u];
    float c1 = g_cos[pos * 32 + 2 * u + 1], s1 = g_sin[pos * 32 + 2 * u + 1];
    float r0 = x.x * c0 - x.y * s0;
    float r1 = x.y * c0 + x.x * s0;
    float r2 = x.z * c1 - x.w * s1;
    float r3 = x.w * c1 + x.z * s1;
    uint32_t h0, l0, h1, l1;
    split2(r0, r1, h0, l0);
    split2(r2, r3, h1, l1);
    *(uint2*)(dsth + base) = make_uint2(h0, h1);
    *(uint2*)(dstl + base) = make_uint2(l0, l1);
}

// ---------------------------------------------------------------------------
// 4b) V transpose + split: g_V [h][t][d] -> g_Vth/g_Vtl [h][d][t]
// ---------------------------------------------------------------------------
__global__ void vtrans_kernel() {
    __shared__ float tile[32][33];
    int h  = blockIdx.z;
    int d0 = blockIdx.y * 32;
    int t0 = blockIdx.x * 32;
    for (int r = threadIdx.y; r < 32; r += 8) {
        int t = t0 + r;
        if (t < KL)
            tile[r][threadIdx.x] = g_V[((size_t)h * KL + t) * DH + d0 + threadIdx.x];
    }
    __syncthreads();
    for (int r = threadIdx.y; r < 32; r += 8) {
        int d = d0 + r;
        int t = t0 + threadIdx.x;
        if (t < KL) {
            float v = tile[threadIdx.x][r];
            uint32_t uv = __float_as_uint(v) & 0xFFFF0000u;
            g_Vth[((size_t)(h * DH + d)) * KL + t] =
                __ushort_as_bfloat16((unsigned short)(uv >> 16));
            g_Vtl[((size_t)(h * DH + d)) * KL + t] =
                __float2bfloat16(v - __uint_as_float(uv));
        }
    }
}

// ---------------------------------------------------------------------------
// 5) Tensor-core flash attention. 64 KB smem (Q staged inside KV buf 1
//    before tile-1 prefetch) -> 3 blocks/SM. Heavy-qt-first scheduling.
// ---------------------------------------------------------------------------
#define SWADDR(base, row, ch) ((base) + (uint32_t)(row) * 128u + \
                               ((uint32_t)((ch) ^ ((row) & 7)) << 4))

#define ATT_KVPF(TT) do {                                                     \
    int _t0 = ((TT) == 0) ? 0 : (NPM + seg * SEGLEN + ((TT) - 1) * 64);       \
    uint32_t _buf = sbase + (((TT) & 1) ? 32768u : 0u);                       \
    _Pragma("unroll")                                                         \
    for (int _k = 0; _k < 4; _k++) {                                          \
        int _i = tid + _k * 128;                                              \
        int _row = _i >> 3, _ch = _i & 7;                                     \
        uint32_t _d16 = (uint32_t)(_row * 8 + (_ch ^ (_row & 7))) * 16u;      \
        const __nv_bfloat16* _kh = g_Kh + ((size_t)h * KL + _t0 + _row) * DH + _ch * 8; \
        const __nv_bfloat16* _kl = g_Kl + ((size_t)h * KL + _t0 + _row) * DH + _ch * 8; \
        const __nv_bfloat16* _vh = g_Vth + ((size_t)(h * DH + _row)) * KL + _t0 + _ch * 8; \
        const __nv_bfloat16* _vl = g_Vtl + ((size_t)(h * DH + _row)) * KL + _t0 + _ch * 8; \
        CPA16(_buf + _d16,          _kh);                                     \
        CPA16(_buf + 8192u + _d16,  _kl);                                     \
        CPA16(_buf + 16384u + _d16, _vh);                                     \
        CPA16(_buf + 24576u + _d16, _vl);                                     \
    }                                                                         \
    asm volatile("cp.async.commit_group;");                                   \
} while (0)

__global__ __launch_bounds__(128) void attn_mma_kernel() {
    extern __shared__ __align__(16) uint8_t asmem[];
    const uint32_t sbase = (uint32_t)__cvta_generic_to_shared(asmem);

    const int qt = 7 - blockIdx.x;             // heavy blocks first
    const int seg = blockIdx.y, h = blockIdx.z;
    const int tid = threadIdx.x;
    const int lane = tid & 31, w = tid >> 5;
    const int s0 = seg * SEGLEN + qt * 64;
    const int ntiles = qt + 2;                 // mem + (qt+1), >= 2

    // prefetch tile 0 into buf0
    ATT_KVPF(0);

    // stage Q into buf1 region (free until tile-1 prefetch below)
    const uint32_t qb = sbase + 32768u;        // Qh [0,8K), Ql [8K,16K) of buf1
    for (int i = tid; i < 512; i += 128) {
        int row = i >> 3, ch = i & 7;
        int d = row * 8 + (ch ^ (row & 7));
        ((uint4*)(asmem + 32768))[d] =
            *((const uint4*)(g_Qh + ((size_t)h * S_LEN + s0 + row) * DH) + ch);
        ((uint4*)(asmem + 40960))[d] =
            *((const uint4*)(g_Ql + ((size_t)h * S_LEN + s0 + row) * DH) + ch);
    }
    __syncthreads();

    uint32_t qh[4][4], ql[4][4];
    {
        int row = w * 16 + (lane & 15);
        #pragma unroll
        for (int j = 0; j < 4; j++) {
            int ch = 2 * j + (lane >> 4);
            ldsm_x4(qh[j][0], qh[j][1], qh[j][2], qh[j][3], SWADDR(qb, row, ch));
            ldsm_x4(ql[j][0], ql[j][1], ql[j][2], ql[j][3], SWADDR(qb + 8192u, row, ch));
        }
    }
    __syncthreads();                           // all Q reads done before buf1 refill

    ATT_KVPF(1);                               // tile 1 into buf1

    float oacc[8][4];
    #pragma unroll
    for (int nf = 0; nf < 8; nf++)
        #pragma unroll
        for (int q = 0; q < 4; q++) oacc[nf][q] = 0.0f;
    float mrun[2] = {-INFINITY, -INFINITY};
    float lrun[2] = {0.0f, 0.0f};

    const float SC = 0.125f * 1.44269504088896341f;
    const int r1 = lane >> 2;
    const int cbase = (lane & 3) * 2;

    for (int tt = 0; tt < ntiles; tt++) {
        const bool ismem = (tt == 0);
        const bool diag = (!ismem) && ((tt - 1) == qt);

        if (tt + 1 < ntiles) asm volatile("cp.async.wait_group 1;");
        else                 asm volatile("cp.async.wait_group 0;");
        __syncthreads();

        const uint32_t kb0 = sbase + ((tt & 1) ? 32768u : 0u);
        const uint32_t bKh = kb0, bKl = kb0 + 8192u;
        const uint32_t bVh = kb0 + 16384u, bVl = kb0 + 24576u;

        // ---- S = Q K^T (3-split) ----
        float sacc[8][4];
        #pragma unroll
        for (int nf = 0; nf < 8; nf++)
            #pragma unroll
            for (int q = 0; q < 4; q++) sacc[nf][q] = 0.0f;

        #pragma unroll
        for (int j = 0; j < 4; j++) {
            uint32_t kh[4][4], kl[4][4];
            int ch = 2 * j + (lane >> 4);
            #pragma unroll
            for (int ng = 0; ng < 4; ng++) {
                if (ismem && ng > 0) break;
                int row = ng * 16 + (lane & 15);
                ldsm_x4(kh[ng][0], kh[ng][1], kh[ng][2], kh[ng][3], SWADDR(bKh, row, ch));
                ldsm_x4(kl[ng][0], kl[ng][1], kl[ng][2], kl[ng][3], SWADDR(bKl, row, ch));
            }
            #pragma unroll
            for (int nf = 0; nf < 8; nf++) {
                if (ismem && nf >= 2) continue;
                const int ng = nf >> 1, sel = nf & 1;
                uint32_t b0h = kh[ng][sel], b1h = kh[ng][2 + sel];
                uint32_t b0l = kl[ng][sel], b1l = kl[ng][2 + sel];
                mma16816(sacc[nf], qh[j], b0h, b1h);
                mma16816(sacc[nf], qh[j], b0l, b1l);
                mma16816(sacc[nf], ql[j], b0h, b1h);
            }
        }

        // ---- scale + mask (exp2 domain) ----
        #pragma unroll
        for (int nf = 0; nf < 8; nf++) {
            #pragma unroll
            for (int q = 0; q < 4; q++) {
                int col = nf * 8 + cbase + (q & 1);
                int qrow = w * 16 + r1 + ((q >= 2) ? 8 : 0);
                float v = sacc[nf][q] * SC;
                bool bad = (ismem && col >= 16) || (diag && col > qrow);
                sacc[nf][q] = bad ? -INFINITY : v;
            }
        }

        // ---- row max ----
        float ml[2] = {-INFINITY, -INFINITY};
        #pragma unroll
        for (int nf = 0; nf < 8; nf++) {
            ml[0] = fmaxf(ml[0], fmaxf(sacc[nf][0], sacc[nf][1]));
            ml[1] = fmaxf(ml[1], fmaxf(sacc[nf][2], sacc[nf][3]));
        }
        #pragma unroll
        for (int o = 1; o <= 2; o <<= 1) {
            ml[0] = fmaxf(ml[0], __shfl_xor_sync(0xffffffffu, ml[0], o));
            ml[1] = fmaxf(ml[1], __shfl_xor_sync(0xffffffffu, ml[1], o));
        }
        float mnew0 = fmaxf(mrun[0], ml[0]);
        float mnew1 = fmaxf(mrun[1], ml[1]);
        float corr0 = ex2(mrun[0] - mnew0);     // mnew finite after mem tile
        float corr1 = ex2(mrun[1] - mnew1);
        mrun[0] = mnew0; mrun[1] = mnew1;

        // ---- p = exp2(s - m), row sums ----
        float ls[2] = {0.0f, 0.0f};
        #pragma unroll
        for (int nf = 0; nf < 8; nf++) {
            float p0 = ex2(sacc[nf][0] - mnew0);
            float p1 = ex2(sacc[nf][1] - mnew0);
            float p2 = ex2(sacc[nf][2] - mnew1);
            float p3 = ex2(sacc[nf][3] - mnew1);
            sacc[nf][0] = p0; sacc[nf][1] = p1; sacc[nf][2] = p2; sacc[nf][3] = p3;
            ls[0] += p0 + p1; ls[1] += p2 + p3;
        }
        #pragma unroll
        for (int o = 1; o <= 2; o <<= 1) {
            ls[0] += __shfl_xor_sync(0xffffffffu, ls[0], o);
            ls[1] += __shfl_xor_sync(0xffffffffu, ls[1], o);
        }
        lrun[0] = lrun[0] * corr0 + ls[0];
        lrun[1] = lrun[1] * corr1 + ls[1];

        #pragma unroll
        for (int nf = 0; nf < 8; nf++) {
            oacc[nf][0] *= corr0; oacc[nf][1] *= corr0;
            oacc[nf][2] *= corr1; oacc[nf][3] *= corr1;
        }

        // ---- O += P V^T (3-split) ----
        #pragma unroll
        for (int j = 0; j < 4; j++) {
            if (ismem && j > 0) break;
            uint32_t pa_h[4], pa_l[4];
            split2(sacc[2*j][0],   sacc[2*j][1],   pa_h[0], pa_l[0]);
            split2(sacc[2*j][2],   sacc[2*j][3],   pa_h[1], pa_l[1]);
            split2(sacc[2*j+1][0], sacc[2*j+1][1], pa_h[2], pa_l[2]);
            split2(sacc[2*j+1][2], sacc[2*j+1][3], pa_h[3], pa_l[3]);

            uint32_t vh[4][4], vl[4][4];
            int ch = 2 * j + (lane >> 4);
            #pragma unroll
            for (int dg = 0; dg < 4; dg++) {
                int row = dg * 16 + (lane & 15);
                ldsm_x4(vh[dg][0], vh[dg][1], vh[dg][2], vh[dg][3], SWADDR(bVh, row, ch));
                ldsm_x4(vl[dg][0], vl[dg][1], vl[dg][2], vl[dg][3], SWADDR(bVl, row, ch));
            }
            #pragma unroll
            for (int nf = 0; nf < 8; nf++) {
                const int dg = nf >> 1, sel = nf & 1;
                uint32_t b0h = vh[dg][sel], b1h = vh[dg][2 + sel];
                uint32_t b0l = vl[dg][sel], b1l = vl[dg][2 + sel];
                mma16816(oacc[nf], pa_h, b0h, b1h);
                mma16816(oacc[nf], pa_h, b0l, b1l);
                mma16816(oacc[nf], pa_l, b0h, b1h);
            }
        }

        __syncthreads();
        if (tt + 2 < ntiles) ATT_KVPF(tt + 2);
    }

    float inv0 = 1.0f / lrun[0];
    float inv1 = 1.0f / lrun[1];
    int qrow = s0 + w * 16 + r1;
    #pragma unroll
    for (int nf = 0; nf < 8; nf++) {
        int col = h * DH + nf * 8 + cbase;
        uint32_t h0, l0, h1, l1;
        split2(oacc[nf][0] * inv0, oacc[nf][1] * inv0, h0, l0);
        split2(oacc[nf][2] * inv1, oacc[nf][3] * inv1, h1, l1);
        *(uint32_t*)(g_Ah + (size_t)qrow * DIM + col)       = h0;
        *(uint32_t*)(g_Al + (size_t)qrow * DIM + col)       = l0;
        *(uint32_t*)(g_Ah + (size_t)(qrow + 8) * DIM + col) = h1;
        *(uint32_t*)(g_Al + (size_t)(qrow + 8) * DIM + col) = l1;
    }
}

// ---------------------------------------------------------------------------
// Launch
// ---------------------------------------------------------------------------
extern "C" void kernel_launch(void* const* d_in, const int* in_sizes, int n_in,
                              void* d_out, int out_size) {
    const float* seq    = (const float*)d_in[0];
    const float* norm_w = (const float*)d_in[1];
    const float* w_qkv  = (const float*)d_in[2];
    const float* w_out  = (const float*)d_in[3];
    const float* pm     = (const float*)d_in[4];

    __nv_bfloat16 *xh, *xl, *wqh, *wql, *woh, *wol, *ah, *al;
    cudaGetSymbolAddress((void**)&xh,  g_Xh);
    cudaGetSymbolAddress((void**)&xl,  g_Xl);
    cudaGetSymbolAddress((void**)&wqh, g_WqkvTh);
    cudaGetSymbolAddress((void**)&wql, g_WqkvTl);
    cudaGetSymbolAddress((void**)&woh, g_WoutTh);
    cudaGetSymbolAddress((void**)&wol, g_WoutTl);
    cudaGetSymbolAddress((void**)&ah,  g_Ah);
    cudaGetSymbolAddress((void**)&al,  g_Al);

    cudaFuncSetAttribute(mm2_kernel,
                         cudaFuncAttributeMaxDynamicSharedMemorySize, 81920);
    cudaFuncSetAttribute(attn_mma_kernel,
                         cudaFuncAttributeMaxDynamicSharedMemorySize, 65536);

    rope_table_kernel<<<(KL * 32 + 127) / 128, 128>>>();
    convert_x_kernel<<<S_LEN, 128>>>(seq, norm_w);
    wtrans_kernel<<<dim3(QKV_N / 32, DIM / 32), dim3(32, 8)>>>(w_qkv, wqh, wql, DIM, QKV_N);
    wtrans_kernel<<<dim3(DIM / 32, DIM / 32), dim3(32, 8)>>>(w_out, woh, wol, DIM, DIM);

    mm2_kernel<<<dim3(QKV_N / 128, S_LEN / 128), 256, 81920>>>(
        xh, xl, wqh, wql, nullptr, QKV_N, DIM, 1);

    {
        const int TOT = HEADS * KL + HEADS * S_LEN;   // rows
        int threads = TOT * 16;
        rope_apply_kernel<<<(threads + 255) / 256, 256>>>(pm);
    }

    vtrans_kernel<<<dim3((KL + 31) / 32, DH / 32, HEADS), dim3(32, 8)>>>();

    attn_mma_kernel<<<dim3(8, 8, 8), 128, 65536>>>();

    mm2_kernel<<<dim3(DIM / 128, S_LEN / 128), 256, 81920>>>(
        ah, al, woh, wol, (float*)d_out, DIM, DIM, 0);
}

// round 11
// speedup vs baseline: 2.4654x; 1.0108x over previous
#include <cuda_runtime.h>
#include <cuda_bf16.h>
#include <cstdint>
#include <math.h>

// ---------------------------------------------------------------------------
// Problem constants
// ---------------------------------------------------------------------------
#define S_LEN 4096
#define DIM   512
#define HEADS 8
#define DH    64
#define NPM   16
#define SEGLEN 512
#define KL    (S_LEN + NPM)        // 4112 keys after memory prepend
#define QKV_N (3 * HEADS * DH)     // 1536

// ---------------------------------------------------------------------------
// Scratch (device globals: no allocation allowed)
// ---------------------------------------------------------------------------
__device__ float g_Q[HEADS * S_LEN * DH];     // fp32 [h][s][d] (pre-rope)
__device__ float g_K[HEADS * KL * DH];        // fp32 [h][t][d] (pre-rope, t>=16)
__device__ float g_V[HEADS * KL * DH];        // fp32 [h][t][d]
__device__ float g_cos[KL * 32];
__device__ float g_sin[KL * 32];
// pre-split bf16 operands
__device__ __align__(16) __nv_bfloat16 g_Xh[S_LEN * DIM];
__device__ __align__(16) __nv_bfloat16 g_Xl[S_LEN * DIM];
__device__ __align__(16) __nv_bfloat16 g_WqkvTh[QKV_N * DIM];  // [n][k]
__device__ __align__(16) __nv_bfloat16 g_WqkvTl[QKV_N * DIM];
__device__ __align__(16) __nv_bfloat16 g_WoutTh[DIM * DIM];    // [n][k]
__device__ __align__(16) __nv_bfloat16 g_WoutTl[DIM * DIM];
__device__ __align__(16) __nv_bfloat16 g_Ah[S_LEN * DIM];      // attention out
__device__ __align__(16) __nv_bfloat16 g_Al[S_LEN * DIM];
// attention operands
__device__ __align__(16) __nv_bfloat16 g_Qh[HEADS * S_LEN * DH];
__device__ __align__(16) __nv_bfloat16 g_Ql[HEADS * S_LEN * DH];
__device__ __align__(16) __nv_bfloat16 g_Kh[HEADS * KL * DH];
__device__ __align__(16) __nv_bfloat16 g_Kl[HEADS * KL * DH];
__device__ __align__(16) __nv_bfloat16 g_Vth[HEADS * DH * KL]; // [h][d][t]
__device__ __align__(16) __nv_bfloat16 g_Vtl[HEADS * DH * KL];

// ---------------------------------------------------------------------------
// helpers
// ---------------------------------------------------------------------------
__device__ __forceinline__ void split2(float a0, float a1,
                                       uint32_t& hi, uint32_t& lo) {
    uint32_t u0 = __float_as_uint(a0), u1 = __float_as_uint(a1);
    asm("prmt.b32 %0, %1, %2, 0x7632;" : "=r"(hi) : "r"(u0), "r"(u1));
    float r0 = a0 - __uint_as_float(u0 & 0xFFFF0000u);
    float r1 = a1 - __uint_as_float(u1 & 0xFFFF0000u);
    asm("cvt.rn.bf16x2.f32 %0, %1, %2;" : "=r"(lo) : "f"(r1), "f"(r0));
}

__device__ __forceinline__ float ex2(float x) {
    float r; asm("ex2.approx.f32 %0, %1;" : "=f"(r) : "f"(x)); return r;
}

__device__ __forceinline__ void ldsm_x4(uint32_t& r0, uint32_t& r1,
                                        uint32_t& r2, uint32_t& r3, uint32_t addr) {
    asm volatile("ldmatrix.sync.aligned.m8n8.x4.shared.b16 {%0,%1,%2,%3}, [%4];"
                 : "=r"(r0), "=r"(r1), "=r"(r2), "=r"(r3) : "r"(addr));
}

__device__ __forceinline__ void mma16816(float* c, const uint32_t* a,
                                         uint32_t b0, uint32_t b1) {
    asm volatile(
        "mma.sync.aligned.m16n8k16.row.col.f32.bf16.bf16.f32 "
        "{%0,%1,%2,%3}, {%4,%5,%6,%7}, {%8,%9}, {%0,%1,%2,%3};"
        : "+f"(c[0]), "+f"(c[1]), "+f"(c[2]), "+f"(c[3])
        : "r"(a[0]), "r"(a[1]), "r"(a[2]), "r"(a[3]), "r"(b0), "r"(b1));
}

#define CPA16(dst, src) \
    asm volatile("cp.async.cg.shared.global [%0], [%1], 16;" \
                 :: "r"(dst), "l"(src))

// ---------------------------------------------------------------------------
// prep_kernel: fuses rope_table + RMSNorm/convert_x + wtrans(w_qkv) +
// wtrans(w_out). 128 threads. Block-range dispatch (all parts independent).
// ---------------------------------------------------------------------------
#define PREP_TBL_BLKS  1028   // rope table: 131584 elems / 128
#define PREP_CVX_BLKS  4096   // one block per sequence row
#define PREP_WQ_BLKS   768    // w_qkv transpose tiles: (1536/32)*(512/32)
#define PREP_WO_BLKS   256    // w_out  transpose tiles: (512/32)*(512/32)
#define PREP_BLKS (PREP_TBL_BLKS + PREP_CVX_BLKS + PREP_WQ_BLKS + PREP_WO_BLKS)

__device__ __forceinline__ void wtrans_body(const float* __restrict__ src,
                                            __nv_bfloat16* __restrict__ dh,
                                            __nv_bfloat16* __restrict__ dl,
                                            int K, int N, int n0, int k0,
                                            int tid, float* tile /*32*33*/) {
    int tx = tid & 31, ty = tid >> 5;              // 128 threads: ty 0..3
    for (int r = ty; r < 32; r += 4)
        tile[r * 33 + tx] = src[(size_t)(k0 + r) * N + n0 + tx];
    __syncthreads();
    for (int r = ty; r < 32; r += 4) {
        int n = n0 + r, k = k0 + tx;
        float v = tile[tx * 33 + r];
        uint32_t uv = __float_as_uint(v) & 0xFFFF0000u;
        dh[(size_t)n * K + k] = __ushort_as_bfloat16((unsigned short)(uv >> 16));
        dl[(size_t)n * K + k] = __float2bfloat16(v - __uint_as_float(uv));
    }
}

__global__ __launch_bounds__(128) void prep_kernel(
    const float* __restrict__ seq, const float* __restrict__ norm_w,
    const float* __restrict__ w_qkv, const float* __restrict__ w_out)
{
    __shared__ float smem[32 * 33];
    const int b = blockIdx.x;
    const int tid = threadIdx.x;

    if (b < PREP_TBL_BLKS) {
        // ---- RoPE table ----
        int idx = b * 128 + tid;
        if (idx < KL * 32) {
            int pos = idx >> 5, j = idx & 31;
            float rf  = (float)pow(10000.0, -(double)j / 32.0);
            float ang = (float)pos * rf;
            g_cos[idx] = (float)cos((double)ang);
            g_sin[idx] = (float)sin((double)ang);
        }
        return;
    }
    if (b < PREP_TBL_BLKS + PREP_CVX_BLKS) {
        // ---- RMSNorm + X split ----
        int s = b - PREP_TBL_BLKS;
        float4 v = ((const float4*)(seq + (size_t)s * DIM))[tid];
        float p = v.x * v.x + v.y * v.y + v.z * v.z + v.w * v.w;
        #pragma unroll
        for (int o = 16; o; o >>= 1) p += __shfl_xor_sync(0xffffffffu, p, o);
        if ((tid & 31) == 0) smem[tid >> 5] = p;
        __syncthreads();
        float rs = rsqrtf((smem[0] + smem[1] + smem[2] + smem[3])
                          * (1.0f / (float)DIM) + 1.1920928955078125e-07f);
        float4 w = ((const float4*)norm_w)[tid];
        v.x *= rs * w.x; v.y *= rs * w.y; v.z *= rs * w.z; v.w *= rs * w.w;
        uint32_t h0, l0, h1, l1;
        split2(v.x, v.y, h0, l0);
        split2(v.z, v.w, h1, l1);
        ((uint2*)(g_Xh + (size_t)s * DIM))[tid] = make_uint2(h0, h1);
        ((uint2*)(g_Xl + (size_t)s * DIM))[tid] = make_uint2(l0, l1);
        return;
    }
    if (b < PREP_TBL_BLKS + PREP_CVX_BLKS + PREP_WQ_BLKS) {
        // ---- w_qkv transpose+split: [512][1536] -> [1536][512] ----
        int bb = b - PREP_TBL_BLKS - PREP_CVX_BLKS;
        int n0 = (bb % (QKV_N / 32)) * 32;
        int k0 = (bb / (QKV_N / 32)) * 32;
        wtrans_body(w_qkv, g_WqkvTh, g_WqkvTl, DIM, QKV_N, n0, k0, tid, smem);
        return;
    }
    {
        // ---- w_out transpose+split: [512][512] -> [512][512] ----
        int bb = b - PREP_TBL_BLKS - PREP_CVX_BLKS - PREP_WQ_BLKS;
        int n0 = (bb % (DIM / 32)) * 32;
        int k0 = (bb / (DIM / 32)) * 32;
        wtrans_body(w_out, g_WoutTh, g_WoutTl, DIM, DIM, n0, k0, tid, smem);
    }
}

// ---------------------------------------------------------------------------
// 3) bf16 split GEMM, pre-converted inputs, cp.async double-buffered.
//    (verified rounds 7/9/10, unchanged)
// ---------------------------------------------------------------------------
#define STG_A_H 0
#define STG_A_L 10240
#define STG_B_H 20480
#define STG_B_L 30720
#define STG_SZ  40960

#define PREFETCH(S) do {                                                      \
    int _k0 = (S) * 32;                                                       \
    uint32_t _b = sbase + ((S) & 1) * STG_SZ + r * 80 + cg * 16;              \
    const __nv_bfloat16* _ag = Ah + (size_t)(row0 + r) * K + _k0 + cg * 8;    \
    const __nv_bfloat16* _al = Al + (size_t)(row0 + r) * K + _k0 + cg * 8;    \
    const __nv_bfloat16* _bg = Bh + (size_t)(col0 + r) * K + _k0 + cg * 8;    \
    const __nv_bfloat16* _bl = Bl + (size_t)(col0 + r) * K + _k0 + cg * 8;    \
    CPA16(_b + STG_A_H,      _ag);                                            \
    CPA16(_b + STG_A_H + 16, _ag + 8);                                        \
    CPA16(_b + STG_A_L,      _al);                                            \
    CPA16(_b + STG_A_L + 16, _al + 8);                                        \
    CPA16(_b + STG_B_H,      _bg);                                            \
    CPA16(_b + STG_B_H + 16, _bg + 8);                                        \
    CPA16(_b + STG_B_L,      _bl);                                            \
    CPA16(_b + STG_B_L + 16, _bl + 8);                                        \
    asm volatile("cp.async.commit_group;");                                   \
} while (0)

__global__ __launch_bounds__(256) void mm2_kernel(
    const __nv_bfloat16* __restrict__ Ah, const __nv_bfloat16* __restrict__ Al,
    const __nv_bfloat16* __restrict__ Bh, const __nv_bfloat16* __restrict__ Bl,
    float* __restrict__ C, int N, int K, int epi)
{
    extern __shared__ __align__(16) uint8_t smem[];
    const uint32_t sbase = (uint32_t)__cvta_generic_to_shared(smem);

    const int tid  = threadIdx.x;
    const int lane = tid & 31, warp = tid >> 5;
    const int wm = warp & 1, wn = warp >> 1;
    const int row0 = blockIdx.y * 128, col0 = blockIdx.x * 128;

    const int r  = tid >> 1;
    const int cg = (tid & 1) * 2;

    const int NST = K / 32;

    float acc[4][4][4];
    #pragma unroll
    for (int i = 0; i < 4; i++)
        #pragma unroll
        for (int j = 0; j < 4; j++)
            #pragma unroll
            for (int q = 0; q < 4; q++) acc[i][j][q] = 0.0f;

    PREFETCH(0);
    PREFETCH(1);

    const int mbase = wm * 64, nbase = wn * 32;
    const int lr = lane & 15, lh = (lane >> 4) * 16;

    for (int s = 0; s < NST; s++) {
        if (s + 1 < NST) asm volatile("cp.async.wait_group 1;");
        else             asm volatile("cp.async.wait_group 0;");
        __syncthreads();

        const uint32_t bAh = sbase + (s & 1) * STG_SZ + STG_A_H;
        const uint32_t bAl = sbase + (s & 1) * STG_SZ + STG_A_L;
        const uint32_t bBh = sbase + (s & 1) * STG_SZ + STG_B_H;
        const uint32_t bBl = sbase + (s & 1) * STG_SZ + STG_B_L;

        #pragma unroll
        for (int kk = 0; kk < 2; kk++) {
            const uint32_t kb = (uint32_t)(kk * 32 + lh);
            uint32_t ah[4][4], al[4][4], bh[2][4], bl[2][4];
            #pragma unroll
            for (int mf = 0; mf < 4; mf++) {
                uint32_t ro = (uint32_t)(mbase + mf * 16 + lr) * 80 + kb;
                ldsm_x4(ah[mf][0], ah[mf][1], ah[mf][2], ah[mf][3], bAh + ro);
                ldsm_x4(al[mf][0], al[mf][1], al[mf][2], al[mf][3], bAl + ro);
            }
            #pragma unroll
            for (int np = 0; np < 2; np++) {
                uint32_t ro = (uint32_t)(nbase + np * 16 + lr) * 80 + kb;
                ldsm_x4(bh[np][0], bh[np][1], bh[np][2], bh[np][3], bBh + ro);
                ldsm_x4(bl[np][0], bl[np][1], bl[np][2], bl[np][3], bBl + ro);
            }
            #pragma unroll
            for (int mf = 0; mf < 4; mf++) {
                #pragma unroll
                for (int nf = 0; nf < 4; nf++) {
                    const int np = nf >> 1, half = nf & 1;
                    uint32_t b0h = bh[np][half], b1h = bh[np][2 + half];
                    uint32_t b0l = bl[np][half], b1l = bl[np][2 + half];
                    mma16816(acc[mf][nf], ah[mf], b0h, b1h);
                    mma16816(acc[mf][nf], ah[mf], b0l, b1l);
                    mma16816(acc[mf][nf], al[mf], b0h, b1h);
                }
            }
        }
        __syncthreads();
        if (s + 2 < NST) PREFETCH(s + 2);
    }

    #pragma unroll
    for (int mf = 0; mf < 4; mf++) {
        #pragma unroll
        for (int nf = 0; nf < 4; nf++) {
            int rr0 = row0 + mbase + mf * 16 + (lane >> 2);
            int cc0 = col0 + nbase + nf * 8 + (lane & 3) * 2;
            #pragma unroll
            for (int q = 0; q < 4; q++) {
                int row = rr0 + ((q >= 2) ? 8 : 0);
                int col = cc0 + (q & 1);
                float val = acc[mf][nf][q];
                if (epi == 0) {
                    C[(size_t)row * N + col] = val;
                } else {
                    int region = col >> 9;
                    int cr = col & 511;
                    int hh = cr >> 6, dd = cr & 63;
                    if (region == 0)      g_Q[((size_t)hh * S_LEN + row) * DH + dd] = val;
                    else if (region == 1) g_K[((size_t)hh * KL + row + NPM) * DH + dd] = val;
                    else                  g_V[((size_t)hh * KL + row + NPM) * DH + dd] = val;
                }
            }
        }
    }
}

// ---------------------------------------------------------------------------
// post_kernel: fuses rope_apply (Q/K + pm slots) and V transpose+split.
// 128 threads, block-range dispatch.
// ---------------------------------------------------------------------------
#define POST_ROPE_ROWS (HEADS * KL + HEADS * S_LEN)          // 65664
#define POST_ROPE_BLKS ((POST_ROPE_ROWS * 16 + 127) / 128)   // 8208
#define POST_VT_X   ((KL + 31) / 32)                          // 129
#define POST_VT_BLKS (POST_VT_X * (DH / 32) * HEADS)          // 2064
#define POST_BLKS (POST_ROPE_BLKS + POST_VT_BLKS)

__global__ __launch_bounds__(128) void post_kernel(const float* __restrict__ pm) {
    __shared__ float tile[32 * 33];
    const int b = blockIdx.x;
    const int tid = threadIdx.x;

    if (b < POST_ROPE_BLKS) {
        // ---- RoPE apply + Q/K split (16 threads per 64-elem row) ----
        int gid = b * 128 + tid;
        int row = gid >> 4;
        int u   = gid & 15;
        const int KROWS = HEADS * KL;
        if (row >= POST_ROPE_ROWS) return;

        float4 x;
        size_t base;
        int pos;
        __nv_bfloat16 *dsth, *dstl;

        if (row < KROWS) {
            int h = row / KL, t = row % KL;
            pos = t;
            base = ((size_t)h * KL + t) * DH + 4 * u;
            if (t < NPM) {
                x = *(const float4*)(pm + (((size_t)0 * HEADS + h) * NPM + t) * DH + 4 * u);
                float4 vv = *(const float4*)(pm + (((size_t)1 * HEADS + h) * NPM + t) * DH + 4 * u);
                *(float4*)(g_V + base) = vv;
            } else {
                x = *(const float4*)(g_K + base);
            }
            dsth = g_Kh; dstl = g_Kl;
        } else {
            int rr = row - KROWS;
            int h = rr / S_LEN, s = rr % S_LEN;
            pos = s + NPM;
            base = ((size_t)h * S_LEN + s) * DH + 4 * u;
            x = *(const float4*)(g_Q + base);
            dsth = g_Qh; dstl = g_Ql;
        }

        float c0 = g_cos[pos * 32 + 2 * u],     s0 = g_sin[pos * 32 + 2 * u];
        float c1 = g_cos[pos * 32 + 2 * u + 1], s1 = g_sin[pos * 32 + 2 * u + 1];
        float r0 = x.x * c0 - x.y * s0;
        float r1 = x.y * c0 + x.x * s0;
        float r2 = x.z * c1 - x.w * s1;
        float r3 = x.w * c1 + x.z * s1;
        uint32_t h0, l0, h1, l1;
        split2(r0, r1, h0, l0);
        split2(r2, r3, h1, l1);
        *(uint2*)(dsth + base) = make_uint2(h0, h1);
        *(uint2*)(dstl + base) = make_uint2(l0, l1);
        return;
    }

    // ---- V transpose + split ----
    {
        int bb = b - POST_ROPE_BLKS;
        int h   = bb / (POST_VT_X * (DH / 32));
        int rem = bb % (POST_VT_X * (DH / 32));
        int d0  = (rem / POST_VT_X) * 32;
        int t0  = (rem % POST_VT_X) * 32;
        int tx = tid & 31, ty = tid >> 5;          // ty 0..3
        for (int r = ty; r < 32; r += 4) {
            int t = t0 + r;
            if (t < KL)
                tile[r * 33 + tx] = g_V[((size_t)h * KL + t) * DH + d0 + tx];
        }
        __syncthreads();
        for (int r = ty; r < 32; r += 4) {
            int d = d0 + r;
            int t = t0 + tx;
            if (t < KL) {
                float v = tile[tx * 33 + r];
                uint32_t uv = __float_as_uint(v) & 0xFFFF0000u;
                g_Vth[((size_t)(h * DH + d)) * KL + t] =
                    __ushort_as_bfloat16((unsigned short)(uv >> 16));
                g_Vtl[((size_t)(h * DH + d)) * KL + t] =
                    __float2bfloat16(v - __uint_as_float(uv));
            }
        }
    }
}

// ---------------------------------------------------------------------------
// 5) Tensor-core flash attention. 64 KB smem, 3 blocks/SM, heavy-qt-first.
//    K/V fragments loaded per-group (register diet vs round 10).
// ---------------------------------------------------------------------------
#define SWADDR(base, row, ch) ((base) + (uint32_t)(row) * 128u + \
                               ((uint32_t)((ch) ^ ((row) & 7)) << 4))

#define ATT_KVPF(TT) do {                                                     \
    int _t0 = ((TT) == 0) ? 0 : (NPM + seg * SEGLEN + ((TT) - 1) * 64);       \
    uint32_t _buf = sbase + (((TT) & 1) ? 32768u : 0u);                       \
    _Pragma("unroll")                                                         \
    for (int _k = 0; _k < 4; _k++) {                                          \
        int _i = tid + _k * 128;                                              \
        int _row = _i >> 3, _ch = _i & 7;                                     \
        uint32_t _d16 = (uint32_t)(_row * 8 + (_ch ^ (_row & 7))) * 16u;      \
        const __nv_bfloat16* _kh = g_Kh + ((size_t)h * KL + _t0 + _row) * DH + _ch * 8; \
        const __nv_bfloat16* _kl = g_Kl + ((size_t)h * KL + _t0 + _row) * DH + _ch * 8; \
        const __nv_bfloat16* _vh = g_Vth + ((size_t)(h * DH + _row)) * KL + _t0 + _ch * 8; \
        const __nv_bfloat16* _vl = g_Vtl + ((size_t)(h * DH + _row)) * KL + _t0 + _ch * 8; \
        CPA16(_buf + _d16,          _kh);                                     \
        CPA16(_buf + 8192u + _d16,  _kl);                                     \
        CPA16(_buf + 16384u + _d16, _vh);                                     \
        CPA16(_buf + 24576u + _d16, _vl);                                     \
    }                                                                         \
    asm volatile("cp.async.commit_group;");                                   \
} while (0)

__global__ __launch_bounds__(128) void attn_mma_kernel() {
    extern __shared__ __align__(16) uint8_t asmem[];
    const uint32_t sbase = (uint32_t)__cvta_generic_to_shared(asmem);

    const int qt = 7 - blockIdx.x;             // heavy blocks first
    const int seg = blockIdx.y, h = blockIdx.z;
    const int tid = threadIdx.x;
    const int lane = tid & 31, w = tid >> 5;
    const int s0 = seg * SEGLEN + qt * 64;
    const int ntiles = qt + 2;

    ATT_KVPF(0);

    // stage Q into buf1 region (free until tile-1 prefetch below)
    const uint32_t qb = sbase + 32768u;
    for (int i = tid; i < 512; i += 128) {
        int row = i >> 3, ch = i & 7;
        int d = row * 8 + (ch ^ (row & 7));
        ((uint4*)(asmem + 32768))[d] =
            *((const uint4*)(g_Qh + ((size_t)h * S_LEN + s0 + row) * DH) + ch);
        ((uint4*)(asmem + 40960))[d] =
            *((const uint4*)(g_Ql + ((size_t)h * S_LEN + s0 + row) * DH) + ch);
    }
    __syncthreads();

    uint32_t qh[4][4], ql[4][4];
    {
        int row = w * 16 + (lane & 15);
        #pragma unroll
        for (int j = 0; j < 4; j++) {
            int ch = 2 * j + (lane >> 4);
            ldsm_x4(qh[j][0], qh[j][1], qh[j][2], qh[j][3], SWADDR(qb, row, ch));
            ldsm_x4(ql[j][0], ql[j][1], ql[j][2], ql[j][3], SWADDR(qb + 8192u, row, ch));
        }
    }
    __syncthreads();

    ATT_KVPF(1);

    float oacc[8][4];
    #pragma unroll
    for (int nf = 0; nf < 8; nf++)
        #pragma unroll
        for (int q = 0; q < 4; q++) oacc[nf][q] = 0.0f;
    float mrun[2] = {-INFINITY, -INFINITY};
    float lrun[2] = {0.0f, 0.0f};

    const float SC = 0.125f * 1.44269504088896341f;
    const int r1 = lane >> 2;
    const int cbase = (lane & 3) * 2;

    for (int tt = 0; tt < ntiles; tt++) {
        const bool ismem = (tt == 0);
        const bool diag = (!ismem) && ((tt - 1) == qt);

        if (tt + 1 < ntiles) asm volatile("cp.async.wait_group 1;");
        else                 asm volatile("cp.async.wait_group 0;");
        __syncthreads();

        const uint32_t kb0 = sbase + ((tt & 1) ? 32768u : 0u);
        const uint32_t bKh = kb0, bKl = kb0 + 8192u;
        const uint32_t bVh = kb0 + 16384u, bVl = kb0 + 24576u;

        // ---- S = Q K^T (3-split), K frags loaded per-ng ----
        float sacc[8][4];
        #pragma unroll
        for (int nf = 0; nf < 8; nf++)
            #pragma unroll
            for (int q = 0; q < 4; q++) sacc[nf][q] = 0.0f;

        #pragma unroll
        for (int j = 0; j < 4; j++) {
            int ch = 2 * j + (lane >> 4);
            #pragma unroll
            for (int ng = 0; ng < 4; ng++) {
                if (ismem && ng > 0) break;
                int row = ng * 16 + (lane & 15);
                uint32_t kh[4], kl[4];
                ldsm_x4(kh[0], kh[1], kh[2], kh[3], SWADDR(bKh, row, ch));
                ldsm_x4(kl[0], kl[1], kl[2], kl[3], SWADDR(bKl, row, ch));
                #pragma unroll
                for (int sel = 0; sel < 2; sel++) {
                    const int nf = 2 * ng + sel;
                    mma16816(sacc[nf], qh[j], kh[sel], kh[2 + sel]);
                    mma16816(sacc[nf], qh[j], kl[sel], kl[2 + sel]);
                    mma16816(sacc[nf], ql[j], kh[sel], kh[2 + sel]);
                }
            }
        }

        // ---- scale + mask (exp2 domain) ----
        #pragma unroll
        for (int nf = 0; nf < 8; nf++) {
            #pragma unroll
            for (int q = 0; q < 4; q++) {
                int col = nf * 8 + cbase + (q & 1);
                int qrow = w * 16 + r1 + ((q >= 2) ? 8 : 0);
                float v = sacc[nf][q] * SC;
                bool bad = (ismem && col >= 16) || (diag && col > qrow);
                sacc[nf][q] = bad ? -INFINITY : v;
            }
        }

        // ---- row max ----
        float ml[2] = {-INFINITY, -INFINITY};
        #pragma unroll
        for (int nf = 0; nf < 8; nf++) {
            ml[0] = fmaxf(ml[0], fmaxf(sacc[nf][0], sacc[nf][1]));
            ml[1] = fmaxf(ml[1], fmaxf(sacc[nf][2], sacc[nf][3]));
        }
        #pragma unroll
        for (int o = 1; o <= 2; o <<= 1) {
            ml[0] = fmaxf(ml[0], __shfl_xor_sync(0xffffffffu, ml[0], o));
            ml[1] = fmaxf(ml[1], __shfl_xor_sync(0xffffffffu, ml[1], o));
        }
        float mnew0 = fmaxf(mrun[0], ml[0]);
        float mnew1 = fmaxf(mrun[1], ml[1]);
        float corr0 = ex2(mrun[0] - mnew0);
        float corr1 = ex2(mrun[1] - mnew1);
        mrun[0] = mnew0; mrun[1] = mnew1;

        // ---- p = exp2(s - m), row sums ----
        float ls[2] = {0.0f, 0.0f};
        #pragma unroll
        for (int nf = 0; nf < 8; nf++) {
            float p0 = ex2(sacc[nf][0] - mnew0);
            float p1 = ex2(sacc[nf][1] - mnew0);
            float p2 = ex2(sacc[nf][2] - mnew1);
            float p3 = ex2(sacc[nf][3] - mnew1);
            sacc[nf][0] = p0; sacc[nf][1] = p1; sacc[nf][2] = p2; sacc[nf][3] = p3;
            ls[0] += p0 + p1; ls[1] += p2 + p3;
        }
        #pragma unroll
        for (int o = 1; o <= 2; o <<= 1) {
            ls[0] += __shfl_xor_sync(0xffffffffu, ls[0], o);
            ls[1] += __shfl_xor_sync(0xffffffffu, ls[1], o);
        }
        lrun[0] = lrun[0] * corr0 + ls[0];
        lrun[1] = lrun[1] * corr1 + ls[1];

        #pragma unroll
        for (int nf = 0; nf < 8; nf++) {
            oacc[nf][0] *= corr0; oacc[nf][1] *= corr0;
            oacc[nf][2] *= corr1; oacc[nf][3] *= corr1;
        }

        // ---- O += P V^T (3-split), V frags loaded per-dg ----
        #pragma unroll
        for (int j = 0; j < 4; j++) {
            if (ismem && j > 0) break;
            uint32_t pa_h[4], pa_l[4];
            split2(sacc[2*j][0],   sacc[2*j][1],   pa_h[0], pa_l[0]);
            split2(sacc[2*j][2],   sacc[2*j][3],   pa_h[1], pa_l[1]);
            split2(sacc[2*j+1][0], sacc[2*j+1][1], pa_h[2], pa_l[2]);
            split2(sacc[2*j+1][2], sacc[2*j+1][3], pa_h[3], pa_l[3]);

            int ch = 2 * j + (lane >> 4);
            #pragma unroll
            for (int dg = 0; dg < 4; dg++) {
                int row = dg * 16 + (lane & 15);
                uint32_t vh[4], vl[4];
                ldsm_x4(vh[0], vh[1], vh[2], vh[3], SWADDR(bVh, row, ch));
                ldsm_x4(vl[0], vl[1], vl[2], vl[3], SWADDR(bVl, row, ch));
                #pragma unroll
                for (int sel = 0; sel < 2; sel++) {
                    const int nf = 2 * dg + sel;
                    mma16816(oacc[nf], pa_h, vh[sel], vh[2 + sel]);
                    mma16816(oacc[nf], pa_h, vl[sel], vl[2 + sel]);
                    mma16816(oacc[nf], pa_l, vh[sel], vh[2 + sel]);
                }
            }
        }

        __syncthreads();
        if (tt + 2 < ntiles) ATT_KVPF(tt + 2);
    }

    float inv0 = 1.0f / lrun[0];
    float inv1 = 1.0f / lrun[1];
    int qrow = s0 + w * 16 + r1;
    #pragma unroll
    for (int nf = 0; nf < 8; nf++) {
        int col = h * DH + nf * 8 + cbase;
        uint32_t h0, l0, h1, l1;
        split2(oacc[nf][0] * inv0, oacc[nf][1] * inv0, h0, l0);
        split2(oacc[nf][2] * inv1, oacc[nf][3] * inv1, h1, l1);
        *(uint32_t*)(g_Ah + (size_t)qrow * DIM + col)       = h0;
        *(uint32_t*)(g_Al + (size_t)qrow * DIM + col)       = l0;
        *(uint32_t*)(g_Ah + (size_t)(qrow + 8) * DIM + col) = h1;
        *(uint32_t*)(g_Al + (size_t)(qrow + 8) * DIM + col) = l1;
    }
}

// ---------------------------------------------------------------------------
// Launch: 5 kernels (prep -> GEMM1 -> post -> attn -> GEMM2)
// ---------------------------------------------------------------------------
extern "C" void kernel_launch(void* const* d_in, const int* in_sizes, int n_in,
                              void* d_out, int out_size) {
    const float* seq    = (const float*)d_in[0];
    const float* norm_w = (const float*)d_in[1];
    const float* w_qkv  = (const float*)d_in[2];
    const float* w_out  = (const float*)d_in[3];
    const float* pm     = (const float*)d_in[4];

    __nv_bfloat16 *xh, *xl, *wqh, *wql, *woh, *wol, *ah, *al;
    cudaGetSymbolAddress((void**)&xh,  g_Xh);
    cudaGetSymbolAddress((void**)&xl,  g_Xl);
    cudaGetSymbolAddress((void**)&wqh, g_WqkvTh);
    cudaGetSymbolAddress((void**)&wql, g_WqkvTl);
    cudaGetSymbolAddress((void**)&woh, g_WoutTh);
    cudaGetSymbolAddress((void**)&wol, g_WoutTl);
    cudaGetSymbolAddress((void**)&ah,  g_Ah);
    cudaGetSymbolAddress((void**)&al,  g_Al);

    cudaFuncSetAttribute(mm2_kernel,
                         cudaFuncAttributeMaxDynamicSharedMemorySize, 81920);
    cudaFuncSetAttribute(attn_mma_kernel,
                         cudaFuncAttributeMaxDynamicSharedMemorySize, 65536);

    prep_kernel<<<PREP_BLKS, 128>>>(seq, norm_w, w_qkv, w_out);

    mm2_kernel<<<dim3(QKV_N / 128, S_LEN / 128), 256, 81920>>>(
        xh, xl, wqh, wql, nullptr, QKV_N, DIM, 1);

    post_kernel<<<POST_BLKS, 128>>>(pm);

    attn_mma_kernel<<<dim3(8, 8, 8), 128, 65536>>>();

    mm2_kernel<<<dim3(DIM / 128, S_LEN / 128), 256, 81920>>>(
        ah, al, woh, wol, (float*)d_out, DIM, DIM, 0);
}

// round 12
// speedup vs baseline: 2.5424x; 1.0312x over previous
#include <cuda_runtime.h>
#include <cuda_bf16.h>
#include <cstdint>
#include <math.h>

// ---------------------------------------------------------------------------
// Problem constants
// ---------------------------------------------------------------------------
#define S_LEN 4096
#define DIM   512
#define HEADS 8
#define DH    64
#define NPM   16
#define SEGLEN 512
#define KL    (S_LEN + NPM)        // 4112 keys after memory prepend
#define QKV_N (3 * HEADS * DH)     // 1536

// ---------------------------------------------------------------------------
// Scratch (device globals: no allocation allowed)
// ---------------------------------------------------------------------------
__device__ float g_Q[HEADS * S_LEN * DH];     // fp32 [h][s][d] (pre-rope)
__device__ float g_K[HEADS * KL * DH];        // fp32 [h][t][d] (pre-rope, t>=16)
__device__ float g_V[HEADS * KL * DH];        // fp32 [h][t][d]
__device__ float g_cos[KL * 32];
__device__ float g_sin[KL * 32];
// pre-split bf16 operands
__device__ __align__(16) __nv_bfloat16 g_Xh[S_LEN * DIM];
__device__ __align__(16) __nv_bfloat16 g_Xl[S_LEN * DIM];
__device__ __align__(16) __nv_bfloat16 g_WqkvTh[QKV_N * DIM];  // [n][k]
__device__ __align__(16) __nv_bfloat16 g_WqkvTl[QKV_N * DIM];
__device__ __align__(16) __nv_bfloat16 g_WoutTh[DIM * DIM];    // [n][k]
__device__ __align__(16) __nv_bfloat16 g_WoutTl[DIM * DIM];
__device__ __align__(16) __nv_bfloat16 g_Ah[S_LEN * DIM];      // attention out
__device__ __align__(16) __nv_bfloat16 g_Al[S_LEN * DIM];
// attention operands
__device__ __align__(16) __nv_bfloat16 g_Qh[HEADS * S_LEN * DH];
__device__ __align__(16) __nv_bfloat16 g_Ql[HEADS * S_LEN * DH];
__device__ __align__(16) __nv_bfloat16 g_Kh[HEADS * KL * DH];
__device__ __align__(16) __nv_bfloat16 g_Kl[HEADS * KL * DH];
__device__ __align__(16) __nv_bfloat16 g_Vth[HEADS * DH * KL]; // [h][d][t]
__device__ __align__(16) __nv_bfloat16 g_Vtl[HEADS * DH * KL];

// ---------------------------------------------------------------------------
// helpers
// ---------------------------------------------------------------------------
__device__ __forceinline__ void split2(float a0, float a1,
                                       uint32_t& hi, uint32_t& lo) {
    uint32_t u0 = __float_as_uint(a0), u1 = __float_as_uint(a1);
    asm("prmt.b32 %0, %1, %2, 0x7632;" : "=r"(hi) : "r"(u0), "r"(u1));
    float r0 = a0 - __uint_as_float(u0 & 0xFFFF0000u);
    float r1 = a1 - __uint_as_float(u1 & 0xFFFF0000u);
    asm("cvt.rn.bf16x2.f32 %0, %1, %2;" : "=r"(lo) : "f"(r1), "f"(r0));
}

__device__ __forceinline__ float ex2(float x) {
    float r; asm("ex2.approx.f32 %0, %1;" : "=f"(r) : "f"(x)); return r;
}

__device__ __forceinline__ void ldsm_x4(uint32_t& r0, uint32_t& r1,
                                        uint32_t& r2, uint32_t& r3, uint32_t addr) {
    asm volatile("ldmatrix.sync.aligned.m8n8.x4.shared.b16 {%0,%1,%2,%3}, [%4];"
                 : "=r"(r0), "=r"(r1), "=r"(r2), "=r"(r3) : "r"(addr));
}

__device__ __forceinline__ void mma16816(float* c, const uint32_t* a,
                                         uint32_t b0, uint32_t b1) {
    asm volatile(
        "mma.sync.aligned.m16n8k16.row.col.f32.bf16.bf16.f32 "
        "{%0,%1,%2,%3}, {%4,%5,%6,%7}, {%8,%9}, {%0,%1,%2,%3};"
        : "+f"(c[0]), "+f"(c[1]), "+f"(c[2]), "+f"(c[3])
        : "r"(a[0]), "r"(a[1]), "r"(a[2]), "r"(a[3]), "r"(b0), "r"(b1));
}

#define CPA16(dst, src) \
    asm volatile("cp.async.cg.shared.global [%0], [%1], 16;" \
                 :: "r"(dst), "l"(src))

// ---------------------------------------------------------------------------
// prep_kernel: fuses rope_table + RMSNorm/convert_x + wtrans(w_qkv) +
// wtrans(w_out). 128 threads. Block-range dispatch.
// ---------------------------------------------------------------------------
#define PREP_TBL_BLKS  1028   // rope table: 131584 elems / 128
#define PREP_CVX_BLKS  4096   // one block per sequence row
#define PREP_WQ_BLKS   768    // w_qkv transpose tiles
#define PREP_WO_BLKS   256    // w_out  transpose tiles
#define PREP_BLKS (PREP_TBL_BLKS + PREP_CVX_BLKS + PREP_WQ_BLKS + PREP_WO_BLKS)

__device__ __forceinline__ void wtrans_body(const float* __restrict__ src,
                                            __nv_bfloat16* __restrict__ dh,
                                            __nv_bfloat16* __restrict__ dl,
                                            int K, int N, int n0, int k0,
                                            int tid, float* tile /*32*33*/) {
    int tx = tid & 31, ty = tid >> 5;              // 128 threads: ty 0..3
    for (int r = ty; r < 32; r += 4)
        tile[r * 33 + tx] = src[(size_t)(k0 + r) * N + n0 + tx];
    __syncthreads();
    for (int r = ty; r < 32; r += 4) {
        int n = n0 + r, k = k0 + tx;
        float v = tile[tx * 33 + r];
        uint32_t uv = __float_as_uint(v) & 0xFFFF0000u;
        dh[(size_t)n * K + k] = __ushort_as_bfloat16((unsigned short)(uv >> 16));
        dl[(size_t)n * K + k] = __float2bfloat16(v - __uint_as_float(uv));
    }
}

__global__ __launch_bounds__(128) void prep_kernel(
    const float* __restrict__ seq, const float* __restrict__ norm_w,
    const float* __restrict__ w_qkv, const float* __restrict__ w_out)
{
    __shared__ float smem[32 * 33];
    const int b = blockIdx.x;
    const int tid = threadIdx.x;

    if (b < PREP_TBL_BLKS) {
        // ---- RoPE table: rf in double (bit-exact f32 inv_freq), trig in
        //      float sincosf of the SAME f32 angle (error ~2 ulp of result).
        int idx = b * 128 + tid;
        if (idx < KL * 32) {
            int pos = idx >> 5, j = idx & 31;
            float rf  = (float)pow(10000.0, -(double)j / 32.0);
            float ang = (float)pos * rf;
            float s, c;
            sincosf(ang, &s, &c);
            g_cos[idx] = c;
            g_sin[idx] = s;
        }
        return;
    }
    if (b < PREP_TBL_BLKS + PREP_CVX_BLKS) {
        // ---- RMSNorm + X split ----
        int s = b - PREP_TBL_BLKS;
        float4 v = ((const float4*)(seq + (size_t)s * DIM))[tid];
        float p = v.x * v.x + v.y * v.y + v.z * v.z + v.w * v.w;
        #pragma unroll
        for (int o = 16; o; o >>= 1) p += __shfl_xor_sync(0xffffffffu, p, o);
        if ((tid & 31) == 0) smem[tid >> 5] = p;
        __syncthreads();
        float rs = rsqrtf((smem[0] + smem[1] + smem[2] + smem[3])
                          * (1.0f / (float)DIM) + 1.1920928955078125e-07f);
        float4 w = ((const float4*)norm_w)[tid];
        v.x *= rs * w.x; v.y *= rs * w.y; v.z *= rs * w.z; v.w *= rs * w.w;
        uint32_t h0, l0, h1, l1;
        split2(v.x, v.y, h0, l0);
        split2(v.z, v.w, h1, l1);
        ((uint2*)(g_Xh + (size_t)s * DIM))[tid] = make_uint2(h0, h1);
        ((uint2*)(g_Xl + (size_t)s * DIM))[tid] = make_uint2(l0, l1);
        return;
    }
    if (b < PREP_TBL_BLKS + PREP_CVX_BLKS + PREP_WQ_BLKS) {
        int bb = b - PREP_TBL_BLKS - PREP_CVX_BLKS;
        int n0 = (bb % (QKV_N / 32)) * 32;
        int k0 = (bb / (QKV_N / 32)) * 32;
        wtrans_body(w_qkv, g_WqkvTh, g_WqkvTl, DIM, QKV_N, n0, k0, tid, smem);
        return;
    }
    {
        int bb = b - PREP_TBL_BLKS - PREP_CVX_BLKS - PREP_WQ_BLKS;
        int n0 = (bb % (DIM / 32)) * 32;
        int k0 = (bb / (DIM / 32)) * 32;
        wtrans_body(w_out, g_WoutTh, g_WoutTl, DIM, DIM, n0, k0, tid, smem);
    }
}

// ---------------------------------------------------------------------------
// 3) bf16 split GEMM, pre-converted inputs, cp.async double-buffered.
//    (verified rounds 7/9/10/11, unchanged)
// ---------------------------------------------------------------------------
#define STG_A_H 0
#define STG_A_L 10240
#define STG_B_H 20480
#define STG_B_L 30720
#define STG_SZ  40960

#define PREFETCH(S) do {                                                      \
    int _k0 = (S) * 32;                                                       \
    uint32_t _b = sbase + ((S) & 1) * STG_SZ + r * 80 + cg * 16;              \
    const __nv_bfloat16* _ag = Ah + (size_t)(row0 + r) * K + _k0 + cg * 8;    \
    const __nv_bfloat16* _al = Al + (size_t)(row0 + r) * K + _k0 + cg * 8;    \
    const __nv_bfloat16* _bg = Bh + (size_t)(col0 + r) * K + _k0 + cg * 8;    \
    const __nv_bfloat16* _bl = Bl + (size_t)(col0 + r) * K + _k0 + cg * 8;    \
    CPA16(_b + STG_A_H,      _ag);                                            \
    CPA16(_b + STG_A_H + 16, _ag + 8);                                        \
    CPA16(_b + STG_A_L,      _al);                                            \
    CPA16(_b + STG_A_L + 16, _al + 8);                                        \
    CPA16(_b + STG_B_H,      _bg);                                            \
    CPA16(_b + STG_B_H + 16, _bg + 8);                                        \
    CPA16(_b + STG_B_L,      _bl);                                            \
    CPA16(_b + STG_B_L + 16, _bl + 8);                                        \
    asm volatile("cp.async.commit_group;");                                   \
} while (0)

__global__ __launch_bounds__(256) void mm2_kernel(
    const __nv_bfloat16* __restrict__ Ah, const __nv_bfloat16* __restrict__ Al,
    const __nv_bfloat16* __restrict__ Bh, const __nv_bfloat16* __restrict__ Bl,
    float* __restrict__ C, int N, int K, int epi)
{
    extern __shared__ __align__(16) uint8_t smem[];
    const uint32_t sbase = (uint32_t)__cvta_generic_to_shared(smem);

    const int tid  = threadIdx.x;
    const int lane = tid & 31, warp = tid >> 5;
    const int wm = warp & 1, wn = warp >> 1;
    const int row0 = blockIdx.y * 128, col0 = blockIdx.x * 128;

    const int r  = tid >> 1;
    const int cg = (tid & 1) * 2;

    const int NST = K / 32;

    float acc[4][4][4];
    #pragma unroll
    for (int i = 0; i < 4; i++)
        #pragma unroll
        for (int j = 0; j < 4; j++)
            #pragma unroll
            for (int q = 0; q < 4; q++) acc[i][j][q] = 0.0f;

    PREFETCH(0);
    PREFETCH(1);

    const int mbase = wm * 64, nbase = wn * 32;
    const int lr = lane & 15, lh = (lane >> 4) * 16;

    for (int s = 0; s < NST; s++) {
        if (s + 1 < NST) asm volatile("cp.async.wait_group 1;");
        else             asm volatile("cp.async.wait_group 0;");
        __syncthreads();

        const uint32_t bAh = sbase + (s & 1) * STG_SZ + STG_A_H;
        const uint32_t bAl = sbase + (s & 1) * STG_SZ + STG_A_L;
        const uint32_t bBh = sbase + (s & 1) * STG_SZ + STG_B_H;
        const uint32_t bBl = sbase + (s & 1) * STG_SZ + STG_B_L;

        #pragma unroll
        for (int kk = 0; kk < 2; kk++) {
            const uint32_t kb = (uint32_t)(kk * 32 + lh);
            uint32_t ah[4][4], al[4][4], bh[2][4], bl[2][4];
            #pragma unroll
            for (int mf = 0; mf < 4; mf++) {
                uint32_t ro = (uint32_t)(mbase + mf * 16 + lr) * 80 + kb;
                ldsm_x4(ah[mf][0], ah[mf][1], ah[mf][2], ah[mf][3], bAh + ro);
                ldsm_x4(al[mf][0], al[mf][1], al[mf][2], al[mf][3], bAl + ro);
            }
            #pragma unroll
            for (int np = 0; np < 2; np++) {
                uint32_t ro = (uint32_t)(nbase + np * 16 + lr) * 80 + kb;
                ldsm_x4(bh[np][0], bh[np][1], bh[np][2], bh[np][3], bBh + ro);
                ldsm_x4(bl[np][0], bl[np][1], bl[np][2], bl[np][3], bBl + ro);
            }
            #pragma unroll
            for (int mf = 0; mf < 4; mf++) {
                #pragma unroll
                for (int nf = 0; nf < 4; nf++) {
                    const int np = nf >> 1, half = nf & 1;
                    uint32_t b0h = bh[np][half], b1h = bh[np][2 + half];
                    uint32_t b0l = bl[np][half], b1l = bl[np][2 + half];
                    mma16816(acc[mf][nf], ah[mf], b0h, b1h);
                    mma16816(acc[mf][nf], ah[mf], b0l, b1l);
                    mma16816(acc[mf][nf], al[mf], b0h, b1h);
                }
            }
        }
        __syncthreads();
        if (s + 2 < NST) PREFETCH(s + 2);
    }

    #pragma unroll
    for (int mf = 0; mf < 4; mf++) {
        #pragma unroll
        for (int nf = 0; nf < 4; nf++) {
            int rr0 = row0 + mbase + mf * 16 + (lane >> 2);
            int cc0 = col0 + nbase + nf * 8 + (lane & 3) * 2;
            #pragma unroll
            for (int q = 0; q < 4; q++) {
                int row = rr0 + ((q >= 2) ? 8 : 0);
                int col = cc0 + (q & 1);
                float val = acc[mf][nf][q];
                if (epi == 0) {
                    C[(size_t)row * N + col] = val;
                } else {
                    int region = col >> 9;
                    int cr = col & 511;
                    int hh = cr >> 6, dd = cr & 63;
                    if (region == 0)      g_Q[((size_t)hh * S_LEN + row) * DH + dd] = val;
                    else if (region == 1) g_K[((size_t)hh * KL + row + NPM) * DH + dd] = val;
                    else                  g_V[((size_t)hh * KL + row + NPM) * DH + dd] = val;
                }
            }
        }
    }
}

// ---------------------------------------------------------------------------
// post_kernel: fuses rope_apply (Q/K + pm slots) and V transpose+split.
// ---------------------------------------------------------------------------
#define POST_ROPE_ROWS (HEADS * KL + HEADS * S_LEN)          // 65664
#define POST_ROPE_BLKS ((POST_ROPE_ROWS * 16 + 127) / 128)   // 8208
#define POST_VT_X   ((KL + 31) / 32)                          // 129
#define POST_VT_BLKS (POST_VT_X * (DH / 32) * HEADS)          // 2064
#define POST_BLKS (POST_ROPE_BLKS + POST_VT_BLKS)

__global__ __launch_bounds__(128) void post_kernel(const float* __restrict__ pm) {
    __shared__ float tile[32 * 33];
    const int b = blockIdx.x;
    const int tid = threadIdx.x;

    if (b < POST_ROPE_BLKS) {
        int gid = b * 128 + tid;
        int row = gid >> 4;
        int u   = gid & 15;
        const int KROWS = HEADS * KL;
        if (row >= POST_ROPE_ROWS) return;

        float4 x;
        size_t base;
        int pos;
        __nv_bfloat16 *dsth, *dstl;

        if (row < KROWS) {
            int h = row / KL, t = row % KL;
            pos = t;
            base = ((size_t)h * KL + t) * DH + 4 * u;
            if (t < NPM) {
                x = *(const float4*)(pm + (((size_t)0 * HEADS + h) * NPM + t) * DH + 4 * u);
                float4 vv = *(const float4*)(pm + (((size_t)1 * HEADS + h) * NPM + t) * DH + 4 * u);
                *(float4*)(g_V + base) = vv;
            } else {
                x = *(const float4*)(g_K + base);
            }
            dsth = g_Kh; dstl = g_Kl;
        } else {
            int rr = row - KROWS;
            int h = rr / S_LEN, s = rr % S_LEN;
            pos = s + NPM;
            base = ((size_t)h * S_LEN + s) * DH + 4 * u;
            x = *(const float4*)(g_Q + base);
            dsth = g_Qh; dstl = g_Ql;
        }

        float c0 = g_cos[pos * 32 + 2 * u],     s0 = g_sin[pos * 32 + 2 * u];
        float c1 = g_cos[pos * 32 + 2 * u + 1], s1 = g_sin[pos * 32 + 2 * u + 1];
        float r0 = x.x * c0 - x.y * s0;
        float r1 = x.y * c0 + x.x * s0;
        float r2 = x.z * c1 - x.w * s1;
        float r3 = x.w * c1 + x.z * s1;
        uint32_t h0, l0, h1, l1;
        split2(r0, r1, h0, l0);
        split2(r2, r3, h1, l1);
        *(uint2*)(dsth + base) = make_uint2(h0, h1);
        *(uint2*)(dstl + base) = make_uint2(l0, l1);
        return;
    }

    {
        int bb = b - POST_ROPE_BLKS;
        int h   = bb / (POST_VT_X * (DH / 32));
        int rem = bb % (POST_VT_X * (DH / 32));
        int d0  = (rem / POST_VT_X) * 32;
        int t0  = (rem % POST_VT_X) * 32;
        int tx = tid & 31, ty = tid >> 5;
        for (int r = ty; r < 32; r += 4) {
            int t = t0 + r;
            if (t < KL)
                tile[r * 33 + tx] = g_V[((size_t)h * KL + t) * DH + d0 + tx];
        }
        __syncthreads();
        for (int r = ty; r < 32; r += 4) {
            int d = d0 + r;
            int t = t0 + tx;
            if (t < KL) {
                float v = tile[tx * 33 + r];
                uint32_t uv = __float_as_uint(v) & 0xFFFF0000u;
                g_Vth[((size_t)(h * DH + d)) * KL + t] =
                    __ushort_as_bfloat16((unsigned short)(uv >> 16));
                g_Vtl[((size_t)(h * DH + d)) * KL + t] =
                    __float2bfloat16(v - __uint_as_float(uv));
            }
        }
    }
}

// ---------------------------------------------------------------------------
// 5) Tensor-core flash attention. 64 KB smem; __launch_bounds__(128,3)
//    forces regs <= 170 so 3 blocks/SM actually fit (round-11 ncu: 174 regs
//    capped us at 2 blocks/SM, occ 11.1%).
// ---------------------------------------------------------------------------
#define SWADDR(base, row, ch) ((base) + (uint32_t)(row) * 128u + \
                               ((uint32_t)((ch) ^ ((row) & 7)) << 4))

#define ATT_KVPF(TT) do {                                                     \
    int _t0 = ((TT) == 0) ? 0 : (NPM + seg * SEGLEN + ((TT) - 1) * 64);       \
    uint32_t _buf = sbase + (((TT) & 1) ? 32768u : 0u);                       \
    _Pragma("unroll")                                                         \
    for (int _k = 0; _k < 4; _k++) {                                          \
        int _i = tid + _k * 128;                                              \
        int _row = _i >> 3, _ch = _i & 7;                                     \
        uint32_t _d16 = (uint32_t)(_row * 8 + (_ch ^ (_row & 7))) * 16u;      \
        const __nv_bfloat16* _kh = g_Kh + ((size_t)h * KL + _t0 + _row) * DH + _ch * 8; \
        const __nv_bfloat16* _kl = g_Kl + ((size_t)h * KL + _t0 + _row) * DH + _ch * 8; \
        const __nv_bfloat16* _vh = g_Vth + ((size_t)(h * DH + _row)) * KL + _t0 + _ch * 8; \
        const __nv_bfloat16* _vl = g_Vtl + ((size_t)(h * DH + _row)) * KL + _t0 + _ch * 8; \
        CPA16(_buf + _d16,          _kh);                                     \
        CPA16(_buf + 8192u + _d16,  _kl);                                     \
        CPA16(_buf + 16384u + _d16, _vh);                                     \
        CPA16(_buf + 24576u + _d16, _vl);                                     \
    }                                                                         \
    asm volatile("cp.async.commit_group;");                                   \
} while (0)

__global__ __launch_bounds__(128, 3) void attn_mma_kernel() {
    extern __shared__ __align__(16) uint8_t asmem[];
    const uint32_t sbase = (uint32_t)__cvta_generic_to_shared(asmem);

    const int qt = 7 - blockIdx.x;             // heavy blocks first
    const int seg = blockIdx.y, h = blockIdx.z;
    const int tid = threadIdx.x;
    const int lane = tid & 31, w = tid >> 5;
    const int s0 = seg * SEGLEN + qt * 64;
    const int ntiles = qt + 2;

    ATT_KVPF(0);

    // stage Q into buf1 region (free until tile-1 prefetch below)
    const uint32_t qb = sbase + 32768u;
    for (int i = tid; i < 512; i += 128) {
        int row = i >> 3, ch = i & 7;
        int d = row * 8 + (ch ^ (row & 7));
        ((uint4*)(asmem + 32768))[d] =
            *((const uint4*)(g_Qh + ((size_t)h * S_LEN + s0 + row) * DH) + ch);
        ((uint4*)(asmem + 40960))[d] =
            *((const uint4*)(g_Ql + ((size_t)h * S_LEN + s0 + row) * DH) + ch);
    }
    __syncthreads();

    uint32_t qh[4][4], ql[4][4];
    {
        int row = w * 16 + (lane & 15);
        #pragma unroll
        for (int j = 0; j < 4; j++) {
            int ch = 2 * j + (lane >> 4);
            ldsm_x4(qh[j][0], qh[j][1], qh[j][2], qh[j][3], SWADDR(qb, row, ch));
            ldsm_x4(ql[j][0], ql[j][1], ql[j][2], ql[j][3], SWADDR(qb + 8192u, row, ch));
        }
    }
    __syncthreads();

    ATT_KVPF(1);

    float oacc[8][4];
    #pragma unroll
    for (int nf = 0; nf < 8; nf++)
        #pragma unroll
        for (int q = 0; q < 4; q++) oacc[nf][q] = 0.0f;
    float mrun[2] = {-INFINITY, -INFINITY};
    float lrun[2] = {0.0f, 0.0f};

    const float SC = 0.125f * 1.44269504088896341f;
    const int r1 = lane >> 2;
    const int cbase = (lane & 3) * 2;

    for (int tt = 0; tt < ntiles; tt++) {
        const bool ismem = (tt == 0);
        const bool diag = (!ismem) && ((tt - 1) == qt);

        if (tt + 1 < ntiles) asm volatile("cp.async.wait_group 1;");
        else                 asm volatile("cp.async.wait_group 0;");
        __syncthreads();

        const uint32_t kb0 = sbase + ((tt & 1) ? 32768u : 0u);
        const uint32_t bKh = kb0, bKl = kb0 + 8192u;
        const uint32_t bVh = kb0 + 16384u, bVl = kb0 + 24576u;

        // ---- S = Q K^T (3-split), K frags loaded per-ng ----
        float sacc[8][4];
        #pragma unroll
        for (int nf = 0; nf < 8; nf++)
            #pragma unroll
            for (int q = 0; q < 4; q++) sacc[nf][q] = 0.0f;

        #pragma unroll
        for (int j = 0; j < 4; j++) {
            int ch = 2 * j + (lane >> 4);
            #pragma unroll
            for (int ng = 0; ng < 4; ng++) {
                if (ismem && ng > 0) break;
                int row = ng * 16 + (lane & 15);
                uint32_t kh[4], kl[4];
                ldsm_x4(kh[0], kh[1], kh[2], kh[3], SWADDR(bKh, row, ch));
                ldsm_x4(kl[0], kl[1], kl[2], kl[3], SWADDR(bKl, row, ch));
                #pragma unroll
                for (int sel = 0; sel < 2; sel++) {
                    const int nf = 2 * ng + sel;
                    mma16816(sacc[nf], qh[j], kh[sel], kh[2 + sel]);
                    mma16816(sacc[nf], qh[j], kl[sel], kl[2 + sel]);
                    mma16816(sacc[nf], ql[j], kh[sel], kh[2 + sel]);
                }
            }
        }

        // ---- scale + mask (exp2 domain) ----
        #pragma unroll
        for (int nf = 0; nf < 8; nf++) {
            #pragma unroll
            for (int q = 0; q < 4; q++) {
                int col = nf * 8 + cbase + (q & 1);
                int qrow = w * 16 + r1 + ((q >= 2) ? 8 : 0);
                float v = sacc[nf][q] * SC;
                bool bad = (ismem && col >= 16) || (diag && col > qrow);
                sacc[nf][q] = bad ? -INFINITY : v;
            }
        }

        // ---- row max ----
        float ml[2] = {-INFINITY, -INFINITY};
        #pragma unroll
        for (int nf = 0; nf < 8; nf++) {
            ml[0] = fmaxf(ml[0], fmaxf(sacc[nf][0], sacc[nf][1]));
            ml[1] = fmaxf(ml[1], fmaxf(sacc[nf][2], sacc[nf][3]));
        }
        #pragma unroll
        for (int o = 1; o <= 2; o <<= 1) {
            ml[0] = fmaxf(ml[0], __shfl_xor_sync(0xffffffffu, ml[0], o));
            ml[1] = fmaxf(ml[1], __shfl_xor_sync(0xffffffffu, ml[1], o));
        }
        float mnew0 = fmaxf(mrun[0], ml[0]);
        float mnew1 = fmaxf(mrun[1], ml[1]);
        float corr0 = ex2(mrun[0] - mnew0);
        float corr1 = ex2(mrun[1] - mnew1);
        mrun[0] = mnew0; mrun[1] = mnew1;

        // ---- p = exp2(s - m), row sums ----
        float ls[2] = {0.0f, 0.0f};
        #pragma unroll
        for (int nf = 0; nf < 8; nf++) {
            float p0 = ex2(sacc[nf][0] - mnew0);
            float p1 = ex2(sacc[nf][1] - mnew0);
            float p2 = ex2(sacc[nf][2] - mnew1);
            float p3 = ex2(sacc[nf][3] - mnew1);
            sacc[nf][0] = p0; sacc[nf][1] = p1; sacc[nf][2] = p2; sacc[nf][3] = p3;
            ls[0] += p0 + p1; ls[1] += p2 + p3;
        }
        #pragma unroll
        for (int o = 1; o <= 2; o <<= 1) {
            ls[0] += __shfl_xor_sync(0xffffffffu, ls[0], o);
            ls[1] += __shfl_xor_sync(0xffffffffu, ls[1], o);
        }
        lrun[0] = lrun[0] * corr0 + ls[0];
        lrun[1] = lrun[1] * corr1 + ls[1];

        #pragma unroll
        for (int nf = 0; nf < 8; nf++) {
            oacc[nf][0] *= corr0; oacc[nf][1] *= corr0;
            oacc[nf][2] *= corr1; oacc[nf][3] *= corr1;
        }

        // ---- O += P V^T (3-split), V frags loaded per-dg ----
        #pragma unroll
        for (int j = 0; j < 4; j++) {
            if (ismem && j > 0) break;
            uint32_t pa_h[4], pa_l[4];
            split2(sacc[2*j][0],   sacc[2*j][1],   pa_h[0], pa_l[0]);
            split2(sacc[2*j][2],   sacc[2*j][3],   pa_h[1], pa_l[1]);
            split2(sacc[2*j+1][0], sacc[2*j+1][1], pa_h[2], pa_l[2]);
            split2(sacc[2*j+1][2], sacc[2*j+1][3], pa_h[3], pa_l[3]);

            int ch = 2 * j + (lane >> 4);
            #pragma unroll
            for (int dg = 0; dg < 4; dg++) {
                int row = dg * 16 + (lane & 15);
                uint32_t vh[4], vl[4];
                ldsm_x4(vh[0], vh[1], vh[2], vh[3], SWADDR(bVh, row, ch));
                ldsm_x4(vl[0], vl[1], vl[2], vl[3], SWADDR(bVl, row, ch));
                #pragma unroll
                for (int sel = 0; sel < 2; sel++) {
                    const int nf = 2 * dg + sel;
                    mma16816(oacc[nf], pa_h, vh[sel], vh[2 + sel]);
                    mma16816(oacc[nf], pa_h, vl[sel], vl[2 + sel]);
                    mma16816(oacc[nf], pa_l, vh[sel], vh[2 + sel]);
                }
            }
        }

        __syncthreads();
        if (tt + 2 < ntiles) ATT_KVPF(tt + 2);
    }

    float inv0 = 1.0f / lrun[0];
    float inv1 = 1.0f / lrun[1];
    int qrow = s0 + w * 16 + r1;
    #pragma unroll
    for (int nf = 0; nf < 8; nf++) {
        int col = h * DH + nf * 8 + cbase;
        uint32_t h0, l0, h1, l1;
        split2(oacc[nf][0] * inv0, oacc[nf][1] * inv0, h0, l0);
        split2(oacc[nf][2] * inv1, oacc[nf][3] * inv1, h1, l1);
        *(uint32_t*)(g_Ah + (size_t)qrow * DIM + col)       = h0;
        *(uint32_t*)(g_Al + (size_t)qrow * DIM + col)       = l0;
        *(uint32_t*)(g_Ah + (size_t)(qrow + 8) * DIM + col) = h1;
        *(uint32_t*)(g_Al + (size_t)(qrow + 8) * DIM + col) = l1;
    }
}

// ---------------------------------------------------------------------------
// Launch: 5 kernels (prep -> GEMM1 -> post -> attn -> GEMM2)
// ---------------------------------------------------------------------------
extern "C" void kernel_launch(void* const* d_in, const int* in_sizes, int n_in,
                              void* d_out, int out_size) {
    const float* seq    = (const float*)d_in[0];
    const float* norm_w = (const float*)d_in[1];
    const float* w_qkv  = (const float*)d_in[2];
    const float* w_out  = (const float*)d_in[3];
    const float* pm     = (const float*)d_in[4];

    __nv_bfloat16 *xh, *xl, *wqh, *wql, *woh, *wol, *ah, *al;
    cudaGetSymbolAddress((void**)&xh,  g_Xh);
    cudaGetSymbolAddress((void**)&xl,  g_Xl);
    cudaGetSymbolAddress((void**)&wqh, g_WqkvTh);
    cudaGetSymbolAddress((void**)&wql, g_WqkvTl);
    cudaGetSymbolAddress((void**)&woh, g_WoutTh);
    cudaGetSymbolAddress((void**)&wol, g_WoutTl);
    cudaGetSymbolAddress((void**)&ah,  g_Ah);
    cudaGetSymbolAddress((void**)&al,  g_Al);

    cudaFuncSetAttribute(mm2_kernel,
                         cudaFuncAttributeMaxDynamicSharedMemorySize, 81920);
    cudaFuncSetAttribute(attn_mma_kernel,
                         cudaFuncAttributeMaxDynamicSharedMemorySize, 65536);

    prep_kernel<<<PREP_BLKS, 128>>>(seq, norm_w, w_qkv, w_out);

    mm2_kernel<<<dim3(QKV_N / 128, S_LEN / 128), 256, 81920>>>(
        xh, xl, wqh, wql, nullptr, QKV_N, DIM, 1);

    post_kernel<<<POST_BLKS, 128>>>(pm);

    attn_mma_kernel<<<dim3(8, 8, 8), 128, 65536>>>();

    mm2_kernel<<<dim3(DIM / 128, S_LEN / 128), 256, 81920>>>(
        ah, al, woh, wol, (float*)d_out, DIM, DIM, 0);
}

// round 14
// speedup vs baseline: 2.5513x; 1.0035x over previous
#include <cuda_runtime.h>
#include <cuda_bf16.h>
#include <cstdint>
#include <math.h>

// ---------------------------------------------------------------------------
// Problem constants
// ---------------------------------------------------------------------------
#define S_LEN 4096
#define DIM   512
#define HEADS 8
#define DH    64
#define NPM   16
#define SEGLEN 512
#define KL    (S_LEN + NPM)        // 4112 keys after memory prepend
#define QKV_N (3 * HEADS * DH)     // 1536

// ---------------------------------------------------------------------------
// Scratch (device globals: no allocation allowed)
// ---------------------------------------------------------------------------
__device__ float g_V[HEADS * KL * DH];        // fp32 [h][t][d]
__device__ float g_cos[KL * 32];
__device__ float g_sin[KL * 32];
// pre-split bf16 operands
__device__ __align__(16) __nv_bfloat16 g_Xh[S_LEN * DIM];
__device__ __align__(16) __nv_bfloat16 g_Xl[S_LEN * DIM];
__device__ __align__(16) __nv_bfloat16 g_WqkvTh[QKV_N * DIM];  // [n][k]
__device__ __align__(16) __nv_bfloat16 g_WqkvTl[QKV_N * DIM];
__device__ __align__(16) __nv_bfloat16 g_WoutTh[DIM * DIM];    // [n][k]
__device__ __align__(16) __nv_bfloat16 g_WoutTl[DIM * DIM];
__device__ __align__(16) __nv_bfloat16 g_Ah[S_LEN * DIM];      // attention out
__device__ __align__(16) __nv_bfloat16 g_Al[S_LEN * DIM];
// attention operands (rope'd, split)
__device__ __align__(16) __nv_bfloat16 g_Qh[HEADS * S_LEN * DH];
__device__ __align__(16) __nv_bfloat16 g_Ql[HEADS * S_LEN * DH];
__device__ __align__(16) __nv_bfloat16 g_Kh[HEADS * KL * DH];
__device__ __align__(16) __nv_bfloat16 g_Kl[HEADS * KL * DH];
__device__ __align__(16) __nv_bfloat16 g_Vth[HEADS * DH * KL]; // [h][d][t]
__device__ __align__(16) __nv_bfloat16 g_Vtl[HEADS * DH * KL];

// ---------------------------------------------------------------------------
// helpers
// ---------------------------------------------------------------------------
__device__ __forceinline__ void split2(float a0, float a1,
                                       uint32_t& hi, uint32_t& lo) {
    uint32_t u0 = __float_as_uint(a0), u1 = __float_as_uint(a1);
    asm("prmt.b32 %0, %1, %2, 0x7632;" : "=r"(hi) : "r"(u0), "r"(u1));
    float r0 = a0 - __uint_as_float(u0 & 0xFFFF0000u);
    float r1 = a1 - __uint_as_float(u1 & 0xFFFF0000u);
    asm("cvt.rn.bf16x2.f32 %0, %1, %2;" : "=r"(lo) : "f"(r1), "f"(r0));
}

__device__ __forceinline__ float ex2(float x) {
    float r; asm("ex2.approx.f32 %0, %1;" : "=f"(r) : "f"(x)); return r;
}

__device__ __forceinline__ void ldsm_x4(uint32_t& r0, uint32_t& r1,
                                        uint32_t& r2, uint32_t& r3, uint32_t addr) {
    asm volatile("ldmatrix.sync.aligned.m8n8.x4.shared.b16 {%0,%1,%2,%3}, [%4];"
                 : "=r"(r0), "=r"(r1), "=r"(r2), "=r"(r3) : "r"(addr));
}

__device__ __forceinline__ void mma16816(float* c, const uint32_t* a,
                                         uint32_t b0, uint32_t b1) {
    asm volatile(
        "mma.sync.aligned.m16n8k16.row.col.f32.bf16.bf16.f32 "
        "{%0,%1,%2,%3}, {%4,%5,%6,%7}, {%8,%9}, {%0,%1,%2,%3};"
        : "+f"(c[0]), "+f"(c[1]), "+f"(c[2]), "+f"(c[3])
        : "r"(a[0]), "r"(a[1]), "r"(a[2]), "r"(a[3]), "r"(b0), "r"(b1));
}

#define CPA16(dst, src) \
    asm volatile("cp.async.cg.shared.global [%0], [%1], 16;" \
                 :: "r"(dst), "l"(src))

// ---------------------------------------------------------------------------
// prep_kernel: rope_table + RMSNorm/convert_x + wtrans(w_qkv) + wtrans(w_out)
// + pm memory slots (K rope t<16 + pm->V copy; cos/sin computed inline with
// the SAME formula as the table -> bit-identical, no intra-kernel dependency).
// Running pm slots here guarantees g_V[t<16] is written BEFORE post_kernel's
// vtrans reads it (the round-13 race).
// ---------------------------------------------------------------------------
#define PREP_TBL_BLKS  1028
#define PREP_CVX_BLKS  4096
#define PREP_WQ_BLKS   768
#define PREP_WO_BLKS   256
#define PREP_PM_BLKS   16     // 128 rows (h*16+t) x 16 threads
#define PREP_BLKS (PREP_TBL_BLKS + PREP_CVX_BLKS + PREP_WQ_BLKS + \
                   PREP_WO_BLKS + PREP_PM_BLKS)

__device__ __forceinline__ void wtrans_body(const float* __restrict__ src,
                                            __nv_bfloat16* __restrict__ dh,
                                            __nv_bfloat16* __restrict__ dl,
                                            int K, int N, int n0, int k0,
                                            int tid, float* tile /*32*33*/) {
    int tx = tid & 31, ty = tid >> 5;
    for (int r = ty; r < 32; r += 4)
        tile[r * 33 + tx] = src[(size_t)(k0 + r) * N + n0 + tx];
    __syncthreads();
    for (int r = ty; r < 32; r += 4) {
        int n = n0 + r, k = k0 + tx;
        float v = tile[tx * 33 + r];
        uint32_t uv = __float_as_uint(v) & 0xFFFF0000u;
        dh[(size_t)n * K + k] = __ushort_as_bfloat16((unsigned short)(uv >> 16));
        dl[(size_t)n * K + k] = __float2bfloat16(v - __uint_as_float(uv));
    }
}

__global__ __launch_bounds__(128) void prep_kernel(
    const float* __restrict__ seq, const float* __restrict__ norm_w,
    const float* __restrict__ w_qkv, const float* __restrict__ w_out,
    const float* __restrict__ pm)
{
    __shared__ float smem[32 * 33];
    const int b = blockIdx.x;
    const int tid = threadIdx.x;

    if (b < PREP_TBL_BLKS) {
        int idx = b * 128 + tid;
        if (idx < KL * 32) {
            int pos = idx >> 5, j = idx & 31;
            float rf  = (float)pow(10000.0, -(double)j / 32.0);
            float ang = (float)pos * rf;
            float s, c;
            sincosf(ang, &s, &c);
            g_cos[idx] = c;
            g_sin[idx] = s;
        }
        return;
    }
    if (b < PREP_TBL_BLKS + PREP_CVX_BLKS) {
        int s = b - PREP_TBL_BLKS;
        float4 v = ((const float4*)(seq + (size_t)s * DIM))[tid];
        float p = v.x * v.x + v.y * v.y + v.z * v.z + v.w * v.w;
        #pragma unroll
        for (int o = 16; o; o >>= 1) p += __shfl_xor_sync(0xffffffffu, p, o);
        if ((tid & 31) == 0) smem[tid >> 5] = p;
        __syncthreads();
        float rs = rsqrtf((smem[0] + smem[1] + smem[2] + smem[3])
                          * (1.0f / (float)DIM) + 1.1920928955078125e-07f);
        float4 w = ((const float4*)norm_w)[tid];
        v.x *= rs * w.x; v.y *= rs * w.y; v.z *= rs * w.z; v.w *= rs * w.w;
        uint32_t h0, l0, h1, l1;
        split2(v.x, v.y, h0, l0);
        split2(v.z, v.w, h1, l1);
        ((uint2*)(g_Xh + (size_t)s * DIM))[tid] = make_uint2(h0, h1);
        ((uint2*)(g_Xl + (size_t)s * DIM))[tid] = make_uint2(l0, l1);
        return;
    }
    if (b < PREP_TBL_BLKS + PREP_CVX_BLKS + PREP_WQ_BLKS) {
        int bb = b - PREP_TBL_BLKS - PREP_CVX_BLKS;
        int n0 = (bb % (QKV_N / 32)) * 32;
        int k0 = (bb / (QKV_N / 32)) * 32;
        wtrans_body(w_qkv, g_WqkvTh, g_WqkvTl, DIM, QKV_N, n0, k0, tid, smem);
        return;
    }
    if (b < PREP_TBL_BLKS + PREP_CVX_BLKS + PREP_WQ_BLKS + PREP_WO_BLKS) {
        int bb = b - PREP_TBL_BLKS - PREP_CVX_BLKS - PREP_WQ_BLKS;
        int n0 = (bb % (DIM / 32)) * 32;
        int k0 = (bb / (DIM / 32)) * 32;
        wtrans_body(w_out, g_WoutTh, g_WoutTl, DIM, DIM, n0, k0, tid, smem);
        return;
    }
    {
        // ---- pm memory slots: rope K rows t<16 (pos=t), copy pm -> V ----
        int bb = b - PREP_TBL_BLKS - PREP_CVX_BLKS - PREP_WQ_BLKS - PREP_WO_BLKS;
        int gid = bb * 128 + tid;
        int row = gid >> 4;              // 0..127 = h*16 + t
        int u   = gid & 15;              // pairs (2u, 2u+1)
        int h = row >> 4, t = row & 15;
        size_t base = ((size_t)h * KL + t) * DH + 4 * u;
        float4 x  = *(const float4*)(pm + (((size_t)0 * HEADS + h) * NPM + t) * DH + 4 * u);
        float4 vv = *(const float4*)(pm + (((size_t)1 * HEADS + h) * NPM + t) * DH + 4 * u);
        *(float4*)(g_V + base) = vv;
        // inline cos/sin, identical formula to table blocks (bit-identical)
        int j0 = 2 * u, j1 = 2 * u + 1;
        float rf0 = (float)pow(10000.0, -(double)j0 / 32.0);
        float rf1 = (float)pow(10000.0, -(double)j1 / 32.0);
        float s0, c0, s1, c1;
        sincosf((float)t * rf0, &s0, &c0);
        sincosf((float)t * rf1, &s1, &c1);
        float r0 = x.x * c0 - x.y * s0;
        float r1 = x.y * c0 + x.x * s0;
        float r2 = x.z * c1 - x.w * s1;
        float r3 = x.w * c1 + x.z * s1;
        uint32_t h0, l0, h1, l1;
        split2(r0, r1, h0, l0);
        split2(r2, r3, h1, l1);
        *(uint2*)(g_Kh + base) = make_uint2(h0, h1);
        *(uint2*)(g_Kl + base) = make_uint2(l0, l1);
    }
}

// ---------------------------------------------------------------------------
// 3) bf16 split GEMM, cp.async double-buffered (mainloop verified r7-r12).
// epi==1 epilogue applies RoPE + split for Q/K in-register (each thread holds
// the full rotation pair (col, col+1), col even; pos = row + NPM for both).
// V region stores fp32 for the transpose pass.
// ---------------------------------------------------------------------------
#define STG_A_H 0
#define STG_A_L 10240
#define STG_B_H 20480
#define STG_B_L 30720
#define STG_SZ  40960

#define PREFETCH(S) do {                                                      \
    int _k0 = (S) * 32;                                                       \
    uint32_t _b = sbase + ((S) & 1) * STG_SZ + r * 80 + cg * 16;              \
    const __nv_bfloat16* _ag = Ah + (size_t)(row0 + r) * K + _k0 + cg * 8;    \
    const __nv_bfloat16* _al = Al + (size_t)(row0 + r) * K + _k0 + cg * 8;    \
    const __nv_bfloat16* _bg = Bh + (size_t)(col0 + r) * K + _k0 + cg * 8;    \
    const __nv_bfloat16* _bl = Bl + (size_t)(col0 + r) * K + _k0 + cg * 8;    \
    CPA16(_b + STG_A_H,      _ag);                                            \
    CPA16(_b + STG_A_H + 16, _ag + 8);                                        \
    CPA16(_b + STG_A_L,      _al);                                            \
    CPA16(_b + STG_A_L + 16, _al + 8);                                        \
    CPA16(_b + STG_B_H,      _bg);                                            \
    CPA16(_b + STG_B_H + 16, _bg + 8);                                        \
    CPA16(_b + STG_B_L,      _bl);                                            \
    CPA16(_b + STG_B_L + 16, _bl + 8);                                        \
    asm volatile("cp.async.commit_group;");                                   \
} while (0)

__global__ __launch_bounds__(256) void mm2_kernel(
    const __nv_bfloat16* __restrict__ Ah, const __nv_bfloat16* __restrict__ Al,
    const __nv_bfloat16* __restrict__ Bh, const __nv_bfloat16* __restrict__ Bl,
    float* __restrict__ C, int N, int K, int epi)
{
    extern __shared__ __align__(16) uint8_t smem[];
    const uint32_t sbase = (uint32_t)__cvta_generic_to_shared(smem);

    const int tid  = threadIdx.x;
    const int lane = tid & 31, warp = tid >> 5;
    const int wm = warp & 1, wn = warp >> 1;
    const int row0 = blockIdx.y * 128, col0 = blockIdx.x * 128;

    const int r  = tid >> 1;
    const int cg = (tid & 1) * 2;

    const int NST = K / 32;

    float acc[4][4][4];
    #pragma unroll
    for (int i = 0; i < 4; i++)
        #pragma unroll
        for (int j = 0; j < 4; j++)
            #pragma unroll
            for (int q = 0; q < 4; q++) acc[i][j][q] = 0.0f;

    PREFETCH(0);
    PREFETCH(1);

    const int mbase = wm * 64, nbase = wn * 32;
    const int lr = lane & 15, lh = (lane >> 4) * 16;

    for (int s = 0; s < NST; s++) {
        if (s + 1 < NST) asm volatile("cp.async.wait_group 1;");
        else             asm volatile("cp.async.wait_group 0;");
        __syncthreads();

        const uint32_t bAh = sbase + (s & 1) * STG_SZ + STG_A_H;
        const uint32_t bAl = sbase + (s & 1) * STG_SZ + STG_A_L;
        const uint32_t bBh = sbase + (s & 1) * STG_SZ + STG_B_H;
        const uint32_t bBl = sbase + (s & 1) * STG_SZ + STG_B_L;

        #pragma unroll
        for (int kk = 0; kk < 2; kk++) {
            const uint32_t kb = (uint32_t)(kk * 32 + lh);
            uint32_t ah[4][4], al[4][4], bh[2][4], bl[2][4];
            #pragma unroll
            for (int mf = 0; mf < 4; mf++) {
                uint32_t ro = (uint32_t)(mbase + mf * 16 + lr) * 80 + kb;
                ldsm_x4(ah[mf][0], ah[mf][1], ah[mf][2], ah[mf][3], bAh + ro);
                ldsm_x4(al[mf][0], al[mf][1], al[mf][2], al[mf][3], bAl + ro);
            }
            #pragma unroll
            for (int np = 0; np < 2; np++) {
                uint32_t ro = (uint32_t)(nbase + np * 16 + lr) * 80 + kb;
                ldsm_x4(bh[np][0], bh[np][1], bh[np][2], bh[np][3], bBh + ro);
                ldsm_x4(bl[np][0], bl[np][1], bl[np][2], bl[np][3], bBl + ro);
            }
            #pragma unroll
            for (int mf = 0; mf < 4; mf++) {
                #pragma unroll
                for (int nf = 0; nf < 4; nf++) {
                    const int np = nf >> 1, half = nf & 1;
                    uint32_t b0h = bh[np][half], b1h = bh[np][2 + half];
                    uint32_t b0l = bl[np][half], b1l = bl[np][2 + half];
                    mma16816(acc[mf][nf], ah[mf], b0h, b1h);
                    mma16816(acc[mf][nf], ah[mf], b0l, b1l);
                    mma16816(acc[mf][nf], al[mf], b0h, b1h);
                }
            }
        }
        __syncthreads();
        if (s + 2 < NST) PREFETCH(s + 2);
    }

    #pragma unroll
    for (int mf = 0; mf < 4; mf++) {
        #pragma unroll
        for (int nf = 0; nf < 4; nf++) {
            int rr0 = row0 + mbase + mf * 16 + (lane >> 2);
            int col = col0 + nbase + nf * 8 + (lane & 3) * 2;   // even
            #pragma unroll
            for (int half = 0; half < 2; half++) {
                int row = rr0 + half * 8;
                float v0 = acc[mf][nf][half * 2 + 0];
                float v1 = acc[mf][nf][half * 2 + 1];
                if (epi == 0) {
                    *(float2*)(C + (size_t)row * N + col) = make_float2(v0, v1);
                } else {
                    int region = col >> 9;          // 0:q 1:k 2:v
                    int cr = col & 511;
                    int hh = cr >> 6, dd = cr & 63; // dd even
                    if (region == 2) {
                        *(float2*)(g_V + ((size_t)hh * KL + row + NPM) * DH + dd)
                            = make_float2(v0, v1);
                    } else {
                        int pos = row + NPM;        // same for Q and K
                        float c  = g_cos[pos * 32 + (dd >> 1)];
                        float sn = g_sin[pos * 32 + (dd >> 1)];
                        float r1 = v0 * c - v1 * sn;
                        float r2 = v1 * c + v0 * sn;
                        uint32_t hi, lo;
                        split2(r1, r2, hi, lo);
                        if (region == 0) {
                            size_t base = ((size_t)hh * S_LEN + row) * DH + dd;
                            *(uint32_t*)(g_Qh + base) = hi;
                            *(uint32_t*)(g_Ql + base) = lo;
                        } else {
                            size_t base = ((size_t)hh * KL + row + NPM) * DH + dd;
                            *(uint32_t*)(g_Kh + base) = hi;
                            *(uint32_t*)(g_Kl + base) = lo;
                        }
                    }
                }
            }
        }
    }
}

// ---------------------------------------------------------------------------
// post_kernel: V transpose + split only (g_V fully written by prep + GEMM1).
// ---------------------------------------------------------------------------
#define POST_VT_X   ((KL + 31) / 32)                          // 129
#define POST_BLKS (POST_VT_X * (DH / 32) * HEADS)             // 2064

__global__ __launch_bounds__(128) void post_kernel() {
    __shared__ float tile[32 * 33];
    const int b = blockIdx.x;
    const int tid = threadIdx.x;

    int h   = b / (POST_VT_X * (DH / 32));
    int rem = b % (POST_VT_X * (DH / 32));
    int d0  = (rem / POST_VT_X) * 32;
    int t0  = (rem % POST_VT_X) * 32;
    int tx = tid & 31, ty = tid >> 5;
    for (int r = ty; r < 32; r += 4) {
        int t = t0 + r;
        if (t < KL)
            tile[r * 33 + tx] = g_V[((size_t)h * KL + t) * DH + d0 + tx];
    }
    __syncthreads();
    for (int r = ty; r < 32; r += 4) {
        int d = d0 + r;
        int t = t0 + tx;
        if (t < KL) {
            float v = tile[tx * 33 + r];
            uint32_t uv = __float_as_uint(v) & 0xFFFF0000u;
            g_Vth[((size_t)(h * DH + d)) * KL + t] =
                __ushort_as_bfloat16((unsigned short)(uv >> 16));
            g_Vtl[((size_t)(h * DH + d)) * KL + t] =
                __float2bfloat16(v - __uint_as_float(uv));
        }
    }
}

// ---------------------------------------------------------------------------
// 5) Tensor-core flash attention (verified round 12, unchanged).
// ---------------------------------------------------------------------------
#define SWADDR(base, row, ch) ((base) + (uint32_t)(row) * 128u + \
                               ((uint32_t)((ch) ^ ((row) & 7)) << 4))

#define ATT_KVPF(TT) do {                                                     \
    int _t0 = ((TT) == 0) ? 0 : (NPM + seg * SEGLEN + ((TT) - 1) * 64);       \
    uint32_t _buf = sbase + (((TT) & 1) ? 32768u : 0u);                       \
    _Pragma("unroll")                                                         \
    for (int _k = 0; _k < 4; _k++) {                                          \
        int _i = tid + _k * 128;                                              \
        int _row = _i >> 3, _ch = _i & 7;                                     \
        uint32_t _d16 = (uint32_t)(_row * 8 + (_ch ^ (_row & 7))) * 16u;      \
        const __nv_bfloat16* _kh = g_Kh + ((size_t)h * KL + _t0 + _row) * DH + _ch * 8; \
        const __nv_bfloat16* _kl = g_Kl + ((size_t)h * KL + _t0 + _row) * DH + _ch * 8; \
        const __nv_bfloat16* _vh = g_Vth + ((size_t)(h * DH + _row)) * KL + _t0 + _ch * 8; \
        const __nv_bfloat16* _vl = g_Vtl + ((size_t)(h * DH + _row)) * KL + _t0 + _ch * 8; \
        CPA16(_buf + _d16,          _kh);                                     \
        CPA16(_buf + 8192u + _d16,  _kl);                                     \
        CPA16(_buf + 16384u + _d16, _vh);                                     \
        CPA16(_buf + 24576u + _d16, _vl);                                     \
    }                                                                         \
    asm volatile("cp.async.commit_group;");                                   \
} while (0)

__global__ __launch_bounds__(128, 3) void attn_mma_kernel() {
    extern __shared__ __align__(16) uint8_t asmem[];
    const uint32_t sbase = (uint32_t)__cvta_generic_to_shared(asmem);

    const int qt = 7 - blockIdx.x;             // heavy blocks first
    const int seg = blockIdx.y, h = blockIdx.z;
    const int tid = threadIdx.x;
    const int lane = tid & 31, w = tid >> 5;
    const int s0 = seg * SEGLEN + qt * 64;
    const int ntiles = qt + 2;

    ATT_KVPF(0);

    const uint32_t qb = sbase + 32768u;
    for (int i = tid; i < 512; i += 128) {
        int row = i >> 3, ch = i & 7;
        int d = row * 8 + (ch ^ (row & 7));
        ((uint4*)(asmem + 32768))[d] =
            *((const uint4*)(g_Qh + ((size_t)h * S_LEN + s0 + row) * DH) + ch);
        ((uint4*)(asmem + 40960))[d] =
            *((const uint4*)(g_Ql + ((size_t)h * S_LEN + s0 + row) * DH) + ch);
    }
    __syncthreads();

    uint32_t qh[4][4], ql[4][4];
    {
        int row = w * 16 + (lane & 15);
        #pragma unroll
        for (int j = 0; j < 4; j++) {
            int ch = 2 * j + (lane >> 4);
            ldsm_x4(qh[j][0], qh[j][1], qh[j][2], qh[j][3], SWADDR(qb, row, ch));
            ldsm_x4(ql[j][0], ql[j][1], ql[j][2], ql[j][3], SWADDR(qb + 8192u, row, ch));
        }
    }
    __syncthreads();

    ATT_KVPF(1);

    float oacc[8][4];
    #pragma unroll
    for (int nf = 0; nf < 8; nf++)
        #pragma unroll
        for (int q = 0; q < 4; q++) oacc[nf][q] = 0.0f;
    float mrun[2] = {-INFINITY, -INFINITY};
    float lrun[2] = {0.0f, 0.0f};

    const float SC = 0.125f * 1.44269504088896341f;
    const int r1 = lane >> 2;
    const int cbase = (lane & 3) * 2;

    for (int tt = 0; tt < ntiles; tt++) {
        const bool ismem = (tt == 0);
        const bool diag = (!ismem) && ((tt - 1) == qt);

        if (tt + 1 < ntiles) asm volatile("cp.async.wait_group 1;");
        else                 asm volatile("cp.async.wait_group 0;");
        __syncthreads();

        const uint32_t kb0 = sbase + ((tt & 1) ? 32768u : 0u);
        const uint32_t bKh = kb0, bKl = kb0 + 8192u;
        const uint32_t bVh = kb0 + 16384u, bVl = kb0 + 24576u;

        float sacc[8][4];
        #pragma unroll
        for (int nf = 0; nf < 8; nf++)
            #pragma unroll
            for (int q = 0; q < 4; q++) sacc[nf][q] = 0.0f;

        #pragma unroll
        for (int j = 0; j < 4; j++) {
            int ch = 2 * j + (lane >> 4);
            #pragma unroll
            for (int ng = 0; ng < 4; ng++) {
                if (ismem && ng > 0) break;
                int row = ng * 16 + (lane & 15);
                uint32_t kh[4], kl[4];
                ldsm_x4(kh[0], kh[1], kh[2], kh[3], SWADDR(bKh, row, ch));
                ldsm_x4(kl[0], kl[1], kl[2], kl[3], SWADDR(bKl, row, ch));
                #pragma unroll
                for (int sel = 0; sel < 2; sel++) {
                    const int nf = 2 * ng + sel;
                    mma16816(sacc[nf], qh[j], kh[sel], kh[2 + sel]);
                    mma16816(sacc[nf], qh[j], kl[sel], kl[2 + sel]);
                    mma16816(sacc[nf], ql[j], kh[sel], kh[2 + sel]);
                }
            }
        }

        #pragma unroll
        for (int nf = 0; nf < 8; nf++) {
            #pragma unroll
            for (int q = 0; q < 4; q++) {
                int col = nf * 8 + cbase + (q & 1);
                int qrow = w * 16 + r1 + ((q >= 2) ? 8 : 0);
                float v = sacc[nf][q] * SC;
                bool bad = (ismem && col >= 16) || (diag && col > qrow);
                sacc[nf][q] = bad ? -INFINITY : v;
            }
        }

        float ml[2] = {-INFINITY, -INFINITY};
        #pragma unroll
        for (int nf = 0; nf < 8; nf++) {
            ml[0] = fmaxf(ml[0], fmaxf(sacc[nf][0], sacc[nf][1]));
            ml[1] = fmaxf(ml[1], fmaxf(sacc[nf][2], sacc[nf][3]));
        }
        #pragma unroll
        for (int o = 1; o <= 2; o <<= 1) {
            ml[0] = fmaxf(ml[0], __shfl_xor_sync(0xffffffffu, ml[0], o));
            ml[1] = fmaxf(ml[1], __shfl_xor_sync(0xffffffffu, ml[1], o));
        }
        float mnew0 = fmaxf(mrun[0], ml[0]);
        float mnew1 = fmaxf(mrun[1], ml[1]);
        float corr0 = ex2(mrun[0] - mnew0);
        float corr1 = ex2(mrun[1] - mnew1);
        mrun[0] = mnew0; mrun[1] = mnew1;

        float ls[2] = {0.0f, 0.0f};
        #pragma unroll
        for (int nf = 0; nf < 8; nf++) {
            float p0 = ex2(sacc[nf][0] - mnew0);
            float p1 = ex2(sacc[nf][1] - mnew0);
            float p2 = ex2(sacc[nf][2] - mnew1);
            float p3 = ex2(sacc[nf][3] - mnew1);
            sacc[nf][0] = p0; sacc[nf][1] = p1; sacc[nf][2] = p2; sacc[nf][3] = p3;
            ls[0] += p0 + p1; ls[1] += p2 + p3;
        }
        #pragma unroll
        for (int o = 1; o <= 2; o <<= 1) {
            ls[0] += __shfl_xor_sync(0xffffffffu, ls[0], o);
            ls[1] += __shfl_xor_sync(0xffffffffu, ls[1], o);
        }
        lrun[0] = lrun[0] * corr0 + ls[0];
        lrun[1] = lrun[1] * corr1 + ls[1];

        #pragma unroll
        for (int nf = 0; nf < 8; nf++) {
            oacc[nf][0] *= corr0; oacc[nf][1] *= corr0;
            oacc[nf][2] *= corr1; oacc[nf][3] *= corr1;
        }

        #pragma unroll
        for (int j = 0; j < 4; j++) {
            if (ismem && j > 0) break;
            uint32_t pa_h[4], pa_l[4];
            split2(sacc[2*j][0],   sacc[2*j][1],   pa_h[0], pa_l[0]);
            split2(sacc[2*j][2],   sacc[2*j][3],   pa_h[1], pa_l[1]);
            split2(sacc[2*j+1][0], sacc[2*j+1][1], pa_h[2], pa_l[2]);
            split2(sacc[2*j+1][2], sacc[2*j+1][3], pa_h[3], pa_l[3]);

            int ch = 2 * j + (lane >> 4);
            #pragma unroll
            for (int dg = 0; dg < 4; dg++) {
                int row = dg * 16 + (lane & 15);
                uint32_t vh[4], vl[4];
                ldsm_x4(vh[0], vh[1], vh[2], vh[3], SWADDR(bVh, row, ch));
                ldsm_x4(vl[0], vl[1], vl[2], vl[3], SWADDR(bVl, row, ch));
                #pragma unroll
                for (int sel = 0; sel < 2; sel++) {
                    const int nf = 2 * dg + sel;
                    mma16816(oacc[nf], pa_h, vh[sel], vh[2 + sel]);
                    mma16816(oacc[nf], pa_h, vl[sel], vl[2 + sel]);
                    mma16816(oacc[nf], pa_l, vh[sel], vh[2 + sel]);
                }
            }
        }

        __syncthreads();
        if (tt + 2 < ntiles) ATT_KVPF(tt + 2);
    }

    float inv0 = 1.0f / lrun[0];
    float inv1 = 1.0f / lrun[1];
    int qrow = s0 + w * 16 + r1;
    #pragma unroll
    for (int nf = 0; nf < 8; nf++) {
        int col = h * DH + nf * 8 + cbase;
        uint32_t h0, l0, h1, l1;
        split2(oacc[nf][0] * inv0, oacc[nf][1] * inv0, h0, l0);
        split2(oacc[nf][2] * inv1, oacc[nf][3] * inv1, h1, l1);
        *(uint32_t*)(g_Ah + (size_t)qrow * DIM + col)       = h0;
        *(uint32_t*)(g_Al + (size_t)qrow * DIM + col)       = l0;
        *(uint32_t*)(g_Ah + (size_t)(qrow + 8) * DIM + col) = h1;
        *(uint32_t*)(g_Al + (size_t)(qrow + 8) * DIM + col) = l1;
    }
}

// ---------------------------------------------------------------------------
// Launch: 5 kernels (prep(+pm) -> GEMM1(+rope epi) -> post(vtrans) -> attn
// -> GEMM2)
// ---------------------------------------------------------------------------
extern "C" void kernel_launch(void* const* d_in, const int* in_sizes, int n_in,
                              void* d_out, int out_size) {
    const float* seq    = (const float*)d_in[0];
    const float* norm_w = (const float*)d_in[1];
    const float* w_qkv  = (const float*)d_in[2];
    const float* w_out  = (const float*)d_in[3];
    const float* pm     = (const float*)d_in[4];

    __nv_bfloat16 *xh, *xl, *wqh, *wql, *woh, *wol, *ah, *al;
    cudaGetSymbolAddress((void**)&xh,  g_Xh);
    cudaGetSymbolAddress((void**)&xl,  g_Xl);
    cudaGetSymbolAddress((void**)&wqh, g_WqkvTh);
    cudaGetSymbolAddress((void**)&wql, g_WqkvTl);
    cudaGetSymbolAddress((void**)&woh, g_WoutTh);
    cudaGetSymbolAddress((void**)&wol, g_WoutTl);
    cudaGetSymbolAddress((void**)&ah,  g_Ah);
    cudaGetSymbolAddress((void**)&al,  g_Al);

    cudaFuncSetAttribute(mm2_kernel,
                         cudaFuncAttributeMaxDynamicSharedMemorySize, 81920);
    cudaFuncSetAttribute(attn_mma_kernel,
                         cudaFuncAttributeMaxDynamicSharedMemorySize, 65536);

    prep_kernel<<<PREP_BLKS, 128>>>(seq, norm_w, w_qkv, w_out, pm);

    mm2_kernel<<<dim3(QKV_N / 128, S_LEN / 128), 256, 81920>>>(
        xh, xl, wqh, wql, nullptr, QKV_N, DIM, 1);

    post_kernel<<<POST_BLKS, 128>>>();

    attn_mma_kernel<<<dim3(8, 8, 8), 128, 65536>>>();

    mm2_kernel<<<dim3(DIM / 128, S_LEN / 128), 256, 81920>>>(
        ah, al, woh, wol, (float*)d_out, DIM, DIM, 0);
}

// round 15
// speedup vs baseline: 2.5671x; 1.0062x over previous
#include <cuda_runtime.h>
#include <cuda_bf16.h>
#include <cstdint>
#include <math.h>

// ---------------------------------------------------------------------------
// Problem constants
// ---------------------------------------------------------------------------
#define S_LEN 4096
#define DIM   512
#define HEADS 8
#define DH    64
#define NPM   16
#define SEGLEN 512
#define KL    (S_LEN + NPM)        // 4112 keys after memory prepend
#define QKV_N (3 * HEADS * DH)     // 1536

// scale * log2(e), folded into Q at the GEMM1 epilogue
#define SC_FOLD 0.1803368801111731f   // 0.125 * 1.44269504088896341

// ---------------------------------------------------------------------------
// Scratch (device globals: no allocation allowed)
// ---------------------------------------------------------------------------
__device__ float g_V[HEADS * KL * DH];        // fp32 [h][t][d]
__device__ float g_cos[KL * 32];
__device__ float g_sin[KL * 32];
// pre-split bf16 operands
__device__ __align__(16) __nv_bfloat16 g_Xh[S_LEN * DIM];
__device__ __align__(16) __nv_bfloat16 g_Xl[S_LEN * DIM];
__device__ __align__(16) __nv_bfloat16 g_WqkvTh[QKV_N * DIM];  // [n][k]
__device__ __align__(16) __nv_bfloat16 g_WqkvTl[QKV_N * DIM];
__device__ __align__(16) __nv_bfloat16 g_WoutTh[DIM * DIM];    // [n][k]
__device__ __align__(16) __nv_bfloat16 g_WoutTl[DIM * DIM];
__device__ __align__(16) __nv_bfloat16 g_Ah[S_LEN * DIM];      // attention out
__device__ __align__(16) __nv_bfloat16 g_Al[S_LEN * DIM];
// attention operands (rope'd, split; Q pre-scaled by SC_FOLD)
__device__ __align__(16) __nv_bfloat16 g_Qh[HEADS * S_LEN * DH];
__device__ __align__(16) __nv_bfloat16 g_Ql[HEADS * S_LEN * DH];
__device__ __align__(16) __nv_bfloat16 g_Kh[HEADS * KL * DH];
__device__ __align__(16) __nv_bfloat16 g_Kl[HEADS * KL * DH];
__device__ __align__(16) __nv_bfloat16 g_Vth[HEADS * DH * KL]; // [h][d][t]
__device__ __align__(16) __nv_bfloat16 g_Vtl[HEADS * DH * KL];

// ---------------------------------------------------------------------------
// helpers
// ---------------------------------------------------------------------------
__device__ __forceinline__ void split2(float a0, float a1,
                                       uint32_t& hi, uint32_t& lo) {
    uint32_t u0 = __float_as_uint(a0), u1 = __float_as_uint(a1);
    asm("prmt.b32 %0, %1, %2, 0x7632;" : "=r"(hi) : "r"(u0), "r"(u1));
    float r0 = a0 - __uint_as_float(u0 & 0xFFFF0000u);
    float r1 = a1 - __uint_as_float(u1 & 0xFFFF0000u);
    asm("cvt.rn.bf16x2.f32 %0, %1, %2;" : "=r"(lo) : "f"(r1), "f"(r0));
}

__device__ __forceinline__ float ex2(float x) {
    float r; asm("ex2.approx.f32 %0, %1;" : "=f"(r) : "f"(x)); return r;
}

__device__ __forceinline__ float rcp(float x) {
    float r; asm("rcp.approx.f32 %0, %1;" : "=f"(r) : "f"(x)); return r;
}

__device__ __forceinline__ void ldsm_x4(uint32_t& r0, uint32_t& r1,
                                        uint32_t& r2, uint32_t& r3, uint32_t addr) {
    asm volatile("ldmatrix.sync.aligned.m8n8.x4.shared.b16 {%0,%1,%2,%3}, [%4];"
                 : "=r"(r0), "=r"(r1), "=r"(r2), "=r"(r3) : "r"(addr));
}

__device__ __forceinline__ void mma16816(float* c, const uint32_t* a,
                                         uint32_t b0, uint32_t b1) {
    asm volatile(
        "mma.sync.aligned.m16n8k16.row.col.f32.bf16.bf16.f32 "
        "{%0,%1,%2,%3}, {%4,%5,%6,%7}, {%8,%9}, {%0,%1,%2,%3};"
        : "+f"(c[0]), "+f"(c[1]), "+f"(c[2]), "+f"(c[3])
        : "r"(a[0]), "r"(a[1]), "r"(a[2]), "r"(a[3]), "r"(b0), "r"(b1));
}

#define CPA16(dst, src) \
    asm volatile("cp.async.cg.shared.global [%0], [%1], 16;" \
                 :: "r"(dst), "l"(src))

// ---------------------------------------------------------------------------
// prep_kernel: rope_table + RMSNorm/convert_x + wtrans(w_qkv) + wtrans(w_out)
// + pm memory slots (K rope t<16 + pm->V copy; inline cos/sin, bit-identical
// to the table formula). Hard ordering: g_V[t<16] done before post's vtrans.
// ---------------------------------------------------------------------------
#define PREP_TBL_BLKS  1028
#define PREP_CVX_BLKS  4096
#define PREP_WQ_BLKS   768
#define PREP_WO_BLKS   256
#define PREP_PM_BLKS   16
#define PREP_BLKS (PREP_TBL_BLKS + PREP_CVX_BLKS + PREP_WQ_BLKS + \
                   PREP_WO_BLKS + PREP_PM_BLKS)

__device__ __forceinline__ void wtrans_body(const float* __restrict__ src,
                                            __nv_bfloat16* __restrict__ dh,
                                            __nv_bfloat16* __restrict__ dl,
                                            int K, int N, int n0, int k0,
                                            int tid, float* tile /*32*33*/) {
    int tx = tid & 31, ty = tid >> 5;
    for (int r = ty; r < 32; r += 4)
        tile[r * 33 + tx] = src[(size_t)(k0 + r) * N + n0 + tx];
    __syncthreads();
    for (int r = ty; r < 32; r += 4) {
        int n = n0 + r, k = k0 + tx;
        float v = tile[tx * 33 + r];
        uint32_t uv = __float_as_uint(v) & 0xFFFF0000u;
        dh[(size_t)n * K + k] = __ushort_as_bfloat16((unsigned short)(uv >> 16));
        dl[(size_t)n * K + k] = __float2bfloat16(v - __uint_as_float(uv));
    }
}

__global__ __launch_bounds__(128) void prep_kernel(
    const float* __restrict__ seq, const float* __restrict__ norm_w,
    const float* __restrict__ w_qkv, const float* __restrict__ w_out,
    const float* __restrict__ pm)
{
    __shared__ float smem[32 * 33];
    const int b = blockIdx.x;
    const int tid = threadIdx.x;

    if (b < PREP_TBL_BLKS) {
        int idx = b * 128 + tid;
        if (idx < KL * 32) {
            int pos = idx >> 5, j = idx & 31;
            float rf  = (float)pow(10000.0, -(double)j / 32.0);
            float ang = (float)pos * rf;
            float s, c;
            sincosf(ang, &s, &c);
            g_cos[idx] = c;
            g_sin[idx] = s;
        }
        return;
    }
    if (b < PREP_TBL_BLKS + PREP_CVX_BLKS) {
        int s = b - PREP_TBL_BLKS;
        float4 v = ((const float4*)(seq + (size_t)s * DIM))[tid];
        float p = v.x * v.x + v.y * v.y + v.z * v.z + v.w * v.w;
        #pragma unroll
        for (int o = 16; o; o >>= 1) p += __shfl_xor_sync(0xffffffffu, p, o);
        if ((tid & 31) == 0) smem[tid >> 5] = p;
        __syncthreads();
        float rs = rsqrtf((smem[0] + smem[1] + smem[2] + smem[3])
                          * (1.0f / (float)DIM) + 1.1920928955078125e-07f);
        float4 w = ((const float4*)norm_w)[tid];
        v.x *= rs * w.x; v.y *= rs * w.y; v.z *= rs * w.z; v.w *= rs * w.w;
        uint32_t h0, l0, h1, l1;
        split2(v.x, v.y, h0, l0);
        split2(v.z, v.w, h1, l1);
        ((uint2*)(g_Xh + (size_t)s * DIM))[tid] = make_uint2(h0, h1);
        ((uint2*)(g_Xl + (size_t)s * DIM))[tid] = make_uint2(l0, l1);
        return;
    }
    if (b < PREP_TBL_BLKS + PREP_CVX_BLKS + PREP_WQ_BLKS) {
        int bb = b - PREP_TBL_BLKS - PREP_CVX_BLKS;
        int n0 = (bb % (QKV_N / 32)) * 32;
        int k0 = (bb / (QKV_N / 32)) * 32;
        wtrans_body(w_qkv, g_WqkvTh, g_WqkvTl, DIM, QKV_N, n0, k0, tid, smem);
        return;
    }
    if (b < PREP_TBL_BLKS + PREP_CVX_BLKS + PREP_WQ_BLKS + PREP_WO_BLKS) {
        int bb = b - PREP_TBL_BLKS - PREP_CVX_BLKS - PREP_WQ_BLKS;
        int n0 = (bb % (DIM / 32)) * 32;
        int k0 = (bb / (DIM / 32)) * 32;
        wtrans_body(w_out, g_WoutTh, g_WoutTl, DIM, DIM, n0, k0, tid, smem);
        return;
    }
    {
        // ---- pm memory slots: rope K rows t<16 (pos=t), copy pm -> V ----
        int bb = b - PREP_TBL_BLKS - PREP_CVX_BLKS - PREP_WQ_BLKS - PREP_WO_BLKS;
        int gid = bb * 128 + tid;
        int row = gid >> 4;              // 0..127 = h*16 + t
        int u   = gid & 15;
        int h = row >> 4, t = row & 15;
        size_t base = ((size_t)h * KL + t) * DH + 4 * u;
        float4 x  = *(const float4*)(pm + (((size_t)0 * HEADS + h) * NPM + t) * DH + 4 * u);
        float4 vv = *(const float4*)(pm + (((size_t)1 * HEADS + h) * NPM + t) * DH + 4 * u);
        *(float4*)(g_V + base) = vv;
        int j0 = 2 * u, j1 = 2 * u + 1;
        float rf0 = (float)pow(10000.0, -(double)j0 / 32.0);
        float rf1 = (float)pow(10000.0, -(double)j1 / 32.0);
        float s0, c0, s1, c1;
        sincosf((float)t * rf0, &s0, &c0);
        sincosf((float)t * rf1, &s1, &c1);
        float r0 = x.x * c0 - x.y * s0;
        float r1 = x.y * c0 + x.x * s0;
        float r2 = x.z * c1 - x.w * s1;
        float r3 = x.w * c1 + x.z * s1;
        uint32_t h0, l0, h1, l1;
        split2(r0, r1, h0, l0);
        split2(r2, r3, h1, l1);
        *(uint2*)(g_Kh + base) = make_uint2(h0, h1);
        *(uint2*)(g_Kl + base) = make_uint2(l0, l1);
    }
}

// ---------------------------------------------------------------------------
// 3) bf16 split GEMM, cp.async double-buffered (mainloop verified r7-r14).
// epi==1 epilogue: RoPE + split for Q/K in-register; Q additionally scaled
// by SC_FOLD so attention scores land directly in exp2 domain.
// ---------------------------------------------------------------------------
#define STG_A_H 0
#define STG_A_L 10240
#define STG_B_H 20480
#define STG_B_L 30720
#define STG_SZ  40960

#define PREFETCH(S) do {                                                      \
    int _k0 = (S) * 32;                                                       \
    uint32_t _b = sbase + ((S) & 1) * STG_SZ + r * 80 + cg * 16;              \
    const __nv_bfloat16* _ag = Ah + (size_t)(row0 + r) * K + _k0 + cg * 8;    \
    const __nv_bfloat16* _al = Al + (size_t)(row0 + r) * K + _k0 + cg * 8;    \
    const __nv_bfloat16* _bg = Bh + (size_t)(col0 + r) * K + _k0 + cg * 8;    \
    const __nv_bfloat16* _bl = Bl + (size_t)(col0 + r) * K + _k0 + cg * 8;    \
    CPA16(_b + STG_A_H,      _ag);                                            \
    CPA16(_b + STG_A_H + 16, _ag + 8);                                        \
    CPA16(_b + STG_A_L,      _al);                                            \
    CPA16(_b + STG_A_L + 16, _al + 8);                                        \
    CPA16(_b + STG_B_H,      _bg);                                            \
    CPA16(_b + STG_B_H + 16, _bg + 8);                                        \
    CPA16(_b + STG_B_L,      _bl);                                            \
    CPA16(_b + STG_B_L + 16, _bl + 8);                                        \
    asm volatile("cp.async.commit_group;");                                   \
} while (0)

__global__ __launch_bounds__(256) void mm2_kernel(
    const __nv_bfloat16* __restrict__ Ah, const __nv_bfloat16* __restrict__ Al,
    const __nv_bfloat16* __restrict__ Bh, const __nv_bfloat16* __restrict__ Bl,
    float* __restrict__ C, int N, int K, int epi)
{
    extern __shared__ __align__(16) uint8_t smem[];
    const uint32_t sbase = (uint32_t)__cvta_generic_to_shared(smem);

    const int tid  = threadIdx.x;
    const int lane = tid & 31, warp = tid >> 5;
    const int wm = warp & 1, wn = warp >> 1;
    const int row0 = blockIdx.y * 128, col0 = blockIdx.x * 128;

    const int r  = tid >> 1;
    const int cg = (tid & 1) * 2;

    const int NST = K / 32;

    float acc[4][4][4];
    #pragma unroll
    for (int i = 0; i < 4; i++)
        #pragma unroll
        for (int j = 0; j < 4; j++)
            #pragma unroll
            for (int q = 0; q < 4; q++) acc[i][j][q] = 0.0f;

    PREFETCH(0);
    PREFETCH(1);

    const int mbase = wm * 64, nbase = wn * 32;
    const int lr = lane & 15, lh = (lane >> 4) * 16;

    for (int s = 0; s < NST; s++) {
        if (s + 1 < NST) asm volatile("cp.async.wait_group 1;");
        else             asm volatile("cp.async.wait_group 0;");
        __syncthreads();

        const uint32_t bAh = sbase + (s & 1) * STG_SZ + STG_A_H;
        const uint32_t bAl = sbase + (s & 1) * STG_SZ + STG_A_L;
        const uint32_t bBh = sbase + (s & 1) * STG_SZ + STG_B_H;
        const uint32_t bBl = sbase + (s & 1) * STG_SZ + STG_B_L;

        #pragma unroll
        for (int kk = 0; kk < 2; kk++) {
            const uint32_t kb = (uint32_t)(kk * 32 + lh);
            uint32_t ah[4][4], al[4][4], bh[2][4], bl[2][4];
            #pragma unroll
            for (int mf = 0; mf < 4; mf++) {
                uint32_t ro = (uint32_t)(mbase + mf * 16 + lr) * 80 + kb;
                ldsm_x4(ah[mf][0], ah[mf][1], ah[mf][2], ah[mf][3], bAh + ro);
                ldsm_x4(al[mf][0], al[mf][1], al[mf][2], al[mf][3], bAl + ro);
            }
            #pragma unroll
            for (int np = 0; np < 2; np++) {
                uint32_t ro = (uint32_t)(nbase + np * 16 + lr) * 80 + kb;
                ldsm_x4(bh[np][0], bh[np][1], bh[np][2], bh[np][3], bBh + ro);
                ldsm_x4(bl[np][0], bl[np][1], bl[np][2], bl[np][3], bBl + ro);
            }
            #pragma unroll
            for (int mf = 0; mf < 4; mf++) {
                #pragma unroll
                for (int nf = 0; nf < 4; nf++) {
                    const int np = nf >> 1, half = nf & 1;
                    uint32_t b0h = bh[np][half], b1h = bh[np][2 + half];
                    uint32_t b0l = bl[np][half], b1l = bl[np][2 + half];
                    mma16816(acc[mf][nf], ah[mf], b0h, b1h);
                    mma16816(acc[mf][nf], ah[mf], b0l, b1l);
                    mma16816(acc[mf][nf], al[mf], b0h, b1h);
                }
            }
        }
        __syncthreads();
        if (s + 2 < NST) PREFETCH(s + 2);
    }

    #pragma unroll
    for (int mf = 0; mf < 4; mf++) {
        #pragma unroll
        for (int nf = 0; nf < 4; nf++) {
            int rr0 = row0 + mbase + mf * 16 + (lane >> 2);
            int col = col0 + nbase + nf * 8 + (lane & 3) * 2;   // even
            #pragma unroll
            for (int half = 0; half < 2; half++) {
                int row = rr0 + half * 8;
                float v0 = acc[mf][nf][half * 2 + 0];
                float v1 = acc[mf][nf][half * 2 + 1];
                if (epi == 0) {
                    *(float2*)(C + (size_t)row * N + col) = make_float2(v0, v1);
                } else {
                    int region = col >> 9;          // 0:q 1:k 2:v
                    int cr = col & 511;
                    int hh = cr >> 6, dd = cr & 63; // dd even
                    if (region == 2) {
                        *(float2*)(g_V + ((size_t)hh * KL + row + NPM) * DH + dd)
                            = make_float2(v0, v1);
                    } else {
                        int pos = row + NPM;        // same for Q and K
                        float c  = g_cos[pos * 32 + (dd >> 1)];
                        float sn = g_sin[pos * 32 + (dd >> 1)];
                        float r1 = v0 * c - v1 * sn;
                        float r2 = v1 * c + v0 * sn;
                        uint32_t hi, lo;
                        if (region == 0) {
                            r1 *= SC_FOLD;          // fold score scale into Q
                            r2 *= SC_FOLD;
                            split2(r1, r2, hi, lo);
                            size_t base = ((size_t)hh * S_LEN + row) * DH + dd;
                            *(uint32_t*)(g_Qh + base) = hi;
                            *(uint32_t*)(g_Ql + base) = lo;
                        } else {
                            split2(r1, r2, hi, lo);
                            size_t base = ((size_t)hh * KL + row + NPM) * DH + dd;
                            *(uint32_t*)(g_Kh + base) = hi;
                            *(uint32_t*)(g_Kl + base) = lo;
                        }
                    }
                }
            }
        }
    }
}

// ---------------------------------------------------------------------------
// post_kernel: V transpose + split only.
// ---------------------------------------------------------------------------
#define POST_VT_X   ((KL + 31) / 32)                          // 129
#define POST_BLKS (POST_VT_X * (DH / 32) * HEADS)             // 2064

__global__ __launch_bounds__(128) void post_kernel() {
    __shared__ float tile[32 * 33];
    const int b = blockIdx.x;
    const int tid = threadIdx.x;

    int h   = b / (POST_VT_X * (DH / 32));
    int rem = b % (POST_VT_X * (DH / 32));
    int d0  = (rem / POST_VT_X) * 32;
    int t0  = (rem % POST_VT_X) * 32;
    int tx = tid & 31, ty = tid >> 5;
    for (int r = ty; r < 32; r += 4) {
        int t = t0 + r;
        if (t < KL)
            tile[r * 33 + tx] = g_V[((size_t)h * KL + t) * DH + d0 + tx];
    }
    __syncthreads();
    for (int r = ty; r < 32; r += 4) {
        int d = d0 + r;
        int t = t0 + tx;
        if (t < KL) {
            float v = tile[tx * 33 + r];
            uint32_t uv = __float_as_uint(v) & 0xFFFF0000u;
            g_Vth[((size_t)(h * DH + d)) * KL + t] =
                __ushort_as_bfloat16((unsigned short)(uv >> 16));
            g_Vtl[((size_t)(h * DH + d)) * KL + t] =
                __float2bfloat16(v - __uint_as_float(uv));
        }
    }
}

// ---------------------------------------------------------------------------
// 5) Tensor-core flash attention. Q pre-scaled (scores in exp2 domain);
// mask pass only on mem/diag tiles; interior tiles go straight to row-max.
// ---------------------------------------------------------------------------
#define SWADDR(base, row, ch) ((base) + (uint32_t)(row) * 128u + \
                               ((uint32_t)((ch) ^ ((row) & 7)) << 4))

#define ATT_KVPF(TT) do {                                                     \
    int _t0 = ((TT) == 0) ? 0 : (NPM + seg * SEGLEN + ((TT) - 1) * 64);       \
    uint32_t _buf = sbase + (((TT) & 1) ? 32768u : 0u);                       \
    _Pragma("unroll")                                                         \
    for (int _k = 0; _k < 4; _k++) {                                          \
        int _i = tid + _k * 128;                                              \
        int _row = _i >> 3, _ch = _i & 7;                                     \
        uint32_t _d16 = (uint32_t)(_row * 8 + (_ch ^ (_row & 7))) * 16u;      \
        const __nv_bfloat16* _kh = g_Kh + ((size_t)h * KL + _t0 + _row) * DH + _ch * 8; \
        const __nv_bfloat16* _kl = g_Kl + ((size_t)h * KL + _t0 + _row) * DH + _ch * 8; \
        const __nv_bfloat16* _vh = g_Vth + ((size_t)(h * DH + _row)) * KL + _t0 + _ch * 8; \
        const __nv_bfloat16* _vl = g_Vtl + ((size_t)(h * DH + _row)) * KL + _t0 + _ch * 8; \
        CPA16(_buf + _d16,          _kh);                                     \
        CPA16(_buf + 8192u + _d16,  _kl);                                     \
        CPA16(_buf + 16384u + _d16, _vh);                                     \
        CPA16(_buf + 24576u + _d16, _vl);                                     \
    }                                                                         \
    asm volatile("cp.async.commit_group;");                                   \
} while (0)

__global__ __launch_bounds__(128, 3) void attn_mma_kernel() {
    extern __shared__ __align__(16) uint8_t asmem[];
    const uint32_t sbase = (uint32_t)__cvta_generic_to_shared(asmem);

    const int qt = 7 - blockIdx.x;             // heavy blocks first
    const int seg = blockIdx.y, h = blockIdx.z;
    const int tid = threadIdx.x;
    const int lane = tid & 31, w = tid >> 5;
    const int s0 = seg * SEGLEN + qt * 64;
    const int ntiles = qt + 2;

    ATT_KVPF(0);

    const uint32_t qb = sbase + 32768u;
    for (int i = tid; i < 512; i += 128) {
        int row = i >> 3, ch = i & 7;
        int d = row * 8 + (ch ^ (row & 7));
        ((uint4*)(asmem + 32768))[d] =
            *((const uint4*)(g_Qh + ((size_t)h * S_LEN + s0 + row) * DH) + ch);
        ((uint4*)(asmem + 40960))[d] =
            *((const uint4*)(g_Ql + ((size_t)h * S_LEN + s0 + row) * DH) + ch);
    }
    __syncthreads();

    uint32_t qh[4][4], ql[4][4];
    {
        int row = w * 16 + (lane & 15);
        #pragma unroll
        for (int j = 0; j < 4; j++) {
            int ch = 2 * j + (lane >> 4);
            ldsm_x4(qh[j][0], qh[j][1], qh[j][2], qh[j][3], SWADDR(qb, row, ch));
            ldsm_x4(ql[j][0], ql[j][1], ql[j][2], ql[j][3], SWADDR(qb + 8192u, row, ch));
        }
    }
    __syncthreads();

    ATT_KVPF(1);

    float oacc[8][4];
    #pragma unroll
    for (int nf = 0; nf < 8; nf++)
        #pragma unroll
        for (int q = 0; q < 4; q++) oacc[nf][q] = 0.0f;
    float mrun[2] = {-INFINITY, -INFINITY};
    float lrun[2] = {0.0f, 0.0f};

    const int r1 = lane >> 2;
    const int cbase = (lane & 3) * 2;

    for (int tt = 0; tt < ntiles; tt++) {
        const bool ismem = (tt == 0);
        const bool diag = (!ismem) && ((tt - 1) == qt);

        if (tt + 1 < ntiles) asm volatile("cp.async.wait_group 1;");
        else                 asm volatile("cp.async.wait_group 0;");
        __syncthreads();

        const uint32_t kb0 = sbase + ((tt & 1) ? 32768u : 0u);
        const uint32_t bKh = kb0, bKl = kb0 + 8192u;
        const uint32_t bVh = kb0 + 16384u, bVl = kb0 + 24576u;

        float sacc[8][4];
        #pragma unroll
        for (int nf = 0; nf < 8; nf++)
            #pragma unroll
            for (int q = 0; q < 4; q++) sacc[nf][q] = 0.0f;

        #pragma unroll
        for (int j = 0; j < 4; j++) {
            int ch = 2 * j + (lane >> 4);
            #pragma unroll
            for (int ng = 0; ng < 4; ng++) {
                if (ismem && ng > 0) break;
                int row = ng * 16 + (lane & 15);
                uint32_t kh[4], kl[4];
                ldsm_x4(kh[0], kh[1], kh[2], kh[3], SWADDR(bKh, row, ch));
                ldsm_x4(kl[0], kl[1], kl[2], kl[3], SWADDR(bKl, row, ch));
                #pragma unroll
                for (int sel = 0; sel < 2; sel++) {
                    const int nf = 2 * ng + sel;
                    mma16816(sacc[nf], qh[j], kh[sel], kh[2 + sel]);
                    mma16816(sacc[nf], qh[j], kl[sel], kl[2 + sel]);
                    mma16816(sacc[nf], ql[j], kh[sel], kh[2 + sel]);
                }
            }
        }

        // ---- mask: only mem / diagonal tiles need it (Q pre-scaled) ----
        if (ismem || diag) {
            #pragma unroll
            for (int nf = 0; nf < 8; nf++) {
                #pragma unroll
                for (int q = 0; q < 4; q++) {
                    int col = nf * 8 + cbase + (q & 1);
                    int qrow = w * 16 + r1 + ((q >= 2) ? 8 : 0);
                    bool bad = (ismem && col >= 16) || (diag && col > qrow);
                    if (bad) sacc[nf][q] = -INFINITY;
                }
            }
        }

        float ml[2] = {-INFINITY, -INFINITY};
        #pragma unroll
        for (int nf = 0; nf < 8; nf++) {
            ml[0] = fmaxf(ml[0], fmaxf(sacc[nf][0], sacc[nf][1]));
            ml[1] = fmaxf(ml[1], fmaxf(sacc[nf][2], sacc[nf][3]));
        }
        #pragma unroll
        for (int o = 1; o <= 2; o <<= 1) {
            ml[0] = fmaxf(ml[0], __shfl_xor_sync(0xffffffffu, ml[0], o));
            ml[1] = fmaxf(ml[1], __shfl_xor_sync(0xffffffffu, ml[1], o));
        }
        float mnew0 = fmaxf(mrun[0], ml[0]);
        float mnew1 = fmaxf(mrun[1], ml[1]);
        float corr0 = ex2(mrun[0] - mnew0);
        float corr1 = ex2(mrun[1] - mnew1);
        mrun[0] = mnew0; mrun[1] = mnew1;

        float ls[2] = {0.0f, 0.0f};
        #pragma unroll
        for (int nf = 0; nf < 8; nf++) {
            float p0 = ex2(sacc[nf][0] - mnew0);
            float p1 = ex2(sacc[nf][1] - mnew0);
            float p2 = ex2(sacc[nf][2] - mnew1);
            float p3 = ex2(sacc[nf][3] - mnew1);
            sacc[nf][0] = p0; sacc[nf][1] = p1; sacc[nf][2] = p2; sacc[nf][3] = p3;
            ls[0] += p0 + p1; ls[1] += p2 + p3;
        }
        #pragma unroll
        for (int o = 1; o <= 2; o <<= 1) {
            ls[0] += __shfl_xor_sync(0xffffffffu, ls[0], o);
            ls[1] += __shfl_xor_sync(0xffffffffu, ls[1], o);
        }
        lrun[0] = lrun[0] * corr0 + ls[0];
        lrun[1] = lrun[1] * corr1 + ls[1];

        #pragma unroll
        for (int nf = 0; nf < 8; nf++) {
            oacc[nf][0] *= corr0; oacc[nf][1] *= corr0;
            oacc[nf][2] *= corr1; oacc[nf][3] *= corr1;
        }

        #pragma unroll
        for (int j = 0; j < 4; j++) {
            if (ismem && j > 0) break;
            uint32_t pa_h[4], pa_l[4];
            split2(sacc[2*j][0],   sacc[2*j][1],   pa_h[0], pa_l[0]);
            split2(sacc[2*j][2],   sacc[2*j][3],   pa_h[1], pa_l[1]);
            split2(sacc[2*j+1][0], sacc[2*j+1][1], pa_h[2], pa_l[2]);
            split2(sacc[2*j+1][2], sacc[2*j+1][3], pa_h[3], pa_l[3]);

            int ch = 2 * j + (lane >> 4);
            #pragma unroll
            for (int dg = 0; dg < 4; dg++) {
                int row = dg * 16 + (lane & 15);
                uint32_t vh[4], vl[4];
                ldsm_x4(vh[0], vh[1], vh[2], vh[3], SWADDR(bVh, row, ch));
                ldsm_x4(vl[0], vl[1], vl[2], vl[3], SWADDR(bVl, row, ch));
                #pragma unroll
                for (int sel = 0; sel < 2; sel++) {
                    const int nf = 2 * dg + sel;
                    mma16816(oacc[nf], pa_h, vh[sel], vh[2 + sel]);
                    mma16816(oacc[nf], pa_h, vl[sel], vl[2 + sel]);
                    mma16816(oacc[nf], pa_l, vh[sel], vh[2 + sel]);
                }
            }
        }

        __syncthreads();
        if (tt + 2 < ntiles) ATT_KVPF(tt + 2);
    }

    float inv0 = rcp(lrun[0]);
    float inv1 = rcp(lrun[1]);
    int qrow = s0 + w * 16 + r1;
    #pragma unroll
    for (int nf = 0; nf < 8; nf++) {
        int col = h * DH + nf * 8 + cbase;
        uint32_t h0, l0, h1, l1;
        split2(oacc[nf][0] * inv0, oacc[nf][1] * inv0, h0, l0);
        split2(oacc[nf][2] * inv1, oacc[nf][3] * inv1, h1, l1);
        *(uint32_t*)(g_Ah + (size_t)qrow * DIM + col)       = h0;
        *(uint32_t*)(g_Al + (size_t)qrow * DIM + col)       = l0;
        *(uint32_t*)(g_Ah + (size_t)(qrow + 8) * DIM + col) = h1;
        *(uint32_t*)(g_Al + (size_t)(qrow + 8) * DIM + col) = l1;
    }
}

// ---------------------------------------------------------------------------
// Launch: 5 kernels (prep(+pm) -> GEMM1(+rope/SC epi) -> post(vtrans) ->
// attn -> GEMM2)
// ---------------------------------------------------------------------------
extern "C" void kernel_launch(void* const* d_in, const int* in_sizes, int n_in,
                              void* d_out, int out_size) {
    const float* seq    = (const float*)d_in[0];
    const float* norm_w = (const float*)d_in[1];
    const float* w_qkv  = (const float*)d_in[2];
    const float* w_out  = (const float*)d_in[3];
    const float* pm     = (const float*)d_in[4];

    __nv_bfloat16 *xh, *xl, *wqh, *wql, *woh, *wol, *ah, *al;
    cudaGetSymbolAddress((void**)&xh,  g_Xh);
    cudaGetSymbolAddress((void**)&xl,  g_Xl);
    cudaGetSymbolAddress((void**)&wqh, g_WqkvTh);
    cudaGetSymbolAddress((void**)&wql, g_WqkvTl);
    cudaGetSymbolAddress((void**)&woh, g_WoutTh);
    cudaGetSymbolAddress((void**)&wol, g_WoutTl);
    cudaGetSymbolAddress((void**)&ah,  g_Ah);
    cudaGetSymbolAddress((void**)&al,  g_Al);

    cudaFuncSetAttribute(mm2_kernel,
                         cudaFuncAttributeMaxDynamicSharedMemorySize, 81920);
    cudaFuncSetAttribute(attn_mma_kernel,
                         cudaFuncAttributeMaxDynamicSharedMemorySize, 65536);

    prep_kernel<<<PREP_BLKS, 128>>>(seq, norm_w, w_qkv, w_out, pm);

    mm2_kernel<<<dim3(QKV_N / 128, S_LEN / 128), 256, 81920>>>(
        xh, xl, wqh, wql, nullptr, QKV_N, DIM, 1);

    post_kernel<<<POST_BLKS, 128>>>();

    attn_mma_kernel<<<dim3(8, 8, 8), 128, 65536>>>();

    mm2_kernel<<<dim3(DIM / 128, S_LEN / 128), 256, 81920>>>(
        ah, al, woh, wol, (float*)d_out, DIM, DIM, 0);
}

// round 17
// speedup vs baseline: 2.6452x; 1.0304x over previous
#include <cuda_runtime.h>
#include <cuda_bf16.h>
#include <cuda_fp16.h>
#include <cstdint>
#include <math.h>

// ---------------------------------------------------------------------------
// Problem constants
// ---------------------------------------------------------------------------
#define S_LEN 4096
#define DIM   512
#define HEADS 8
#define DH    64
#define NPM   16
#define SEGLEN 512
#define KL    (S_LEN + NPM)        // 4112 keys after memory prepend
#define QKV_N (3 * HEADS * DH)     // 1536

// scale * log2(e), folded into Q at the GEMM1 epilogue
#define SC_FOLD 0.1803368801111731f

// ---------------------------------------------------------------------------
// Scratch (device globals: no allocation allowed)
// ---------------------------------------------------------------------------
__device__ float g_V[HEADS * KL * DH];        // fp32 [h][t][d]
__device__ float g_cos[KL * 32];
__device__ float g_sin[KL * 32];
__device__ __align__(16) __nv_bfloat16 g_Xh[S_LEN * DIM];
__device__ __align__(16) __nv_bfloat16 g_Xl[S_LEN * DIM];
__device__ __align__(16) __nv_bfloat16 g_WqkvTh[QKV_N * DIM];  // [n][k]
__device__ __align__(16) __nv_bfloat16 g_WqkvTl[QKV_N * DIM];
__device__ __align__(16) __nv_bfloat16 g_WoutTh[DIM * DIM];    // [n][k]
__device__ __align__(16) __nv_bfloat16 g_WoutTl[DIM * DIM];
__device__ __align__(16) __nv_bfloat16 g_Ah[S_LEN * DIM];
__device__ __align__(16) __nv_bfloat16 g_Al[S_LEN * DIM];
__device__ __align__(16) __nv_bfloat16 g_Qh[HEADS * S_LEN * DH];
__device__ __align__(16) __nv_bfloat16 g_Ql[HEADS * S_LEN * DH];
__device__ __align__(16) __nv_bfloat16 g_Kh[HEADS * KL * DH];
__device__ __align__(16) __nv_bfloat16 g_Kl[HEADS * KL * DH];
__device__ __align__(16) __half g_Vth[HEADS * DH * KL];        // f16 [h][d][t]
__device__ __align__(16) __half g_Vtl[HEADS * DH * KL];        // f16 residual

// ---------------------------------------------------------------------------
// helpers
// ---------------------------------------------------------------------------
__device__ __forceinline__ void split2(float a0, float a1,
                                       uint32_t& hi, uint32_t& lo) {
    uint32_t u0 = __float_as_uint(a0), u1 = __float_as_uint(a1);
    asm("prmt.b32 %0, %1, %2, 0x7632;" : "=r"(hi) : "r"(u0), "r"(u1));
    float r0 = a0 - __uint_as_float(u0 & 0xFFFF0000u);
    float r1 = a1 - __uint_as_float(u1 & 0xFFFF0000u);
    asm("cvt.rn.bf16x2.f32 %0, %1, %2;" : "=r"(lo) : "f"(r1), "f"(r0));
}

// pack two floats into f16x2 (element 0 in low half)
__device__ __forceinline__ uint32_t f16pack(float a0, float a1) {
    uint32_t r;
    asm("cvt.rn.f16x2.f32 %0, %1, %2;" : "=r"(r) : "f"(a1), "f"(a0));
    return r;
}

__device__ __forceinline__ float ex2(float x) {
    float r; asm("ex2.approx.f32 %0, %1;" : "=f"(r) : "f"(x)); return r;
}
__device__ __forceinline__ float rcp(float x) {
    float r; asm("rcp.approx.f32 %0, %1;" : "=f"(r) : "f"(x)); return r;
}

__device__ __forceinline__ void ldsm_x4(uint32_t& r0, uint32_t& r1,
                                        uint32_t& r2, uint32_t& r3, uint32_t addr) {
    asm volatile("ldmatrix.sync.aligned.m8n8.x4.shared.b16 {%0,%1,%2,%3}, [%4];"
                 : "=r"(r0), "=r"(r1), "=r"(r2), "=r"(r3) : "r"(addr));
}

__device__ __forceinline__ void mma16816(float* c, const uint32_t* a,
                                         uint32_t b0, uint32_t b1) {
    asm volatile(
        "mma.sync.aligned.m16n8k16.row.col.f32.bf16.bf16.f32 "
        "{%0,%1,%2,%3}, {%4,%5,%6,%7}, {%8,%9}, {%0,%1,%2,%3};"
        : "+f"(c[0]), "+f"(c[1]), "+f"(c[2]), "+f"(c[3])
        : "r"(a[0]), "r"(a[1]), "r"(a[2]), "r"(a[3]), "r"(b0), "r"(b1));
}

// f16 variant (for PV)
__device__ __forceinline__ void mma16816h(float* c, const uint32_t* a,
                                          uint32_t b0, uint32_t b1) {
    asm volatile(
        "mma.sync.aligned.m16n8k16.row.col.f32.f16.f16.f32 "
        "{%0,%1,%2,%3}, {%4,%5,%6,%7}, {%8,%9}, {%0,%1,%2,%3};"
        : "+f"(c[0]), "+f"(c[1]), "+f"(c[2]), "+f"(c[3])
        : "r"(a[0]), "r"(a[1]), "r"(a[2]), "r"(a[3]), "r"(b0), "r"(b1));
}

#define CPA16(dst, src) \
    asm volatile("cp.async.cg.shared.global [%0], [%1], 16;" \
                 :: "r"(dst), "l"(src))

// ---------------------------------------------------------------------------
// prep_kernel (verified round 15, unchanged)
// ---------------------------------------------------------------------------
#define PREP_TBL_BLKS  1028
#define PREP_CVX_BLKS  4096
#define PREP_WQ_BLKS   768
#define PREP_WO_BLKS   256
#define PREP_PM_BLKS   16
#define PREP_BLKS (PREP_TBL_BLKS + PREP_CVX_BLKS + PREP_WQ_BLKS + \
                   PREP_WO_BLKS + PREP_PM_BLKS)

__device__ __forceinline__ void wtrans_body(const float* __restrict__ src,
                                            __nv_bfloat16* __restrict__ dh,
                                            __nv_bfloat16* __restrict__ dl,
                                            int K, int N, int n0, int k0,
                                            int tid, float* tile) {
    int tx = tid & 31, ty = tid >> 5;
    for (int r = ty; r < 32; r += 4)
        tile[r * 33 + tx] = src[(size_t)(k0 + r) * N + n0 + tx];
    __syncthreads();
    for (int r = ty; r < 32; r += 4) {
        int n = n0 + r, k = k0 + tx;
        float v = tile[tx * 33 + r];
        uint32_t uv = __float_as_uint(v) & 0xFFFF0000u;
        dh[(size_t)n * K + k] = __ushort_as_bfloat16((unsigned short)(uv >> 16));
        dl[(size_t)n * K + k] = __float2bfloat16(v - __uint_as_float(uv));
    }
}

__global__ __launch_bounds__(128) void prep_kernel(
    const float* __restrict__ seq, const float* __restrict__ norm_w,
    const float* __restrict__ w_qkv, const float* __restrict__ w_out,
    const float* __restrict__ pm)
{
    __shared__ float smem[32 * 33];
    const int b = blockIdx.x;
    const int tid = threadIdx.x;

    if (b < PREP_TBL_BLKS) {
        int idx = b * 128 + tid;
        if (idx < KL * 32) {
            int pos = idx >> 5, j = idx & 31;
            float rf  = (float)pow(10000.0, -(double)j / 32.0);
            float ang = (float)pos * rf;
            float s, c;
            sincosf(ang, &s, &c);
            g_cos[idx] = c;
            g_sin[idx] = s;
        }
        return;
    }
    if (b < PREP_TBL_BLKS + PREP_CVX_BLKS) {
        int s = b - PREP_TBL_BLKS;
        float4 v = ((const float4*)(seq + (size_t)s * DIM))[tid];
        float p = v.x * v.x + v.y * v.y + v.z * v.z + v.w * v.w;
        #pragma unroll
        for (int o = 16; o; o >>= 1) p += __shfl_xor_sync(0xffffffffu, p, o);
        if ((tid & 31) == 0) smem[tid >> 5] = p;
        __syncthreads();
        float rs = rsqrtf((smem[0] + smem[1] + smem[2] + smem[3])
                          * (1.0f / (float)DIM) + 1.1920928955078125e-07f);
        float4 w = ((const float4*)norm_w)[tid];
        v.x *= rs * w.x; v.y *= rs * w.y; v.z *= rs * w.z; v.w *= rs * w.w;
        uint32_t h0, l0, h1, l1;
        split2(v.x, v.y, h0, l0);
        split2(v.z, v.w, h1, l1);
        ((uint2*)(g_Xh + (size_t)s * DIM))[tid] = make_uint2(h0, h1);
        ((uint2*)(g_Xl + (size_t)s * DIM))[tid] = make_uint2(l0, l1);
        return;
    }
    if (b < PREP_TBL_BLKS + PREP_CVX_BLKS + PREP_WQ_BLKS) {
        int bb = b - PREP_TBL_BLKS - PREP_CVX_BLKS;
        int n0 = (bb % (QKV_N / 32)) * 32;
        int k0 = (bb / (QKV_N / 32)) * 32;
        wtrans_body(w_qkv, g_WqkvTh, g_WqkvTl, DIM, QKV_N, n0, k0, tid, smem);
        return;
    }
    if (b < PREP_TBL_BLKS + PREP_CVX_BLKS + PREP_WQ_BLKS + PREP_WO_BLKS) {
        int bb = b - PREP_TBL_BLKS - PREP_CVX_BLKS - PREP_WQ_BLKS;
        int n0 = (bb % (DIM / 32)) * 32;
        int k0 = (bb / (DIM / 32)) * 32;
        wtrans_body(w_out, g_WoutTh, g_WoutTl, DIM, DIM, n0, k0, tid, smem);
        return;
    }
    {
        // ---- pm memory slots: rope K rows t<16 (pos=t), copy pm -> V ----
        int bb = b - PREP_TBL_BLKS - PREP_CVX_BLKS - PREP_WQ_BLKS - PREP_WO_BLKS;
        int gid = bb * 128 + tid;
        int row = gid >> 4;              // 0..127 = h*16 + t
        int u   = gid & 15;
        int h = row >> 4, t = row & 15;
        size_t base = ((size_t)h * KL + t) * DH + 4 * u;
        float4 x  = *(const float4*)(pm + (((size_t)0 * HEADS + h) * NPM + t) * DH + 4 * u);
        float4 vv = *(const float4*)(pm + (((size_t)1 * HEADS + h) * NPM + t) * DH + 4 * u);
        *(float4*)(g_V + base) = vv;
        int j0 = 2 * u, j1 = 2 * u + 1;
        float rf0 = (float)pow(10000.0, -(double)j0 / 32.0);
        float rf1 = (float)pow(10000.0, -(double)j1 / 32.0);
        float s0, c0, s1, c1;
        sincosf((float)t * rf0, &s0, &c0);
        sincosf((float)t * rf1, &s1, &c1);
        float r0 = x.x * c0 - x.y * s0;
        float r1 = x.y * c0 + x.x * s0;
        float r2 = x.z * c1 - x.w * s1;
        float r3 = x.w * c1 + x.z * s1;
        uint32_t h0, l0, h1, l1;
        split2(r0, r1, h0, l0);
        split2(r2, r3, h1, l1);
        *(uint2*)(g_Kh + base) = make_uint2(h0, h1);
        *(uint2*)(g_Kl + base) = make_uint2(l0, l1);
    }
}

// ---------------------------------------------------------------------------
// bf16 split GEMM, cp.async double-buffered (mainloop verified r7-r15).
// epi==1: RoPE + split Q/K in-register (Q scaled by SC_FOLD); V fp32 store.
// ---------------------------------------------------------------------------
#define STG_A_H 0
#define STG_A_L 10240
#define STG_B_H 20480
#define STG_B_L 30720
#define STG_SZ  40960

#define PREFETCH(S) do {                                                      \
    int _k0 = (S) * 32;                                                       \
    uint32_t _b = sbase + ((S) & 1) * STG_SZ + r * 80 + cg * 16;              \
    const __nv_bfloat16* _ag = Ah + (size_t)(row0 + r) * K + _k0 + cg * 8;    \
    const __nv_bfloat16* _al = Al + (size_t)(row0 + r) * K + _k0 + cg * 8;    \
    const __nv_bfloat16* _bg = Bh + (size_t)(col0 + r) * K + _k0 + cg * 8;    \
    const __nv_bfloat16* _bl = Bl + (size_t)(col0 + r) * K + _k0 + cg * 8;    \
    CPA16(_b + STG_A_H,      _ag);                                            \
    CPA16(_b + STG_A_H + 16, _ag + 8);                                        \
    CPA16(_b + STG_A_L,      _al);                                            \
    CPA16(_b + STG_A_L + 16, _al + 8);                                        \
    CPA16(_b + STG_B_H,      _bg);                                            \
    CPA16(_b + STG_B_H + 16, _bg + 8);                                        \
    CPA16(_b + STG_B_L,      _bl);                                            \
    CPA16(_b + STG_B_L + 16, _bl + 8);                                        \
    asm volatile("cp.async.commit_group;");                                   \
} while (0)

__global__ __launch_bounds__(256) void mm2_kernel(
    const __nv_bfloat16* __restrict__ Ah, const __nv_bfloat16* __restrict__ Al,
    const __nv_bfloat16* __restrict__ Bh, const __nv_bfloat16* __restrict__ Bl,
    float* __restrict__ C, int N, int K, int epi)
{
    extern __shared__ __align__(16) uint8_t smem[];
    const uint32_t sbase = (uint32_t)__cvta_generic_to_shared(smem);

    const int tid  = threadIdx.x;
    const int lane = tid & 31, warp = tid >> 5;
    const int wm = warp & 1, wn = warp >> 1;
    const int row0 = blockIdx.y * 128, col0 = blockIdx.x * 128;

    const int r  = tid >> 1;
    const int cg = (tid & 1) * 2;

    const int NST = K / 32;

    float acc[4][4][4];
    #pragma unroll
    for (int i = 0; i < 4; i++)
        #pragma unroll
        for (int j = 0; j < 4; j++)
            #pragma unroll
            for (int q = 0; q < 4; q++) acc[i][j][q] = 0.0f;

    PREFETCH(0);
    PREFETCH(1);

    const int mbase = wm * 64, nbase = wn * 32;
    const int lr = lane & 15, lh = (lane >> 4) * 16;

    for (int s = 0; s < NST; s++) {
        if (s + 1 < NST) asm volatile("cp.async.wait_group 1;");
        else             asm volatile("cp.async.wait_group 0;");
        __syncthreads();

        const uint32_t bAh = sbase + (s & 1) * STG_SZ + STG_A_H;
        const uint32_t bAl = sbase + (s & 1) * STG_SZ + STG_A_L;
        const uint32_t bBh = sbase + (s & 1) * STG_SZ + STG_B_H;
        const uint32_t bBl = sbase + (s & 1) * STG_SZ + STG_B_L;

        #pragma unroll
        for (int kk = 0; kk < 2; kk++) {
            const uint32_t kb = (uint32_t)(kk * 32 + lh);
            uint32_t ah[4][4], al[4][4], bh[2][4], bl[2][4];
            #pragma unroll
            for (int mf = 0; mf < 4; mf++) {
                uint32_t ro = (uint32_t)(mbase + mf * 16 + lr) * 80 + kb;
                ldsm_x4(ah[mf][0], ah[mf][1], ah[mf][2], ah[mf][3], bAh + ro);
                ldsm_x4(al[mf][0], al[mf][1], al[mf][2], al[mf][3], bAl + ro);
            }
            #pragma unroll
            for (int np = 0; np < 2; np++) {
                uint32_t ro = (uint32_t)(nbase + np * 16 + lr) * 80 + kb;
                ldsm_x4(bh[np][0], bh[np][1], bh[np][2], bh[np][3], bBh + ro);
                ldsm_x4(bl[np][0], bl[np][1], bl[np][2], bl[np][3], bBl + ro);
            }
            #pragma unroll
            for (int mf = 0; mf < 4; mf++) {
                #pragma unroll
                for (int nf = 0; nf < 4; nf++) {
                    const int np = nf >> 1, half = nf & 1;
                    uint32_t b0h = bh[np][half], b1h = bh[np][2 + half];
                    uint32_t b0l = bl[np][half], b1l = bl[np][2 + half];
                    mma16816(acc[mf][nf], ah[mf], b0h, b1h);
                    mma16816(acc[mf][nf], ah[mf], b0l, b1l);
                    mma16816(acc[mf][nf], al[mf], b0h, b1h);
                }
            }
        }
        __syncthreads();
        if (s + 2 < NST) PREFETCH(s + 2);
    }

    #pragma unroll
    for (int mf = 0; mf < 4; mf++) {
        #pragma unroll
        for (int nf = 0; nf < 4; nf++) {
            int rr0 = row0 + mbase + mf * 16 + (lane >> 2);
            int col = col0 + nbase + nf * 8 + (lane & 3) * 2;   // even
            #pragma unroll
            for (int half = 0; half < 2; half++) {
                int row = rr0 + half * 8;
                float v0 = acc[mf][nf][half * 2 + 0];
                float v1 = acc[mf][nf][half * 2 + 1];
                if (epi == 0) {
                    *(float2*)(C + (size_t)row * N + col) = make_float2(v0, v1);
                } else {
                    int region = col >> 9;          // 0:q 1:k 2:v
                    int cr = col & 511;
                    int hh = cr >> 6, dd = cr & 63; // dd even
                    if (region == 2) {
                        *(float2*)(g_V + ((size_t)hh * KL + row + NPM) * DH + dd)
                            = make_float2(v0, v1);
                    } else {
                        int pos = row + NPM;        // same for Q and K
                        float c  = g_cos[pos * 32 + (dd >> 1)];
                        float sn = g_sin[pos * 32 + (dd >> 1)];
                        float r1 = v0 * c - v1 * sn;
                        float r2 = v1 * c + v0 * sn;
                        uint32_t hi, lo;
                        if (region == 0) {
                            r1 *= SC_FOLD;
                            r2 *= SC_FOLD;
                            split2(r1, r2, hi, lo);
                            size_t base = ((size_t)hh * S_LEN + row) * DH + dd;
                            *(uint32_t*)(g_Qh + base) = hi;
                            *(uint32_t*)(g_Ql + base) = lo;
                        } else {
                            split2(r1, r2, hi, lo);
                            size_t base = ((size_t)hh * KL + row + NPM) * DH + dd;
                            *(uint32_t*)(g_Kh + base) = hi;
                            *(uint32_t*)(g_Kl + base) = lo;
                        }
                    }
                }
            }
        }
    }
}

// ---------------------------------------------------------------------------
// post_kernel: V transpose + split to f16 hi/lo (PV path is f16 now).
// ---------------------------------------------------------------------------
#define POST_VT_X   ((KL + 31) / 32)
#define POST_BLKS (POST_VT_X * (DH / 32) * HEADS)

__global__ __launch_bounds__(128) void post_kernel() {
    __shared__ float tile[32 * 33];
    const int b = blockIdx.x;
    const int tid = threadIdx.x;

    int h   = b / (POST_VT_X * (DH / 32));
    int rem = b % (POST_VT_X * (DH / 32));
    int d0  = (rem / POST_VT_X) * 32;
    int t0  = (rem % POST_VT_X) * 32;
    int tx = tid & 31, ty = tid >> 5;
    for (int r = ty; r < 32; r += 4) {
        int t = t0 + r;
        if (t < KL)
            tile[r * 33 + tx] = g_V[((size_t)h * KL + t) * DH + d0 + tx];
    }
    __syncthreads();
    for (int r = ty; r < 32; r += 4) {
        int d = d0 + r;
        int t = t0 + tx;
        if (t < KL) {
            float v = tile[tx * 33 + r];
            __half hv = __float2half_rn(v);
            g_Vth[((size_t)(h * DH + d)) * KL + t] = hv;
            g_Vtl[((size_t)(h * DH + d)) * KL + t] =
                __float2half_rn(v - __half2float(hv));
        }
    }
}

// ---------------------------------------------------------------------------
// Tensor-core flash attention. QK: bf16 3-split (unchanged). PV: f16,
// P single-f16 (1 pack/pair), V hi/lo f16 -> 2 MMAs instead of 3.
// ---------------------------------------------------------------------------
#define SWADDR(base, row, ch) ((base) + (uint32_t)(row) * 128u + \
                               ((uint32_t)((ch) ^ ((row) & 7)) << 4))

#define ATT_KVPF(TT) do {                                                     \
    int _t0 = ((TT) == 0) ? 0 : (NPM + seg * SEGLEN + ((TT) - 1) * 64);       \
    uint32_t _buf = sbase + (((TT) & 1) ? 32768u : 0u);                       \
    _Pragma("unroll")                                                         \
    for (int _k = 0; _k < 4; _k++) {                                          \
        int _i = tid + _k * 128;                                              \
        int _row = _i >> 3, _ch = _i & 7;                                     \
        uint32_t _d16 = (uint32_t)(_row * 8 + (_ch ^ (_row & 7))) * 16u;      \
        const __nv_bfloat16* _kh = g_Kh + ((size_t)h * KL + _t0 + _row) * DH + _ch * 8; \
        const __nv_bfloat16* _kl = g_Kl + ((size_t)h * KL + _t0 + _row) * DH + _ch * 8; \
        const __half* _vh = g_Vth + ((size_t)(h * DH + _row)) * KL + _t0 + _ch * 8; \
        const __half* _vl = g_Vtl + ((size_t)(h * DH + _row)) * KL + _t0 + _ch * 8; \
        CPA16(_buf + _d16,          _kh);                                     \
        CPA16(_buf + 8192u + _d16,  _kl);                                     \
        CPA16(_buf + 16384u + _d16, _vh);                                     \
        CPA16(_buf + 24576u + _d16, _vl);                                     \
    }                                                                         \
    asm volatile("cp.async.commit_group;");                                   \
} while (0)

__global__ __launch_bounds__(128, 3) void attn_mma_kernel() {
    extern __shared__ __align__(16) uint8_t asmem[];
    const uint32_t sbase = (uint32_t)__cvta_generic_to_shared(asmem);

    const int qt = 7 - blockIdx.x;             // heavy blocks first
    const int seg = blockIdx.y, h = blockIdx.z;
    const int tid = threadIdx.x;
    const int lane = tid & 31, w = tid >> 5;
    const int s0 = seg * SEGLEN + qt * 64;
    const int ntiles = qt + 2;

    ATT_KVPF(0);

    const uint32_t qb = sbase + 32768u;
    for (int i = tid; i < 512; i += 128) {
        int row = i >> 3, ch = i & 7;
        int d = row * 8 + (ch ^ (row & 7));
        ((uint4*)(asmem + 32768))[d] =
            *((const uint4*)(g_Qh + ((size_t)h * S_LEN + s0 + row) * DH) + ch);
        ((uint4*)(asmem + 40960))[d] =
            *((const uint4*)(g_Ql + ((size_t)h * S_LEN + s0 + row) * DH) + ch);
    }
    __syncthreads();

    uint32_t qh[4][4], ql[4][4];
    {
        int row = w * 16 + (lane & 15);
        #pragma unroll
        for (int j = 0; j < 4; j++) {
            int ch = 2 * j + (lane >> 4);
            ldsm_x4(qh[j][0], qh[j][1], qh[j][2], qh[j][3], SWADDR(qb, row, ch));
            ldsm_x4(ql[j][0], ql[j][1], ql[j][2], ql[j][3], SWADDR(qb + 8192u, row, ch));
        }
    }
    __syncthreads();

    ATT_KVPF(1);

    float oacc[8][4];
    #pragma unroll
    for (int nf = 0; nf < 8; nf++)
        #pragma unroll
        for (int q = 0; q < 4; q++) oacc[nf][q] = 0.0f;
    float mrun[2] = {-INFINITY, -INFINITY};
    float lrun[2] = {0.0f, 0.0f};

    const int r1 = lane >> 2;
    const int cbase = (lane & 3) * 2;

    for (int tt = 0; tt < ntiles; tt++) {
        const bool ismem = (tt == 0);
        const bool diag = (!ismem) && ((tt - 1) == qt);

        if (tt + 1 < ntiles) asm volatile("cp.async.wait_group 1;");
        else                 asm volatile("cp.async.wait_group 0;");
        __syncthreads();

        const uint32_t kb0 = sbase + ((tt & 1) ? 32768u : 0u);
        const uint32_t bKh = kb0, bKl = kb0 + 8192u;
        const uint32_t bVh = kb0 + 16384u, bVl = kb0 + 24576u;

        float sacc[8][4];
        #pragma unroll
        for (int nf = 0; nf < 8; nf++)
            #pragma unroll
            for (int q = 0; q < 4; q++) sacc[nf][q] = 0.0f;

        #pragma unroll
        for (int j = 0; j < 4; j++) {
            int ch = 2 * j + (lane >> 4);
            #pragma unroll
            for (int ng = 0; ng < 4; ng++) {
                if (ismem && ng > 0) break;
                int row = ng * 16 + (lane & 15);
                uint32_t kh[4], kl[4];
                ldsm_x4(kh[0], kh[1], kh[2], kh[3], SWADDR(bKh, row, ch));
                ldsm_x4(kl[0], kl[1], kl[2], kl[3], SWADDR(bKl, row, ch));
                #pragma unroll
                for (int sel = 0; sel < 2; sel++) {
                    const int nf = 2 * ng + sel;
                    mma16816(sacc[nf], qh[j], kh[sel], kh[2 + sel]);
                    mma16816(sacc[nf], qh[j], kl[sel], kl[2 + sel]);
                    mma16816(sacc[nf], ql[j], kh[sel], kh[2 + sel]);
                }
            }
        }

        if (ismem || diag) {
            #pragma unroll
            for (int nf = 0; nf < 8; nf++) {
                #pragma unroll
                for (int q = 0; q < 4; q++) {
                    int col = nf * 8 + cbase + (q & 1);
                    int qrow = w * 16 + r1 + ((q >= 2) ? 8 : 0);
                    bool bad = (ismem && col >= 16) || (diag && col > qrow);
                    if (bad) sacc[nf][q] = -INFINITY;
                }
            }
        }

        float ml[2] = {-INFINITY, -INFINITY};
        #pragma unroll
        for (int nf = 0; nf < 8; nf++) {
            ml[0] = fmaxf(ml[0], fmaxf(sacc[nf][0], sacc[nf][1]));
            ml[1] = fmaxf(ml[1], fmaxf(sacc[nf][2], sacc[nf][3]));
        }
        #pragma unroll
        for (int o = 1; o <= 2; o <<= 1) {
            ml[0] = fmaxf(ml[0], __shfl_xor_sync(0xffffffffu, ml[0], o));
            ml[1] = fmaxf(ml[1], __shfl_xor_sync(0xffffffffu, ml[1], o));
        }
        float mnew0 = fmaxf(mrun[0], ml[0]);
        float mnew1 = fmaxf(mrun[1], ml[1]);
        float corr0 = ex2(mrun[0] - mnew0);
        float corr1 = ex2(mrun[1] - mnew1);
        mrun[0] = mnew0; mrun[1] = mnew1;

        float ls[2] = {0.0f, 0.0f};
        #pragma unroll
        for (int nf = 0; nf < 8; nf++) {
            float p0 = ex2(sacc[nf][0] - mnew0);
            float p1 = ex2(sacc[nf][1] - mnew0);
            float p2 = ex2(sacc[nf][2] - mnew1);
            float p3 = ex2(sacc[nf][3] - mnew1);
            sacc[nf][0] = p0; sacc[nf][1] = p1; sacc[nf][2] = p2; sacc[nf][3] = p3;
            ls[0] += p0 + p1; ls[1] += p2 + p3;
        }
        #pragma unroll
        for (int o = 1; o <= 2; o <<= 1) {
            ls[0] += __shfl_xor_sync(0xffffffffu, ls[0], o);
            ls[1] += __shfl_xor_sync(0xffffffffu, ls[1], o);
        }
        lrun[0] = lrun[0] * corr0 + ls[0];
        lrun[1] = lrun[1] * corr1 + ls[1];

        #pragma unroll
        for (int nf = 0; nf < 8; nf++) {
            oacc[nf][0] *= corr0; oacc[nf][1] *= corr0;
            oacc[nf][2] *= corr1; oacc[nf][3] *= corr1;
        }

        // ---- O += P V^T : P single f16, V f16 hi/lo -> 2 MMAs ----
        #pragma unroll
        for (int j = 0; j < 4; j++) {
            if (ismem && j > 0) break;
            uint32_t pa[4];
            pa[0] = f16pack(sacc[2*j][0],   sacc[2*j][1]);
            pa[1] = f16pack(sacc[2*j][2],   sacc[2*j][3]);
            pa[2] = f16pack(sacc[2*j+1][0], sacc[2*j+1][1]);
            pa[3] = f16pack(sacc[2*j+1][2], sacc[2*j+1][3]);

            int ch = 2 * j + (lane >> 4);
            #pragma unroll
            for (int dg = 0; dg < 4; dg++) {
                int row = dg * 16 + (lane & 15);
                uint32_t vh[4], vl[4];
                ldsm_x4(vh[0], vh[1], vh[2], vh[3], SWADDR(bVh, row, ch));
                ldsm_x4(vl[0], vl[1], vl[2], vl[3], SWADDR(bVl, row, ch));
                #pragma unroll
                for (int sel = 0; sel < 2; sel++) {
                    const int nf = 2 * dg + sel;
                    mma16816h(oacc[nf], pa, vh[sel], vh[2 + sel]);
                    mma16816h(oacc[nf], pa, vl[sel], vl[2 + sel]);
                }
            }
        }

        __syncthreads();
        if (tt + 2 < ntiles) ATT_KVPF(tt + 2);
    }

    float inv0 = rcp(lrun[0]);
    float inv1 = rcp(lrun[1]);
    int qrow = s0 + w * 16 + r1;
    #pragma unroll
    for (int nf = 0; nf < 8; nf++) {
        int col = h * DH + nf * 8 + cbase;
        uint32_t h0, l0, h1, l1;
        split2(oacc[nf][0] * inv0, oacc[nf][1] * inv0, h0, l0);
        split2(oacc[nf][2] * inv1, oacc[nf][3] * inv1, h1, l1);
        *(uint32_t*)(g_Ah + (size_t)qrow * DIM + col)       = h0;
        *(uint32_t*)(g_Al + (size_t)qrow * DIM + col)       = l0;
        *(uint32_t*)(g_Ah + (size_t)(qrow + 8) * DIM + col) = h1;
        *(uint32_t*)(g_Al + (size_t)(qrow + 8) * DIM + col) = l1;
    }
}

// ---------------------------------------------------------------------------
// Launch: 5 kernels (prep(+pm) -> GEMM1(+rope/SC epi) -> post(vtrans f16) ->
// attn -> GEMM2)
// ---------------------------------------------------------------------------
extern "C" void kernel_launch(void* const* d_in, const int* in_sizes, int n_in,
                              void* d_out, int out_size) {
    const float* seq    = (const float*)d_in[0];
    const float* norm_w = (const float*)d_in[1];
    const float* w_qkv  = (const float*)d_in[2];
    const float* w_out  = (const float*)d_in[3];
    const float* pm     = (const float*)d_in[4];

    __nv_bfloat16 *xh, *xl, *wqh, *wql, *woh, *wol, *ah, *al;
    cudaGetSymbolAddress((void**)&xh,  g_Xh);
    cudaGetSymbolAddress((void**)&xl,  g_Xl);
    cudaGetSymbolAddress((void**)&wqh, g_WqkvTh);
    cudaGetSymbolAddress((void**)&wql, g_WqkvTl);
    cudaGetSymbolAddress((void**)&woh, g_WoutTh);
    cudaGetSymbolAddress((void**)&wol, g_WoutTl);
    cudaGetSymbolAddress((void**)&ah,  g_Ah);
    cudaGetSymbolAddress((void**)&al,  g_Al);

    cudaFuncSetAttribute(mm2_kernel,
                         cudaFuncAttributeMaxDynamicSharedMemorySize, 81920);
    cudaFuncSetAttribute(attn_mma_kernel,
                         cudaFuncAttributeMaxDynamicSharedMemorySize, 65536);

    prep_kernel<<<PREP_BLKS, 128>>>(seq, norm_w, w_qkv, w_out, pm);

    mm2_kernel<<<dim3(QKV_N / 128, S_LEN / 128), 256, 81920>>>(
        xh, xl, wqh, wql, nullptr, QKV_N, DIM, 1);

    post_kernel<<<POST_BLKS, 128>>>();

    attn_mma_kernel<<<dim3(8, 8, 8), 128, 65536>>>();

    mm2_kernel<<<dim3(DIM / 128, S_LEN / 128), 256, 81920>>>(
        ah, al, woh, wol, (float*)d_out, DIM, DIM, 0);
}